// round 1
// baseline (speedup 1.0000x reference)
#include <cuda_runtime.h>
#include <math.h>

#define B    16
#define VN   256
#define QN   256
#define VD   512
#define QD   768
#define HK   1536
#define HOUT 8
#define HD   512
#define KP   3

// ---------------- scratch (device globals: no allocation allowed) ----------
__device__ float g_v[B * VN * HK];          // v_ = relu(v@Wv^T+bv)   25 MB
__device__ float g_q[B * QN * HK];          // q_ = relu(q@Wq^T+bq)   25 MB
__device__ float g_S[B * VN * QN];          // S = sum_h att           4 MB
__device__ float g_lk[B * HK];              // logits_k
__device__ float g_hw[(HOUT + 1) * HK];     // h rows + sum row
__device__ float g_hbsum;                   // sum of head biases
__device__ unsigned char g_vmask[B * VN];
__device__ unsigned char g_qmask[B * QN];

__device__ __forceinline__ float neg_inf() { return __int_as_float(0xff800000); }

// ---------------- prep: zero-row masks -------------------------------------
__global__ void mask_kernel(const float* __restrict__ v, const float* __restrict__ q) {
    int warp = (blockIdx.x * blockDim.x + threadIdx.x) >> 5;
    int lane = threadIdx.x & 31;
    if (warp < B * VN) {
        const float* row = v + (size_t)warp * VD;
        float s = 0.f;
        for (int i = lane; i < VD; i += 32) s += fabsf(row[i]);
        for (int o = 16; o; o >>= 1) s += __shfl_xor_sync(0xffffffffu, s, o);
        if (lane == 0) g_vmask[warp] = (s == 0.f) ? 1 : 0;
    } else {
        int r = warp - B * VN;
        if (r < B * QN) {
            const float* row = q + (size_t)r * QD;
            float s = 0.f;
            for (int i = lane; i < QD; i += 32) s += fabsf(row[i]);
            for (int o = 16; o; o >>= 1) s += __shfl_xor_sync(0xffffffffu, s, o);
            if (lane == 0) g_qmask[r] = (s == 0.f) ? 1 : 0;
        }
    }
}

// ---------------- prep: head weights + sum row ------------------------------
__global__ void hw_kernel(const float* __restrict__ h_mat, const float* __restrict__ h_bias) {
    int k = blockIdx.x * blockDim.x + threadIdx.x;
    if (k < HK) {
        float s = 0.f;
#pragma unroll
        for (int h = 0; h < HOUT; h++) {
            float w = h_mat[h * HK + k];
            g_hw[h * HK + k] = w;
            s += w;
        }
        g_hw[HOUT * HK + k] = s;
    }
    if (blockIdx.x == 0 && threadIdx.x == 0) {
        float s = 0.f;
#pragma unroll
        for (int h = 0; h < HOUT; h++) s += h_bias[h];
        g_hbsum = s;
    }
}

// ---------------- projection: Y = relu(X @ W^T + bias) ----------------------
// X: [4096, KD] row-major, W: [1536, KD] row-major, Y: [4096, 1536]
// 64x64 tile, kc=8, 256 threads, 4x4 microtile
template <int KD, int IS_V>
__global__ void proj_kernel(const float* __restrict__ X, const float* __restrict__ W,
                            const float* __restrict__ bias) {
    __shared__ __align__(16) float Xs[8][64];
    __shared__ __align__(16) float Ws[8][64];
    float* __restrict__ Y = IS_V ? g_v : g_q;

    int tid = threadIdx.x;
    int tx = tid & 15, ty = tid >> 4;
    int m0 = blockIdx.y * 64, n0 = blockIdx.x * 64;

    float acc[4][4];
#pragma unroll
    for (int i = 0; i < 4; i++)
#pragma unroll
        for (int j = 0; j < 4; j++) acc[i][j] = 0.f;

    for (int k0 = 0; k0 < KD; k0 += 8) {
        if (tid < 128) {
            int row = tid >> 1, part = (tid & 1) * 4;
            float4 x4 = *(const float4*)(X + (size_t)(m0 + row) * KD + k0 + part);
            Xs[part + 0][row] = x4.x; Xs[part + 1][row] = x4.y;
            Xs[part + 2][row] = x4.z; Xs[part + 3][row] = x4.w;
        } else {
            int t = tid - 128;
            int row = t >> 1, part = (t & 1) * 4;
            float4 w4 = *(const float4*)(W + (size_t)(n0 + row) * KD + k0 + part);
            Ws[part + 0][row] = w4.x; Ws[part + 1][row] = w4.y;
            Ws[part + 2][row] = w4.z; Ws[part + 3][row] = w4.w;
        }
        __syncthreads();
#pragma unroll
        for (int kk = 0; kk < 8; kk++) {
            float4 av = *(const float4*)&Xs[kk][ty * 4];
            float4 bv = *(const float4*)&Ws[kk][tx * 4];
            float ar[4] = {av.x, av.y, av.z, av.w};
            float br[4] = {bv.x, bv.y, bv.z, bv.w};
#pragma unroll
            for (int i = 0; i < 4; i++)
#pragma unroll
                for (int j = 0; j < 4; j++) acc[i][j] = fmaf(ar[i], br[j], acc[i][j]);
        }
        __syncthreads();
    }

    float4 bia = *(const float4*)(bias + n0 + tx * 4);
    float br[4] = {bia.x, bia.y, bia.z, bia.w};
#pragma unroll
    for (int i = 0; i < 4; i++) {
        int r = m0 + ty * 4 + i;
        float4 o;
        o.x = fmaxf(acc[i][0] + br[0], 0.f);
        o.y = fmaxf(acc[i][1] + br[1], 0.f);
        o.z = fmaxf(acc[i][2] + br[2], 0.f);
        o.w = fmaxf(acc[i][3] + br[3], 0.f);
        *(float4*)(Y + (size_t)r * HK + n0 + tx * 4) = o;
    }
}

// ---------------- att: 9-head tile kernel ----------------------------------
// att[b,h,v,q] = sum_k h[h,k] v_[b,v,k] q_[b,q,k] + h_bias[h]  (h=0..7)
// S[b,v,q]     = sum over "head 8" (= sum of all head rows) + sum(h_bias)
// 32x32 (v x q) tile per block, 256 threads, 2x2 microtile, 9 accumulator sets
__global__ void att_kernel(const float* __restrict__ h_bias, float* __restrict__ att) {
    __shared__ float vs[16][32];
    __shared__ float qs[16][32];
    __shared__ float hs[16][9];

    int b  = blockIdx.z;
    int v0 = blockIdx.y * 32, q0 = blockIdx.x * 32;
    int tid = threadIdx.x;
    int tx = tid & 15, ty = tid >> 4;

    const float* vp = g_v + ((size_t)b * VN + v0) * HK;
    const float* qp = g_q + ((size_t)b * QN + q0) * HK;

    float acc[9][4];
#pragma unroll
    for (int h = 0; h < 9; h++)
#pragma unroll
        for (int j = 0; j < 4; j++) acc[h][j] = 0.f;

    for (int k0 = 0; k0 < HK; k0 += 16) {
        if (tid < 128) {
            int row = tid >> 2, part = (tid & 3) * 4;
            float4 x = *(const float4*)(vp + (size_t)row * HK + k0 + part);
            vs[part + 0][row] = x.x; vs[part + 1][row] = x.y;
            vs[part + 2][row] = x.z; vs[part + 3][row] = x.w;
        } else {
            int t = tid - 128;
            int row = t >> 2, part = (t & 3) * 4;
            float4 x = *(const float4*)(qp + (size_t)row * HK + k0 + part);
            qs[part + 0][row] = x.x; qs[part + 1][row] = x.y;
            qs[part + 2][row] = x.z; qs[part + 3][row] = x.w;
        }
        if (tid < 144) {
            int kk = tid / 9, h = tid % 9;
            hs[kk][h] = g_hw[h * HK + k0 + kk];
        }
        __syncthreads();
#pragma unroll
        for (int kk = 0; kk < 16; kk++) {
            float va = vs[kk][ty * 2], vb = vs[kk][ty * 2 + 1];
            float qa = qs[kk][tx * 2], qb = qs[kk][tx * 2 + 1];
            float p00 = va * qa, p01 = va * qb, p10 = vb * qa, p11 = vb * qb;
#pragma unroll
            for (int h = 0; h < 9; h++) {
                float w = hs[kk][h];
                acc[h][0] = fmaf(w, p00, acc[h][0]);
                acc[h][1] = fmaf(w, p01, acc[h][1]);
                acc[h][2] = fmaf(w, p10, acc[h][2]);
                acc[h][3] = fmaf(w, p11, acc[h][3]);
            }
        }
        __syncthreads();
    }

    int r = v0 + ty * 2, c = q0 + tx * 2;
    bool vm0 = g_vmask[b * VN + r] != 0, vm1 = g_vmask[b * VN + r + 1] != 0;
    bool qm0 = g_qmask[b * QN + c] != 0, qm1 = g_qmask[b * QN + c + 1] != 0;
    float NI = neg_inf();

#pragma unroll
    for (int h = 0; h < HOUT; h++) {
        float bi = h_bias[h];
        size_t base = (((size_t)b * HOUT + h) * VN + r) * QN + c;
        att[base]          = (vm0 || qm0) ? NI : acc[h][0] + bi;
        att[base + 1]      = (vm0 || qm1) ? NI : acc[h][1] + bi;
        att[base + QN]     = (vm1 || qm0) ? NI : acc[h][2] + bi;
        att[base + QN + 1] = (vm1 || qm1) ? NI : acc[h][3] + bi;
    }
    {
        float bs = g_hbsum;
        size_t base = ((size_t)b * VN + r) * QN + c;
        g_S[base]          = (vm0 || qm0) ? NI : acc[8][0] + bs;
        g_S[base + 1]      = (vm0 || qm1) ? NI : acc[8][1] + bs;
        g_S[base + QN]     = (vm1 || qm0) ? NI : acc[8][2] + bs;
        g_S[base + QN + 1] = (vm1 || qm1) ? NI : acc[8][3] + bs;
    }
}

// ---------------- pooling GEMM + v-reduction --------------------------------
// T[v,k] = sum_q S[b,v,q] q_[b,q,k];  logits_k[b,k] = sum_v v_[b,v,k] T[v,k]
// Per block: one b, one 64-wide k tile, loops all v.
__global__ void pool_kernel() {
    __shared__ __align__(16) float Ss[8][64];
    __shared__ __align__(16) float Qs[8][64];
    __shared__ float red[16][64];

    int b = blockIdx.y;
    int k0 = blockIdx.x * 64;
    int tid = threadIdx.x;
    int tx = tid & 15, ty = tid >> 4;

    const float* Sp = g_S + (size_t)b * VN * QN;
    const float* Qp = g_q + (size_t)b * QN * HK;
    const float* Vp = g_v + (size_t)b * VN * HK;

    float psum[4] = {0.f, 0.f, 0.f, 0.f};

    for (int v0 = 0; v0 < VN; v0 += 64) {
        float t[4][4];
#pragma unroll
        for (int i = 0; i < 4; i++)
#pragma unroll
            for (int j = 0; j < 4; j++) t[i][j] = 0.f;

        for (int q0 = 0; q0 < QN; q0 += 8) {
            if (tid < 128) {
                int row = tid >> 1, part = (tid & 1) * 4;
                float4 x = *(const float4*)(Sp + (size_t)(v0 + row) * QN + q0 + part);
                Ss[part + 0][row] = x.x; Ss[part + 1][row] = x.y;
                Ss[part + 2][row] = x.z; Ss[part + 3][row] = x.w;
            } else {
                int t2 = tid - 128;
                int row = t2 >> 4, col = (t2 & 15) * 4;
                float4 x = *(const float4*)(Qp + (size_t)(q0 + row) * HK + k0 + col);
                *(float4*)&Qs[row][col] = x;
            }
            __syncthreads();
#pragma unroll
            for (int kk = 0; kk < 8; kk++) {
                float4 av = *(const float4*)&Ss[kk][ty * 4];
                float4 bv = *(const float4*)&Qs[kk][tx * 4];
                float ar[4] = {av.x, av.y, av.z, av.w};
                float br[4] = {bv.x, bv.y, bv.z, bv.w};
#pragma unroll
                for (int i = 0; i < 4; i++)
#pragma unroll
                    for (int j = 0; j < 4; j++) t[i][j] = fmaf(ar[i], br[j], t[i][j]);
            }
            __syncthreads();
        }
#pragma unroll
        for (int i = 0; i < 4; i++) {
            float4 vv = *(const float4*)(Vp + (size_t)(v0 + ty * 4 + i) * HK + k0 + tx * 4);
            psum[0] = fmaf(t[i][0], vv.x, psum[0]);
            psum[1] = fmaf(t[i][1], vv.y, psum[1]);
            psum[2] = fmaf(t[i][2], vv.z, psum[2]);
            psum[3] = fmaf(t[i][3], vv.w, psum[3]);
        }
    }

#pragma unroll
    for (int j = 0; j < 4; j++) red[ty][tx * 4 + j] = psum[j];
    __syncthreads();
    if (tid < 64) {
        float s = 0.f;
#pragma unroll
        for (int i = 0; i < 16; i++) s += red[i][tid];
        g_lk[b * HK + k0 + tid] = s;
    }
}

// ---------------- pool-of-3 + BatchNorm (batch stats) ------------------------
__global__ void bn_kernel(const float* __restrict__ gamma, const float* __restrict__ beta,
                          float* __restrict__ out) {
    int c = blockIdx.x * blockDim.x + threadIdx.x;
    if (c >= HD) return;
    float x[B];
    float mu = 0.f;
#pragma unroll
    for (int b = 0; b < B; b++) {
        const float* p = g_lk + b * HK + c * KP;
        x[b] = p[0] + p[1] + p[2];
        mu += x[b];
    }
    mu *= (1.f / B);
    float var = 0.f;
#pragma unroll
    for (int b = 0; b < B; b++) {
        float d = x[b] - mu;
        var = fmaf(d, d, var);
    }
    var *= (1.f / B);
    float scale = rsqrtf(var + 1e-5f) * gamma[c];
    float bet = beta[c];
#pragma unroll
    for (int b = 0; b < B; b++) out[b * HD + c] = (x[b] - mu) * scale + bet;
}

// ---------------- launcher ---------------------------------------------------
extern "C" void kernel_launch(void* const* d_in, const int* in_sizes, int n_in,
                              void* d_out, int out_size) {
    const float* v      = (const float*)d_in[0];
    const float* q      = (const float*)d_in[1];
    const float* Wv     = (const float*)d_in[2];
    const float* bv     = (const float*)d_in[3];
    const float* Wq     = (const float*)d_in[4];
    const float* bq     = (const float*)d_in[5];
    const float* h_mat  = (const float*)d_in[6];
    const float* h_bias = (const float*)d_in[7];
    const float* gamma  = (const float*)d_in[8];
    const float* beta   = (const float*)d_in[9];

    float* out    = (float*)d_out;
    float* logits = out;                 // [16, 512]
    float* att    = out + B * HD;        // [16, 8, 256, 256]

    mask_kernel<<<1024, 256>>>(v, q);
    hw_kernel<<<(HK + 255) / 256, 256>>>(h_mat, h_bias);

    {
        dim3 grid(HK / 64, (B * VN) / 64);
        proj_kernel<VD, 1><<<grid, 256>>>(v, Wv, bv);
    }
    {
        dim3 grid(HK / 64, (B * QN) / 64);
        proj_kernel<QD, 0><<<grid, 256>>>(q, Wq, bq);
    }
    {
        dim3 grid(QN / 32, VN / 32, B);
        att_kernel<<<grid, 256>>>(h_bias, att);
    }
    {
        dim3 grid(HK / 64, B);
        pool_kernel<<<grid, 256>>>();
    }
    bn_kernel<<<(HD + 255) / 256, 256>>>(gamma, beta, logits);
}

// round 4
// speedup vs baseline: 2.0412x; 2.0412x over previous
#include <cuda_runtime.h>
#include <cuda_bf16.h>
#include <stdint.h>
#include <math.h>

#define B    16
#define VN   256
#define QN   256
#define VD   512
#define QD   768
#define HK   1536
#define HOUT 8
#define HD   512
#define KP   3

// ---------------- scratch (device globals) ----------------------------------
__device__ float g_v[B * VN * HK];                 // v_ fp32
__device__ float g_q[B * QN * HK];                 // q_ fp32
__device__ __nv_bfloat16 g_qh[B * QN * HK];        // q_ bf16 hi
__device__ __nv_bfloat16 g_ql[B * QN * HK];        // q_ bf16 lo
__device__ float g_S[B * VN * QN];                 // sum-over-heads att
__device__ float g_lk[B * HK];
__device__ float g_hw[(HOUT + 1) * HK];            // 8 head rows + sum row
__device__ float g_hbsum;
__device__ unsigned char g_vmask[B * VN];
__device__ unsigned char g_qmask[B * QN];

static __device__ __forceinline__ uint32_t smem_u32(const void* p) {
    uint32_t a;
    asm("{ .reg .u64 t; cvta.to.shared.u64 t, %1; cvt.u32.u64 %0, t; }"
        : "=r"(a) : "l"(p));
    return a;
}

#define LDMX4(d, addr) \
    asm volatile("ldmatrix.sync.aligned.m8n8.x4.shared.b16 {%0,%1,%2,%3}, [%4];" \
                 : "=r"((d)[0]), "=r"((d)[1]), "=r"((d)[2]), "=r"((d)[3]) \
                 : "r"(addr))

#define MMA16816(c, a, b0, b1) \
    asm volatile("mma.sync.aligned.m16n8k16.row.col.f32.bf16.bf16.f32 " \
                 "{%0,%1,%2,%3}, {%4,%5,%6,%7}, {%8,%9}, {%0,%1,%2,%3};" \
                 : "+f"((c)[0]), "+f"((c)[1]), "+f"((c)[2]), "+f"((c)[3]) \
                 : "r"((a)[0]), "r"((a)[1]), "r"((a)[2]), "r"((a)[3]), \
                   "r"(b0), "r"(b1))

static __device__ __forceinline__ void split2(float x0, float x1,
                                              uint32_t& hi, uint32_t& lo) {
    __nv_bfloat16 h0 = __float2bfloat16(x0);
    __nv_bfloat16 h1 = __float2bfloat16(x1);
    float l0 = x0 - __bfloat162float(h0);
    float l1 = x1 - __bfloat162float(h1);
    hi = (uint32_t)__bfloat16_as_ushort(h0) |
         ((uint32_t)__bfloat16_as_ushort(h1) << 16);
    lo = (uint32_t)__bfloat16_as_ushort(__float2bfloat16(l0)) |
         ((uint32_t)__bfloat16_as_ushort(__float2bfloat16(l1)) << 16);
}

// ---------------- prep kernels ----------------------------------------------
__global__ void mask_kernel(const float* __restrict__ v, const float* __restrict__ q) {
    int warp = (blockIdx.x * blockDim.x + threadIdx.x) >> 5;
    int lane = threadIdx.x & 31;
    if (warp < B * VN) {
        const float* row = v + (size_t)warp * VD;
        float s = 0.f;
        for (int i = lane; i < VD; i += 32) s += fabsf(row[i]);
        for (int o = 16; o; o >>= 1) s += __shfl_xor_sync(0xffffffffu, s, o);
        if (lane == 0) g_vmask[warp] = (s == 0.f) ? 1 : 0;
    } else {
        int r = warp - B * VN;
        if (r < B * QN) {
            const float* row = q + (size_t)r * QD;
            float s = 0.f;
            for (int i = lane; i < QD; i += 32) s += fabsf(row[i]);
            for (int o = 16; o; o >>= 1) s += __shfl_xor_sync(0xffffffffu, s, o);
            if (lane == 0) g_qmask[r] = (s == 0.f) ? 1 : 0;
        }
    }
}

__global__ void hw_kernel(const float* __restrict__ h_mat, const float* __restrict__ h_bias) {
    int k = blockIdx.x * blockDim.x + threadIdx.x;
    if (k < HK) {
        float s = 0.f;
#pragma unroll
        for (int h = 0; h < HOUT; h++) {
            float w = h_mat[h * HK + k];
            g_hw[h * HK + k] = w;
            s += w;
        }
        g_hw[HOUT * HK + k] = s;
    }
    if (blockIdx.x == 0 && threadIdx.x == 0) {
        float s = 0.f;
#pragma unroll
        for (int h = 0; h < HOUT; h++) s += h_bias[h];
        g_hbsum = s;
    }
}

// ---------------- bf16-split HMMA GEMM ---------------------------------------
// MODE 0: g_v = relu(v @ Wv^T + bv)                M=4096 N=1536 K=512
// MODE 1: g_q = relu(q @ Wq^T + bq) + bf16 hi/lo   M=4096 N=1536 K=768
// MODE 2: att[b,h] = (v_ .* h_w[h]) @ q_^T + bias  (z = b*9+h; h==8 -> S)
// Block: 256 thr (8 warps, 2x4), tile 128x128, warp 64x32, K-chunk 32.
// smem row stride: 40 bf16 = 80 B (conflict-free for ldmatrix).
#define SP   40
#define ABY  (128 * SP * 2)     // 10240 B per array
#define STG  (4 * ABY)          // stage bytes

template <int MODE, int KD>
__global__ __launch_bounds__(256) void mma_kernel(
    const float* __restrict__ Af, const float* __restrict__ Bf,
    const float* __restrict__ bias, float* __restrict__ attout) {
    extern __shared__ char smem[];
    const uint32_t sb = smem_u32(smem);
    const int tid = threadIdx.x;
    const int lane = tid & 31;
    const int wid = tid >> 5;
    const int wm = wid >> 2;          // 0..1
    const int wn = wid & 3;           // 0..3
    const int CH = KD / 32;

    int bz = 0, hz = 0;
    if (MODE == 2) { bz = blockIdx.z / 9; hz = blockIdx.z - bz * 9; }
    const int m0 = blockIdx.y * 128;
    const int n0 = blockIdx.x * 128;

    const float* Ap = (MODE == 2) ? (g_v + (size_t)bz * VN * HK) : Af;
    const float* wrow = (MODE == 2) ? (g_hw + hz * HK) : (const float*)0;
    const __nv_bfloat16* Qh = g_qh + (size_t)bz * QN * HK;
    const __nv_bfloat16* Ql = g_ql + (size_t)bz * QN * HK;

    // ldmatrix per-lane byte offsets within a stage
    const int arow = wm * 64 + (lane & 15);
    const int acol = (lane & 16) ? 8 : 0;
    const uint32_t aoff = (uint32_t)(arow * SP + acol) * 2;
    const int brow = wn * 32 + (lane & 7) + ((lane & 16) ? 8 : 0);
    const int bcol = (lane & 8) ? 8 : 0;
    const uint32_t boff = (uint32_t)(brow * SP + bcol) * 2;

    float acc[4][4][4];
#pragma unroll
    for (int i = 0; i < 4; i++)
#pragma unroll
        for (int j = 0; j < 4; j++)
#pragma unroll
            for (int e = 0; e < 4; e++) acc[i][j][e] = 0.f;

    // prefetch registers
    float4 ra[4], rb[4], rw[4];
    uint4 rqh[2], rql[2];

    // ---- load chunk -> regs ----
    auto load_regs = [&](int c) {
        int k0 = c * 32;
#pragma unroll
        for (int i = 0; i < 4; i++) {
            int idx = tid + i * 256;
            int r = idx >> 3, c4 = idx & 7;
            ra[i] = *(const float4*)(Ap + (size_t)(m0 + r) * KD + k0 + c4 * 4);
            if (MODE == 2) rw[i] = *(const float4*)(wrow + k0 + c4 * 4);
        }
        if (MODE == 2) {
#pragma unroll
            for (int i = 0; i < 2; i++) {
                int idx = tid + i * 256;
                int r = idx >> 2, qt = idx & 3;
                rqh[i] = *(const uint4*)(Qh + (size_t)(n0 + r) * HK + k0 + qt * 8);
                rql[i] = *(const uint4*)(Ql + (size_t)(n0 + r) * HK + k0 + qt * 8);
            }
        } else {
#pragma unroll
            for (int i = 0; i < 4; i++) {
                int idx = tid + i * 256;
                int r = idx >> 3, c4 = idx & 7;
                rb[i] = *(const float4*)(Bf + (size_t)(n0 + r) * KD + k0 + c4 * 4);
            }
        }
    };

    // ---- regs -> smem (split bf16) ----
    auto store_smem = [&](int s) {
        char* st = smem + s * STG;
#pragma unroll
        for (int i = 0; i < 4; i++) {
            int idx = tid + i * 256;
            int r = idx >> 3, c4 = idx & 7;
            float4 x = ra[i];
            if (MODE == 2) {
                x.x *= rw[i].x; x.y *= rw[i].y; x.z *= rw[i].z; x.w *= rw[i].w;
            }
            uint2 hi, lo;
            split2(x.x, x.y, hi.x, lo.x);
            split2(x.z, x.w, hi.y, lo.y);
            uint32_t off = (uint32_t)r * (SP * 2) + c4 * 8;
            *(uint2*)(st + off) = hi;
            *(uint2*)(st + ABY + off) = lo;
        }
        if (MODE == 2) {
#pragma unroll
            for (int i = 0; i < 2; i++) {
                int idx = tid + i * 256;
                int r = idx >> 2, qt = idx & 3;
                uint32_t off = (uint32_t)r * (SP * 2) + qt * 16;
                *(uint4*)(st + 2 * ABY + off) = rqh[i];
                *(uint4*)(st + 3 * ABY + off) = rql[i];
            }
        } else {
#pragma unroll
            for (int i = 0; i < 4; i++) {
                int idx = tid + i * 256;
                int r = idx >> 3, c4 = idx & 7;
                uint2 hi, lo;
                split2(rb[i].x, rb[i].y, hi.x, lo.x);
                split2(rb[i].z, rb[i].w, hi.y, lo.y);
                uint32_t off = (uint32_t)r * (SP * 2) + c4 * 8;
                *(uint2*)(st + 2 * ABY + off) = hi;
                *(uint2*)(st + 3 * ABY + off) = lo;
            }
        }
    };

    load_regs(0);
    store_smem(0);
    __syncthreads();

    for (int c = 0; c < CH; ++c) {
        bool more = (c + 1 < CH);
        if (more) load_regs(c + 1);

        uint32_t stg = sb + (uint32_t)(c & 1) * STG;
        uint32_t aAh = stg + aoff;
        uint32_t aBh = stg + 2 * ABY + boff;
#pragma unroll
        for (int ks = 0; ks < 2; ks++) {
            uint32_t ah[4][4], al[4][4];
#pragma unroll
            for (int mi = 0; mi < 4; mi++) {
                uint32_t ad = aAh + mi * (16 * SP * 2) + ks * 32;
                LDMX4(ah[mi], ad);
                LDMX4(al[mi], ad + ABY);
            }
            uint32_t bh[2][4], bl[2][4];
#pragma unroll
            for (int np = 0; np < 2; np++) {
                uint32_t bd = aBh + np * (16 * SP * 2) + ks * 32;
                LDMX4(bh[np], bd);
                LDMX4(bl[np], bd + ABY);
            }
#pragma unroll
            for (int mi = 0; mi < 4; mi++)
#pragma unroll
                for (int nj = 0; nj < 4; nj++) {
                    uint32_t b0h = bh[nj >> 1][(nj & 1) * 2];
                    uint32_t b1h = bh[nj >> 1][(nj & 1) * 2 + 1];
                    uint32_t b0l = bl[nj >> 1][(nj & 1) * 2];
                    uint32_t b1l = bl[nj >> 1][(nj & 1) * 2 + 1];
                    MMA16816(acc[mi][nj], ah[mi], b0h, b1h);
                    MMA16816(acc[mi][nj], al[mi], b0h, b1h);
                    MMA16816(acc[mi][nj], ah[mi], b0l, b1l);
                }
        }
        if (more) store_smem((c + 1) & 1);
        __syncthreads();
    }

    // ---- epilogue: C fragments -> global ----
    const int gid = lane >> 2, tig = lane & 3;

    if (MODE <= 1) {
        float* Yf = (MODE == 0) ? g_v : g_q;
#pragma unroll
        for (int mi = 0; mi < 4; mi++) {
#pragma unroll
            for (int nj = 0; nj < 4; nj++) {
                int row = m0 + wm * 64 + mi * 16 + gid;
                int col = n0 + wn * 32 + nj * 8 + tig * 2;
                float b0 = bias[col], b1 = bias[col + 1];
                float v0 = fmaxf(acc[mi][nj][0] + b0, 0.f);
                float v1 = fmaxf(acc[mi][nj][1] + b1, 0.f);
                float v2 = fmaxf(acc[mi][nj][2] + b0, 0.f);
                float v3 = fmaxf(acc[mi][nj][3] + b1, 0.f);
                size_t o0 = (size_t)row * HK + col;
                size_t o1 = (size_t)(row + 8) * HK + col;
                *(float2*)(Yf + o0) = make_float2(v0, v1);
                *(float2*)(Yf + o1) = make_float2(v2, v3);
                if (MODE == 1) {
                    uint32_t h0, l0, h1, l1;
                    split2(v0, v1, h0, l0);
                    split2(v2, v3, h1, l1);
                    *(uint32_t*)(g_qh + o0) = h0;
                    *(uint32_t*)(g_ql + o0) = l0;
                    *(uint32_t*)(g_qh + o1) = h1;
                    *(uint32_t*)(g_ql + o1) = l1;
                }
            }
        }
    } else {
        float NI = __int_as_float(0xff800000);
        float hb = (hz < 8) ? bias[hz] : g_hbsum;
        float* dst = (hz < 8)
            ? (attout + (((size_t)bz * HOUT + hz) * VN + m0) * QN + n0)
            : (g_S + ((size_t)bz * VN + m0) * QN + n0);
#pragma unroll
        for (int mi = 0; mi < 4; mi++) {
#pragma unroll
            for (int nj = 0; nj < 4; nj++) {
                int rl = wm * 64 + mi * 16 + gid;
                int cl = wn * 32 + nj * 8 + tig * 2;
                bool vm0 = g_vmask[bz * VN + m0 + rl] != 0;
                bool vm1 = g_vmask[bz * VN + m0 + rl + 8] != 0;
                bool qm0 = g_qmask[bz * QN + n0 + cl] != 0;
                bool qm1 = g_qmask[bz * QN + n0 + cl + 1] != 0;
                float v0 = (vm0 || qm0) ? NI : acc[mi][nj][0] + hb;
                float v1 = (vm0 || qm1) ? NI : acc[mi][nj][1] + hb;
                float v2 = (vm1 || qm0) ? NI : acc[mi][nj][2] + hb;
                float v3 = (vm1 || qm1) ? NI : acc[mi][nj][3] + hb;
                *(float2*)(dst + (size_t)rl * QN + cl) = make_float2(v0, v1);
                *(float2*)(dst + (size_t)(rl + 8) * QN + cl) = make_float2(v2, v3);
            }
        }
    }
}

// ---------------- pooling GEMM + v-reduction (fp32) --------------------------
__global__ void pool_kernel() {
    __shared__ __align__(16) float Ss[8][64];
    __shared__ __align__(16) float Qs[8][64];
    __shared__ float red[16][64];

    int b = blockIdx.y;
    int k0 = blockIdx.x * 64;
    int tid = threadIdx.x;
    int tx = tid & 15, ty = tid >> 4;

    const float* Sp = g_S + (size_t)b * VN * QN;
    const float* Qp = g_q + (size_t)b * QN * HK;
    const float* Vp = g_v + (size_t)b * VN * HK;

    float psum[4] = {0.f, 0.f, 0.f, 0.f};

    for (int v0 = 0; v0 < VN; v0 += 64) {
        float t[4][4];
#pragma unroll
        for (int i = 0; i < 4; i++)
#pragma unroll
            for (int j = 0; j < 4; j++) t[i][j] = 0.f;

        for (int q0 = 0; q0 < QN; q0 += 8) {
            if (tid < 128) {
                int row = tid >> 1, part = (tid & 1) * 4;
                float4 x = *(const float4*)(Sp + (size_t)(v0 + row) * QN + q0 + part);
                Ss[part + 0][row] = x.x; Ss[part + 1][row] = x.y;
                Ss[part + 2][row] = x.z; Ss[part + 3][row] = x.w;
            } else {
                int t2 = tid - 128;
                int row = t2 >> 4, col = (t2 & 15) * 4;
                float4 x = *(const float4*)(Qp + (size_t)(q0 + row) * HK + k0 + col);
                *(float4*)&Qs[row][col] = x;
            }
            __syncthreads();
#pragma unroll
            for (int kk = 0; kk < 8; kk++) {
                float4 av = *(const float4*)&Ss[kk][ty * 4];
                float4 bv = *(const float4*)&Qs[kk][tx * 4];
                float ar[4] = {av.x, av.y, av.z, av.w};
                float br[4] = {bv.x, bv.y, bv.z, bv.w};
#pragma unroll
                for (int i = 0; i < 4; i++)
#pragma unroll
                    for (int j = 0; j < 4; j++) t[i][j] = fmaf(ar[i], br[j], t[i][j]);
            }
            __syncthreads();
        }
#pragma unroll
        for (int i = 0; i < 4; i++) {
            float4 vv = *(const float4*)(Vp + (size_t)(v0 + ty * 4 + i) * HK + k0 + tx * 4);
            psum[0] = fmaf(t[i][0], vv.x, psum[0]);
            psum[1] = fmaf(t[i][1], vv.y, psum[1]);
            psum[2] = fmaf(t[i][2], vv.z, psum[2]);
            psum[3] = fmaf(t[i][3], vv.w, psum[3]);
        }
    }

#pragma unroll
    for (int j = 0; j < 4; j++) red[ty][tx * 4 + j] = psum[j];
    __syncthreads();
    if (tid < 64) {
        float s = 0.f;
#pragma unroll
        for (int i = 0; i < 16; i++) s += red[i][tid];
        g_lk[b * HK + k0 + tid] = s;
    }
}

// ---------------- pool-of-3 + BatchNorm --------------------------------------
__global__ void bn_kernel(const float* __restrict__ gamma, const float* __restrict__ beta,
                          float* __restrict__ out) {
    int c = blockIdx.x * blockDim.x + threadIdx.x;
    if (c >= HD) return;
    float x[B];
    float mu = 0.f;
#pragma unroll
    for (int b = 0; b < B; b++) {
        const float* p = g_lk + b * HK + c * KP;
        x[b] = p[0] + p[1] + p[2];
        mu += x[b];
    }
    mu *= (1.f / B);
    float var = 0.f;
#pragma unroll
    for (int b = 0; b < B; b++) {
        float d = x[b] - mu;
        var = fmaf(d, d, var);
    }
    var *= (1.f / B);
    float scale = rsqrtf(var + 1e-5f) * gamma[c];
    float bet = beta[c];
#pragma unroll
    for (int b = 0; b < B; b++) out[b * HD + c] = (x[b] - mu) * scale + bet;
}

// ---------------- launcher ----------------------------------------------------
extern "C" void kernel_launch(void* const* d_in, const int* in_sizes, int n_in,
                              void* d_out, int out_size) {
    const float* v      = (const float*)d_in[0];
    const float* q      = (const float*)d_in[1];
    const float* Wv     = (const float*)d_in[2];
    const float* bv     = (const float*)d_in[3];
    const float* Wq     = (const float*)d_in[4];
    const float* bq     = (const float*)d_in[5];
    const float* h_mat  = (const float*)d_in[6];
    const float* h_bias = (const float*)d_in[7];
    const float* gamma  = (const float*)d_in[8];
    const float* beta   = (const float*)d_in[9];

    float* out    = (float*)d_out;
    float* logits = out;
    float* att    = out + B * HD;

    const int SMB = 2 * STG;   // 81920 bytes
    cudaFuncSetAttribute(mma_kernel<0, VD>,
                         cudaFuncAttributeMaxDynamicSharedMemorySize, SMB);
    cudaFuncSetAttribute(mma_kernel<1, QD>,
                         cudaFuncAttributeMaxDynamicSharedMemorySize, SMB);
    cudaFuncSetAttribute(mma_kernel<2, HK>,
                         cudaFuncAttributeMaxDynamicSharedMemorySize, SMB);

    mask_kernel<<<1024, 256>>>(v, q);
    hw_kernel<<<(HK + 255) / 256, 256>>>(h_mat, h_bias);

    mma_kernel<0, VD><<<dim3(HK / 128, (B * VN) / 128, 1), 256, SMB>>>(
        v, Wv, bv, (float*)0);
    mma_kernel<1, QD><<<dim3(HK / 128, (B * QN) / 128, 1), 256, SMB>>>(
        q, Wq, bq, (float*)0);
    mma_kernel<2, HK><<<dim3(QN / 128, VN / 128, B * 9), 256, SMB>>>(
        (const float*)0, (const float*)0, h_bias, att);

    pool_kernel<<<dim3(HK / 64, B), 256>>>();
    bn_kernel<<<(HD + 255) / 256, 256>>>(gamma, beta, logits);
}

// round 6
// speedup vs baseline: 2.3174x; 1.1353x over previous
#include <cuda_runtime.h>
#include <cuda_bf16.h>
#include <stdint.h>
#include <math.h>

#define B    16
#define VN   256
#define QN   256
#define VD   512
#define QD   768
#define HK   1536
#define HOUT 8
#define HD   512
#define KP   3

// ---------------- scratch (device globals) ----------------------------------
__device__ float g_v[B * VN * HK];                 // v_ fp32
__device__ float g_q[B * QN * HK];                 // q_ fp32
__device__ __nv_bfloat16 g_qh[B * QN * HK];        // q_ bf16 hi
__device__ __nv_bfloat16 g_ql[B * QN * HK];        // q_ bf16 lo
__device__ float g_S[B * VN * QN];                 // sum-over-heads att
__device__ float g_lk[B * HK];
__device__ float g_hw[(HOUT + 1) * HK];
__device__ unsigned char g_vmask[B * VN];
__device__ unsigned char g_qmask[B * QN];
// pre-split GEMM operands (bf16 hi/lo)
__device__ __nv_bfloat16 g_vsh[B * VN * VD], g_vsl[B * VN * VD];
__device__ __nv_bfloat16 g_qsh[B * QN * QD], g_qsl[B * QN * QD];
__device__ __nv_bfloat16 g_wvh[HK * VD],    g_wvl[HK * VD];
__device__ __nv_bfloat16 g_wqh[HK * QD],    g_wql[HK * QD];

static __device__ __forceinline__ uint32_t smem_u32(const void* p) {
    uint32_t a;
    asm("{ .reg .u64 t; cvta.to.shared.u64 t, %1; cvt.u32.u64 %0, t; }"
        : "=r"(a) : "l"(p));
    return a;
}

#define LDMX4(d, addr) \
    asm volatile("ldmatrix.sync.aligned.m8n8.x4.shared.b16 {%0,%1,%2,%3}, [%4];" \
                 : "=r"((d)[0]), "=r"((d)[1]), "=r"((d)[2]), "=r"((d)[3]) \
                 : "r"(addr))

#define MMA16816(c, a, b0, b1) \
    asm volatile("mma.sync.aligned.m16n8k16.row.col.f32.bf16.bf16.f32 " \
                 "{%0,%1,%2,%3}, {%4,%5,%6,%7}, {%8,%9}, {%0,%1,%2,%3};" \
                 : "+f"((c)[0]), "+f"((c)[1]), "+f"((c)[2]), "+f"((c)[3]) \
                 : "r"((a)[0]), "r"((a)[1]), "r"((a)[2]), "r"((a)[3]), \
                   "r"(b0), "r"(b1))

#define CP16(dst, src) \
    asm volatile("cp.async.cg.shared.global [%0], [%1], 16;" \
                 :: "r"(dst), "l"(src))
#define CP_COMMIT() asm volatile("cp.async.commit_group;" ::: "memory")
#define CP_WAIT0()  asm volatile("cp.async.wait_group 0;" ::: "memory")

static __device__ __forceinline__ void split2(float x0, float x1,
                                              uint32_t& hi, uint32_t& lo) {
    __nv_bfloat16 h0 = __float2bfloat16(x0);
    __nv_bfloat16 h1 = __float2bfloat16(x1);
    float l0 = x0 - __bfloat162float(h0);
    float l1 = x1 - __bfloat162float(h1);
    hi = (uint32_t)__bfloat16_as_ushort(h0) |
         ((uint32_t)__bfloat16_as_ushort(h1) << 16);
    lo = (uint32_t)__bfloat16_as_ushort(__float2bfloat16(l0)) |
         ((uint32_t)__bfloat16_as_ushort(__float2bfloat16(l1)) << 16);
}

// ---------------- prep kernels ----------------------------------------------
__global__ void mask_kernel(const float* __restrict__ v, const float* __restrict__ q) {
    int warp = (blockIdx.x * blockDim.x + threadIdx.x) >> 5;
    int lane = threadIdx.x & 31;
    if (warp < B * VN) {
        const float* row = v + (size_t)warp * VD;
        float s = 0.f;
        for (int i = lane; i < VD; i += 32) s += fabsf(row[i]);
        for (int o = 16; o; o >>= 1) s += __shfl_xor_sync(0xffffffffu, s, o);
        if (lane == 0) g_vmask[warp] = (s == 0.f) ? 1 : 0;
    } else {
        int r = warp - B * VN;
        if (r < B * QN) {
            const float* row = q + (size_t)r * QD;
            float s = 0.f;
            for (int i = lane; i < QD; i += 32) s += fabsf(row[i]);
            for (int o = 16; o; o >>= 1) s += __shfl_xor_sync(0xffffffffu, s, o);
            if (lane == 0) g_qmask[r] = (s == 0.f) ? 1 : 0;
        }
    }
}

__global__ void hw_kernel(const float* __restrict__ h_mat) {
    int k = blockIdx.x * blockDim.x + threadIdx.x;
    if (k < HK) {
#pragma unroll
        for (int h = 0; h < HOUT; h++) g_hw[h * HK + k] = h_mat[h * HK + k];
    }
}

// split fp32 -> bf16 hi/lo (W selects destination pair)
template <int W>
__global__ void split_kernel(const float* __restrict__ src, int n4) {
    int i = blockIdx.x * blockDim.x + threadIdx.x;
    if (i >= n4) return;
    __nv_bfloat16* dh;
    __nv_bfloat16* dl;
    if (W == 0) { dh = g_vsh; dl = g_vsl; }
    else if (W == 1) { dh = g_qsh; dl = g_qsl; }
    else if (W == 2) { dh = g_wvh; dl = g_wvl; }
    else { dh = g_wqh; dl = g_wql; }
    float4 x = ((const float4*)src)[i];
    uint2 hi, lo;
    split2(x.x, x.y, hi.x, lo.x);
    split2(x.z, x.w, hi.y, lo.y);
    *(uint2*)(dh + (size_t)i * 4) = hi;
    *(uint2*)(dl + (size_t)i * 4) = lo;
}

// ---------------- smem geometry ----------------------------------------------
#define SP   40
#define ABY  (128 * SP * 2)     // 10240 B per array
#define STG  (4 * ABY)          // 40960 B per stage
#define SMB  (2 * STG)          // 81920

// ---------------- pure-bf16 proj GEMM (cp.async) -----------------------------
// MODE 0: g_v = relu(v @ Wv^T + bv)      M=4096 N=1536 K=512
// MODE 1: g_q = relu(q @ Wq^T + bq) + q hi/lo splits   K=768
template <int MODE, int KD>
__global__ __launch_bounds__(256, 2) void gemm01_kernel(const float* __restrict__ bias) {
    extern __shared__ char smem[];
    const uint32_t sb = smem_u32(smem);
    const int tid = threadIdx.x;
    const int lane = tid & 31;
    const int wid = tid >> 5;
    const int wm = wid >> 2, wn = wid & 3;
    const int CH = KD / 32;
    const int m0 = blockIdx.y * 128;
    const int n0 = blockIdx.x * 128;

    const __nv_bfloat16* Agh = (MODE == 0) ? g_vsh : g_qsh;
    const __nv_bfloat16* Agl = (MODE == 0) ? g_vsl : g_qsl;
    const __nv_bfloat16* Bgh = (MODE == 0) ? g_wvh : g_wqh;
    const __nv_bfloat16* Bgl = (MODE == 0) ? g_wvl : g_wql;

    const int arow = wm * 64 + (lane & 15);
    const int acol = (lane & 16) ? 8 : 0;
    const uint32_t aoff = (uint32_t)(arow * SP + acol) * 2;
    const int brow = wn * 32 + (lane & 7) + ((lane & 16) ? 8 : 0);
    const int bcol = (lane & 8) ? 8 : 0;
    const uint32_t boff = (uint32_t)(brow * SP + bcol) * 2;

    float acc[4][4][4];
#pragma unroll
    for (int i = 0; i < 4; i++)
#pragma unroll
        for (int j = 0; j < 4; j++)
#pragma unroll
            for (int e = 0; e < 4; e++) acc[i][j][e] = 0.f;

    auto cp_chunk = [&](int c) {
        int k0 = c * 32;
        uint32_t stg = sb + (uint32_t)(c & 1) * STG;
#pragma unroll
        for (int j = 0; j < 8; j++) {
            int u = tid + j * 256;
            int arr = u >> 9;
            int r = (u >> 2) & 127;
            int seg = u & 3;
            uint32_t dst = stg + (uint32_t)arr * ABY + r * (SP * 2) + seg * 16;
            const __nv_bfloat16* src;
            if (arr == 0)      src = Agh + (size_t)(m0 + r) * KD + k0 + seg * 8;
            else if (arr == 1) src = Agl + (size_t)(m0 + r) * KD + k0 + seg * 8;
            else if (arr == 2) src = Bgh + (size_t)(n0 + r) * KD + k0 + seg * 8;
            else               src = Bgl + (size_t)(n0 + r) * KD + k0 + seg * 8;
            CP16(dst, src);
        }
    };

    cp_chunk(0);
    CP_COMMIT();

    for (int c = 0; c < CH; ++c) {
        CP_WAIT0();
        __syncthreads();
        if (c + 1 < CH) { cp_chunk(c + 1); CP_COMMIT(); }

        uint32_t stg = sb + (uint32_t)(c & 1) * STG;
        uint32_t aAh = stg + aoff;
        uint32_t aBh = stg + 2 * ABY + boff;
#pragma unroll
        for (int ks = 0; ks < 2; ks++) {
            uint32_t ah[4][4], al[4][4];
#pragma unroll
            for (int mi = 0; mi < 4; mi++) {
                uint32_t ad = aAh + mi * (16 * SP * 2) + ks * 32;
                LDMX4(ah[mi], ad);
                LDMX4(al[mi], ad + ABY);
            }
            uint32_t bh[2][4], bl[2][4];
#pragma unroll
            for (int np = 0; np < 2; np++) {
                uint32_t bd = aBh + np * (16 * SP * 2) + ks * 32;
                LDMX4(bh[np], bd);
                LDMX4(bl[np], bd + ABY);
            }
#pragma unroll
            for (int mi = 0; mi < 4; mi++)
#pragma unroll
                for (int nj = 0; nj < 4; nj++) {
                    uint32_t b0h = bh[nj >> 1][(nj & 1) * 2];
                    uint32_t b1h = bh[nj >> 1][(nj & 1) * 2 + 1];
                    uint32_t b0l = bl[nj >> 1][(nj & 1) * 2];
                    uint32_t b1l = bl[nj >> 1][(nj & 1) * 2 + 1];
                    MMA16816(acc[mi][nj], ah[mi], b0h, b1h);
                    MMA16816(acc[mi][nj], al[mi], b0h, b1h);
                    MMA16816(acc[mi][nj], ah[mi], b0l, b1l);
                }
        }
    }

    const int gid = lane >> 2, tig = lane & 3;
    float* Yf = (MODE == 0) ? g_v : g_q;
#pragma unroll
    for (int mi = 0; mi < 4; mi++) {
#pragma unroll
        for (int nj = 0; nj < 4; nj++) {
            int row = m0 + wm * 64 + mi * 16 + gid;
            int col = n0 + wn * 32 + nj * 8 + tig * 2;
            float b0 = bias[col], b1 = bias[col + 1];
            float v0 = fmaxf(acc[mi][nj][0] + b0, 0.f);
            float v1 = fmaxf(acc[mi][nj][1] + b1, 0.f);
            float v2 = fmaxf(acc[mi][nj][2] + b0, 0.f);
            float v3 = fmaxf(acc[mi][nj][3] + b1, 0.f);
            size_t o0 = (size_t)row * HK + col;
            size_t o1 = (size_t)(row + 8) * HK + col;
            *(float2*)(Yf + o0) = make_float2(v0, v1);
            *(float2*)(Yf + o1) = make_float2(v2, v3);
            if (MODE == 1) {
                uint32_t h0, l0, h1, l1;
                split2(v0, v1, h0, l0);
                split2(v2, v3, h1, l1);
                *(uint32_t*)(g_qh + o0) = h0;
                *(uint32_t*)(g_ql + o0) = l0;
                *(uint32_t*)(g_qh + o1) = h1;
                *(uint32_t*)(g_ql + o1) = l1;
            }
        }
    }
}

// ---------------- att GEMM: A = v_ .* h_w[h] (fold+split), B = q hi/lo -------
__global__ __launch_bounds__(256, 2) void att_kernel(
    const float* __restrict__ h_bias, float* __restrict__ attout) {
    extern __shared__ char smem[];
    const uint32_t sb = smem_u32(smem);
    const int tid = threadIdx.x;
    const int lane = tid & 31;
    const int wid = tid >> 5;
    const int wm = wid >> 2, wn = wid & 3;
    const int CH = HK / 32;

    const int bz = blockIdx.z >> 3;
    const int hz = blockIdx.z & 7;
    const int m0 = blockIdx.y * 128;
    const int n0 = blockIdx.x * 128;

    const float* Ap = g_v + (size_t)bz * VN * HK;
    const float* wrow = g_hw + hz * HK;
    const __nv_bfloat16* Qh = g_qh + (size_t)bz * QN * HK;
    const __nv_bfloat16* Ql = g_ql + (size_t)bz * QN * HK;

    const int arow = wm * 64 + (lane & 15);
    const int acol = (lane & 16) ? 8 : 0;
    const uint32_t aoff = (uint32_t)(arow * SP + acol) * 2;
    const int brow = wn * 32 + (lane & 7) + ((lane & 16) ? 8 : 0);
    const int bcol = (lane & 8) ? 8 : 0;
    const uint32_t boff = (uint32_t)(brow * SP + bcol) * 2;

    float acc[4][4][4];
#pragma unroll
    for (int i = 0; i < 4; i++)
#pragma unroll
        for (int j = 0; j < 4; j++)
#pragma unroll
            for (int e = 0; e < 4; e++) acc[i][j][e] = 0.f;

    float4 ra[4];

    auto cpB = [&](int c) {
        int k0 = c * 32;
        uint32_t stg = sb + (uint32_t)(c & 1) * STG;
#pragma unroll
        for (int j = 0; j < 4; j++) {
            int u = tid + j * 256;
            int arr = u >> 9;
            int r = (u >> 2) & 127;
            int seg = u & 3;
            uint32_t dst = stg + (uint32_t)(2 + arr) * ABY + r * (SP * 2) + seg * 16;
            const __nv_bfloat16* src = (arr == 0)
                ? (Qh + (size_t)(n0 + r) * HK + k0 + seg * 8)
                : (Ql + (size_t)(n0 + r) * HK + k0 + seg * 8);
            CP16(dst, src);
        }
    };
    auto ldgA = [&](int c) {
        int k0 = c * 32;
#pragma unroll
        for (int i = 0; i < 4; i++) {
            int idx = tid + i * 256;
            int r = idx >> 3, c4 = idx & 7;
            ra[i] = *(const float4*)(Ap + (size_t)(m0 + r) * HK + k0 + c4 * 4);
        }
    };
    auto stsA = [&](int c) {
        int k0 = c * 32;
        char* st = smem + (c & 1) * STG;
#pragma unroll
        for (int i = 0; i < 4; i++) {
            int idx = tid + i * 256;
            int r = idx >> 3, c4 = idx & 7;
            float4 w = *(const float4*)(wrow + k0 + c4 * 4);
            float4 x = ra[i];
            x.x *= w.x; x.y *= w.y; x.z *= w.z; x.w *= w.w;
            uint2 hi, lo;
            split2(x.x, x.y, hi.x, lo.x);
            split2(x.z, x.w, hi.y, lo.y);
            uint32_t off = (uint32_t)r * (SP * 2) + c4 * 8;
            *(uint2*)(st + off) = hi;
            *(uint2*)(st + ABY + off) = lo;
        }
    };

    cpB(0);
    CP_COMMIT();
    ldgA(0);

    for (int c = 0; c < CH; ++c) {
        CP_WAIT0();
        stsA(c);
        __syncthreads();
        if (c + 1 < CH) { cpB(c + 1); CP_COMMIT(); ldgA(c + 1); }

        uint32_t stg = sb + (uint32_t)(c & 1) * STG;
        uint32_t aAh = stg + aoff;
        uint32_t aBh = stg + 2 * ABY + boff;
#pragma unroll
        for (int ks = 0; ks < 2; ks++) {
            uint32_t ah[4][4], al[4][4];
#pragma unroll
            for (int mi = 0; mi < 4; mi++) {
                uint32_t ad = aAh + mi * (16 * SP * 2) + ks * 32;
                LDMX4(ah[mi], ad);
                LDMX4(al[mi], ad + ABY);
            }
            uint32_t bh[2][4], bl[2][4];
#pragma unroll
            for (int np = 0; np < 2; np++) {
                uint32_t bd = aBh + np * (16 * SP * 2) + ks * 32;
                LDMX4(bh[np], bd);
                LDMX4(bl[np], bd + ABY);
            }
#pragma unroll
            for (int mi = 0; mi < 4; mi++)
#pragma unroll
                for (int nj = 0; nj < 4; nj++) {
                    uint32_t b0h = bh[nj >> 1][(nj & 1) * 2];
                    uint32_t b1h = bh[nj >> 1][(nj & 1) * 2 + 1];
                    uint32_t b0l = bl[nj >> 1][(nj & 1) * 2];
                    uint32_t b1l = bl[nj >> 1][(nj & 1) * 2 + 1];
                    MMA16816(acc[mi][nj], ah[mi], b0h, b1h);
                    MMA16816(acc[mi][nj], al[mi], b0h, b1h);
                    MMA16816(acc[mi][nj], ah[mi], b0l, b1l);
                }
        }
    }

    const int gid = lane >> 2, tig = lane & 3;
    float NI = __int_as_float(0xff800000);
    float hb = h_bias[hz];
    float* dst = attout + (((size_t)bz * HOUT + hz) * VN + m0) * QN + n0;
#pragma unroll
    for (int mi = 0; mi < 4; mi++) {
#pragma unroll
        for (int nj = 0; nj < 4; nj++) {
            int rl = wm * 64 + mi * 16 + gid;
            int cl = wn * 32 + nj * 8 + tig * 2;
            bool vm0 = g_vmask[bz * VN + m0 + rl] != 0;
            bool vm1 = g_vmask[bz * VN + m0 + rl + 8] != 0;
            bool qm0 = g_qmask[bz * QN + n0 + cl] != 0;
            bool qm1 = g_qmask[bz * QN + n0 + cl + 1] != 0;
            float v0 = (vm0 || qm0) ? NI : acc[mi][nj][0] + hb;
            float v1 = (vm0 || qm1) ? NI : acc[mi][nj][1] + hb;
            float v2 = (vm1 || qm0) ? NI : acc[mi][nj][2] + hb;
            float v3 = (vm1 || qm1) ? NI : acc[mi][nj][3] + hb;
            *(float2*)(dst + (size_t)rl * QN + cl) = make_float2(v0, v1);
            *(float2*)(dst + (size_t)(rl + 8) * QN + cl) = make_float2(v2, v3);
        }
    }
}

// ---------------- S = sum over heads of att ----------------------------------
__global__ void sumS_kernel(const float* __restrict__ att) {
    int i = blockIdx.x * blockDim.x + threadIdx.x;
    const int per = VN * QN / 4;                  // float4 per (b,h) slice
    int b = i / per, off = i - b * per;
    const float4* a = (const float4*)att;
    size_t base = (size_t)b * HOUT * per + off;
    float4 s = a[base];
#pragma unroll
    for (int h = 1; h < HOUT; h++) {
        float4 x = a[base + (size_t)h * per];
        s.x += x.x; s.y += x.y; s.z += x.z; s.w += x.w;
    }
    ((float4*)g_S)[(size_t)b * per + off] = s;
}

// ---------------- pooling GEMM + v-reduction (fp32) --------------------------
__global__ void pool_kernel() {
    __shared__ __align__(16) float Ss[8][64];
    __shared__ __align__(16) float Qs[8][64];
    __shared__ float red[16][64];

    int b = blockIdx.y;
    int k0 = blockIdx.x * 64;
    int tid = threadIdx.x;
    int tx = tid & 15, ty = tid >> 4;

    const float* Sp = g_S + (size_t)b * VN * QN;
    const float* Qp = g_q + (size_t)b * QN * HK;
    const float* Vp = g_v + (size_t)b * VN * HK;

    float psum[4] = {0.f, 0.f, 0.f, 0.f};

    for (int v0 = 0; v0 < VN; v0 += 64) {
        float t[4][4];
#pragma unroll
        for (int i = 0; i < 4; i++)
#pragma unroll
            for (int j = 0; j < 4; j++) t[i][j] = 0.f;

        for (int q0 = 0; q0 < QN; q0 += 8) {
            if (tid < 128) {
                int row = tid >> 1, part = (tid & 1) * 4;
                float4 x = *(const float4*)(Sp + (size_t)(v0 + row) * QN + q0 + part);
                Ss[part + 0][row] = x.x; Ss[part + 1][row] = x.y;
                Ss[part + 2][row] = x.z; Ss[part + 3][row] = x.w;
            } else {
                int t2 = tid - 128;
                int row = t2 >> 4, col = (t2 & 15) * 4;
                float4 x = *(const float4*)(Qp + (size_t)(q0 + row) * HK + k0 + col);
                *(float4*)&Qs[row][col] = x;
            }
            __syncthreads();
#pragma unroll
            for (int kk = 0; kk < 8; kk++) {
                float4 av = *(const float4*)&Ss[kk][ty * 4];
                float4 bv = *(const float4*)&Qs[kk][tx * 4];
                float ar[4] = {av.x, av.y, av.z, av.w};
                float br[4] = {bv.x, bv.y, bv.z, bv.w};
#pragma unroll
                for (int i = 0; i < 4; i++)
#pragma unroll
                    for (int j = 0; j < 4; j++) t[i][j] = fmaf(ar[i], br[j], t[i][j]);
            }
            __syncthreads();
        }
#pragma unroll
        for (int i = 0; i < 4; i++) {
            float4 vv = *(const float4*)(Vp + (size_t)(v0 + ty * 4 + i) * HK + k0 + tx * 4);
            psum[0] = fmaf(t[i][0], vv.x, psum[0]);
            psum[1] = fmaf(t[i][1], vv.y, psum[1]);
            psum[2] = fmaf(t[i][2], vv.z, psum[2]);
            psum[3] = fmaf(t[i][3], vv.w, psum[3]);
        }
    }

#pragma unroll
    for (int j = 0; j < 4; j++) red[ty][tx * 4 + j] = psum[j];
    __syncthreads();
    if (tid < 64) {
        float s = 0.f;
#pragma unroll
        for (int i = 0; i < 16; i++) s += red[i][tid];
        g_lk[b * HK + k0 + tid] = s;
    }
}

// ---------------- pool-of-3 + BatchNorm --------------------------------------
__global__ void bn_kernel(const float* __restrict__ gamma, const float* __restrict__ beta,
                          float* __restrict__ out) {
    int c = blockIdx.x * blockDim.x + threadIdx.x;
    if (c >= HD) return;
    float x[B];
    float mu = 0.f;
#pragma unroll
    for (int b = 0; b < B; b++) {
        const float* p = g_lk + b * HK + c * KP;
        x[b] = p[0] + p[1] + p[2];
        mu += x[b];
    }
    mu *= (1.f / B);
    float var = 0.f;
#pragma unroll
    for (int b = 0; b < B; b++) {
        float d = x[b] - mu;
        var = fmaf(d, d, var);
    }
    var *= (1.f / B);
    float scale = rsqrtf(var + 1e-5f) * gamma[c];
    float bet = beta[c];
#pragma unroll
    for (int b = 0; b < B; b++) out[b * HD + c] = (x[b] - mu) * scale + bet;
}

// ---------------- launcher ----------------------------------------------------
extern "C" void kernel_launch(void* const* d_in, const int* in_sizes, int n_in,
                              void* d_out, int out_size) {
    const float* v      = (const float*)d_in[0];
    const float* q      = (const float*)d_in[1];
    const float* Wv     = (const float*)d_in[2];
    const float* bv     = (const float*)d_in[3];
    const float* Wq     = (const float*)d_in[4];
    const float* bq     = (const float*)d_in[5];
    const float* h_mat  = (const float*)d_in[6];
    const float* h_bias = (const float*)d_in[7];
    const float* gamma  = (const float*)d_in[8];
    const float* beta   = (const float*)d_in[9];

    float* out    = (float*)d_out;
    float* logits = out;
    float* att    = out + B * HD;

    cudaFuncSetAttribute(gemm01_kernel<0, VD>,
                         cudaFuncAttributeMaxDynamicSharedMemorySize, SMB);
    cudaFuncSetAttribute(gemm01_kernel<1, QD>,
                         cudaFuncAttributeMaxDynamicSharedMemorySize, SMB);
    cudaFuncSetAttribute(att_kernel,
                         cudaFuncAttributeMaxDynamicSharedMemorySize, SMB);

    mask_kernel<<<1024, 256>>>(v, q);
    hw_kernel<<<(HK + 255) / 256, 256>>>(h_mat);

    split_kernel<0><<<(B * VN * VD / 4 + 255) / 256, 256>>>(v, B * VN * VD / 4);
    split_kernel<1><<<(B * QN * QD / 4 + 255) / 256, 256>>>(q, B * QN * QD / 4);
    split_kernel<2><<<(HK * VD / 4 + 255) / 256, 256>>>(Wv, HK * VD / 4);
    split_kernel<3><<<(HK * QD / 4 + 255) / 256, 256>>>(Wq, HK * QD / 4);

    gemm01_kernel<0, VD><<<dim3(HK / 128, (B * VN) / 128), 256, SMB>>>(bv);
    gemm01_kernel<1, QD><<<dim3(HK / 128, (B * QN) / 128), 256, SMB>>>(bq);

    att_kernel<<<dim3(QN / 128, VN / 128, B * HOUT), 256, SMB>>>(h_bias, att);

    sumS_kernel<<<(B * VN * QN / 4) / 256, 256>>>(att);
    pool_kernel<<<dim3(HK / 64, B), 256>>>();
    bn_kernel<<<(HD + 255) / 256, 256>>>(gamma, beta, logits);
}

// round 7
// speedup vs baseline: 2.7562x; 1.1893x over previous
#include <cuda_runtime.h>
#include <cuda_bf16.h>
#include <stdint.h>
#include <math.h>

#define B    16
#define VN   256
#define QN   256
#define VD   512
#define QD   768
#define HK   1536
#define HOUT 8
#define HD   512
#define KP   3

// ---------------- scratch (device globals) ----------------------------------
__device__ float g_v[B * VN * HK];                 // v_ fp32
__device__ __nv_bfloat16 g_qh[B * QN * HK];        // q_ bf16 hi
__device__ __nv_bfloat16 g_ql[B * QN * HK];        // q_ bf16 lo
__device__ __nv_bfloat16 g_ssh[B * VN * QN];       // S bf16 hi
__device__ __nv_bfloat16 g_ssl[B * VN * QN];       // S bf16 lo
__device__ float g_lk[B * HK];
__device__ float g_hw[HOUT * HK];
__device__ unsigned char g_vmask[B * VN];
__device__ unsigned char g_qmask[B * QN];
// pre-split GEMM operands (bf16 hi/lo)
__device__ __nv_bfloat16 g_vsh[B * VN * VD], g_vsl[B * VN * VD];
__device__ __nv_bfloat16 g_qsh[B * QN * QD], g_qsl[B * QN * QD];
__device__ __nv_bfloat16 g_wvh[HK * VD],    g_wvl[HK * VD];
__device__ __nv_bfloat16 g_wqh[HK * QD],    g_wql[HK * QD];

static __device__ __forceinline__ uint32_t smem_u32(const void* p) {
    uint32_t a;
    asm("{ .reg .u64 t; cvta.to.shared.u64 t, %1; cvt.u32.u64 %0, t; }"
        : "=r"(a) : "l"(p));
    return a;
}

#define LDMX4(d, addr) \
    asm volatile("ldmatrix.sync.aligned.m8n8.x4.shared.b16 {%0,%1,%2,%3}, [%4];" \
                 : "=r"((d)[0]), "=r"((d)[1]), "=r"((d)[2]), "=r"((d)[3]) \
                 : "r"(addr))

#define LDMX4T(d, addr) \
    asm volatile("ldmatrix.sync.aligned.m8n8.x4.trans.shared.b16 {%0,%1,%2,%3}, [%4];" \
                 : "=r"((d)[0]), "=r"((d)[1]), "=r"((d)[2]), "=r"((d)[3]) \
                 : "r"(addr))

#define MMA16816(c, a, b0, b1) \
    asm volatile("mma.sync.aligned.m16n8k16.row.col.f32.bf16.bf16.f32 " \
                 "{%0,%1,%2,%3}, {%4,%5,%6,%7}, {%8,%9}, {%0,%1,%2,%3};" \
                 : "+f"((c)[0]), "+f"((c)[1]), "+f"((c)[2]), "+f"((c)[3]) \
                 : "r"((a)[0]), "r"((a)[1]), "r"((a)[2]), "r"((a)[3]), \
                   "r"(b0), "r"(b1))

#define CP16(dst, src) \
    asm volatile("cp.async.cg.shared.global [%0], [%1], 16;" \
                 :: "r"(dst), "l"(src))
#define CP_COMMIT() asm volatile("cp.async.commit_group;" ::: "memory")
#define CP_WAIT0()  asm volatile("cp.async.wait_group 0;" ::: "memory")

static __device__ __forceinline__ void split2(float x0, float x1,
                                              uint32_t& hi, uint32_t& lo) {
    __nv_bfloat16 h0 = __float2bfloat16(x0);
    __nv_bfloat16 h1 = __float2bfloat16(x1);
    float l0 = x0 - __bfloat162float(h0);
    float l1 = x1 - __bfloat162float(h1);
    hi = (uint32_t)__bfloat16_as_ushort(h0) |
         ((uint32_t)__bfloat16_as_ushort(h1) << 16);
    lo = (uint32_t)__bfloat16_as_ushort(__float2bfloat16(l0)) |
         ((uint32_t)__bfloat16_as_ushort(__float2bfloat16(l1)) << 16);
}

// ---------------- prep kernels ----------------------------------------------
__global__ void mask_kernel(const float* __restrict__ v, const float* __restrict__ q) {
    int warp = (blockIdx.x * blockDim.x + threadIdx.x) >> 5;
    int lane = threadIdx.x & 31;
    if (warp < B * VN) {
        const float* row = v + (size_t)warp * VD;
        float s = 0.f;
        for (int i = lane; i < VD; i += 32) s += fabsf(row[i]);
        for (int o = 16; o; o >>= 1) s += __shfl_xor_sync(0xffffffffu, s, o);
        if (lane == 0) g_vmask[warp] = (s == 0.f) ? 1 : 0;
    } else {
        int r = warp - B * VN;
        if (r < B * QN) {
            const float* row = q + (size_t)r * QD;
            float s = 0.f;
            for (int i = lane; i < QD; i += 32) s += fabsf(row[i]);
            for (int o = 16; o; o >>= 1) s += __shfl_xor_sync(0xffffffffu, s, o);
            if (lane == 0) g_qmask[r] = (s == 0.f) ? 1 : 0;
        }
    }
}

__global__ void hw_kernel(const float* __restrict__ h_mat) {
    int k = blockIdx.x * blockDim.x + threadIdx.x;
    if (k < HK) {
#pragma unroll
        for (int h = 0; h < HOUT; h++) g_hw[h * HK + k] = h_mat[h * HK + k];
    }
}

template <int W>
__global__ void split_kernel(const float* __restrict__ src, int n4) {
    int i = blockIdx.x * blockDim.x + threadIdx.x;
    if (i >= n4) return;
    __nv_bfloat16* dh;
    __nv_bfloat16* dl;
    if (W == 0) { dh = g_vsh; dl = g_vsl; }
    else if (W == 1) { dh = g_qsh; dl = g_qsl; }
    else if (W == 2) { dh = g_wvh; dl = g_wvl; }
    else { dh = g_wqh; dl = g_wql; }
    float4 x = ((const float4*)src)[i];
    uint2 hi, lo;
    split2(x.x, x.y, hi.x, lo.x);
    split2(x.z, x.w, hi.y, lo.y);
    *(uint2*)(dh + (size_t)i * 4) = hi;
    *(uint2*)(dl + (size_t)i * 4) = lo;
}

// ---------------- smem geometry (MMA kernels) --------------------------------
#define SP   40
#define ABY  (128 * SP * 2)     // 10240 B per array
#define STG  (4 * ABY)          // 40960 B per stage
#define SMB  (2 * STG)          // 81920

// ---------------- pure-bf16 proj GEMM (cp.async) -----------------------------
template <int MODE, int KD>
__global__ __launch_bounds__(256, 2) void gemm01_kernel(const float* __restrict__ bias) {
    extern __shared__ char smem[];
    const uint32_t sb = smem_u32(smem);
    const int tid = threadIdx.x;
    const int lane = tid & 31;
    const int wid = tid >> 5;
    const int wm = wid >> 2, wn = wid & 3;
    const int CH = KD / 32;
    const int m0 = blockIdx.y * 128;
    const int n0 = blockIdx.x * 128;

    const __nv_bfloat16* Agh = (MODE == 0) ? g_vsh : g_qsh;
    const __nv_bfloat16* Agl = (MODE == 0) ? g_vsl : g_qsl;
    const __nv_bfloat16* Bgh = (MODE == 0) ? g_wvh : g_wqh;
    const __nv_bfloat16* Bgl = (MODE == 0) ? g_wvl : g_wql;

    const int arow = wm * 64 + (lane & 15);
    const int acol = (lane & 16) ? 8 : 0;
    const uint32_t aoff = (uint32_t)(arow * SP + acol) * 2;
    const int brow = wn * 32 + (lane & 7) + ((lane & 16) ? 8 : 0);
    const int bcol = (lane & 8) ? 8 : 0;
    const uint32_t boff = (uint32_t)(brow * SP + bcol) * 2;

    float acc[4][4][4];
#pragma unroll
    for (int i = 0; i < 4; i++)
#pragma unroll
        for (int j = 0; j < 4; j++)
#pragma unroll
            for (int e = 0; e < 4; e++) acc[i][j][e] = 0.f;

    auto cp_chunk = [&](int c) {
        int k0 = c * 32;
        uint32_t stg = sb + (uint32_t)(c & 1) * STG;
#pragma unroll
        for (int j = 0; j < 8; j++) {
            int u = tid + j * 256;
            int arr = u >> 9;
            int r = (u >> 2) & 127;
            int seg = u & 3;
            uint32_t dst = stg + (uint32_t)arr * ABY + r * (SP * 2) + seg * 16;
            const __nv_bfloat16* src;
            if (arr == 0)      src = Agh + (size_t)(m0 + r) * KD + k0 + seg * 8;
            else if (arr == 1) src = Agl + (size_t)(m0 + r) * KD + k0 + seg * 8;
            else if (arr == 2) src = Bgh + (size_t)(n0 + r) * KD + k0 + seg * 8;
            else               src = Bgl + (size_t)(n0 + r) * KD + k0 + seg * 8;
            CP16(dst, src);
        }
    };

    cp_chunk(0);
    CP_COMMIT();

    for (int c = 0; c < CH; ++c) {
        CP_WAIT0();
        __syncthreads();
        if (c + 1 < CH) { cp_chunk(c + 1); CP_COMMIT(); }

        uint32_t stg = sb + (uint32_t)(c & 1) * STG;
        uint32_t aAh = stg + aoff;
        uint32_t aBh = stg + 2 * ABY + boff;
#pragma unroll
        for (int ks = 0; ks < 2; ks++) {
            uint32_t ah[4][4], al[4][4];
#pragma unroll
            for (int mi = 0; mi < 4; mi++) {
                uint32_t ad = aAh + mi * (16 * SP * 2) + ks * 32;
                LDMX4(ah[mi], ad);
                LDMX4(al[mi], ad + ABY);
            }
            uint32_t bh[2][4], bl[2][4];
#pragma unroll
            for (int np = 0; np < 2; np++) {
                uint32_t bd = aBh + np * (16 * SP * 2) + ks * 32;
                LDMX4(bh[np], bd);
                LDMX4(bl[np], bd + ABY);
            }
#pragma unroll
            for (int mi = 0; mi < 4; mi++)
#pragma unroll
                for (int nj = 0; nj < 4; nj++) {
                    uint32_t b0h = bh[nj >> 1][(nj & 1) * 2];
                    uint32_t b1h = bh[nj >> 1][(nj & 1) * 2 + 1];
                    uint32_t b0l = bl[nj >> 1][(nj & 1) * 2];
                    uint32_t b1l = bl[nj >> 1][(nj & 1) * 2 + 1];
                    MMA16816(acc[mi][nj], ah[mi], b0h, b1h);
                    MMA16816(acc[mi][nj], al[mi], b0h, b1h);
                    MMA16816(acc[mi][nj], ah[mi], b0l, b1l);
                }
        }
    }

    const int gid = lane >> 2, tig = lane & 3;
#pragma unroll
    for (int mi = 0; mi < 4; mi++) {
#pragma unroll
        for (int nj = 0; nj < 4; nj++) {
            int row = m0 + wm * 64 + mi * 16 + gid;
            int col = n0 + wn * 32 + nj * 8 + tig * 2;
            float b0 = bias[col], b1 = bias[col + 1];
            float v0 = fmaxf(acc[mi][nj][0] + b0, 0.f);
            float v1 = fmaxf(acc[mi][nj][1] + b1, 0.f);
            float v2 = fmaxf(acc[mi][nj][2] + b0, 0.f);
            float v3 = fmaxf(acc[mi][nj][3] + b1, 0.f);
            size_t o0 = (size_t)row * HK + col;
            size_t o1 = (size_t)(row + 8) * HK + col;
            if (MODE == 0) {
                *(float2*)(g_v + o0) = make_float2(v0, v1);
                *(float2*)(g_v + o1) = make_float2(v2, v3);
            } else {
                uint32_t h0, l0, h1, l1;
                split2(v0, v1, h0, l0);
                split2(v2, v3, h1, l1);
                *(uint32_t*)(g_qh + o0) = h0;
                *(uint32_t*)(g_ql + o0) = l0;
                *(uint32_t*)(g_qh + o1) = h1;
                *(uint32_t*)(g_ql + o1) = l1;
            }
        }
    }
}

// ---------------- att GEMM: A = v_ .* h_w[h] (fold+split), B = q hi/lo -------
__global__ __launch_bounds__(256, 2) void att_kernel(
    const float* __restrict__ h_bias, float* __restrict__ attout) {
    extern __shared__ char smem[];
    const uint32_t sb = smem_u32(smem);
    const int tid = threadIdx.x;
    const int lane = tid & 31;
    const int wid = tid >> 5;
    const int wm = wid >> 2, wn = wid & 3;
    const int CH = HK / 32;

    const int bz = blockIdx.z >> 3;
    const int hz = blockIdx.z & 7;
    const int m0 = blockIdx.y * 128;
    const int n0 = blockIdx.x * 128;

    const float* Ap = g_v + (size_t)bz * VN * HK;
    const float* wrow = g_hw + hz * HK;
    const __nv_bfloat16* Qh = g_qh + (size_t)bz * QN * HK;
    const __nv_bfloat16* Ql = g_ql + (size_t)bz * QN * HK;

    const int arow = wm * 64 + (lane & 15);
    const int acol = (lane & 16) ? 8 : 0;
    const uint32_t aoff = (uint32_t)(arow * SP + acol) * 2;
    const int brow = wn * 32 + (lane & 7) + ((lane & 16) ? 8 : 0);
    const int bcol = (lane & 8) ? 8 : 0;
    const uint32_t boff = (uint32_t)(brow * SP + bcol) * 2;

    float acc[4][4][4];
#pragma unroll
    for (int i = 0; i < 4; i++)
#pragma unroll
        for (int j = 0; j < 4; j++)
#pragma unroll
            for (int e = 0; e < 4; e++) acc[i][j][e] = 0.f;

    float4 ra[4];

    auto cpB = [&](int c) {
        int k0 = c * 32;
        uint32_t stg = sb + (uint32_t)(c & 1) * STG;
#pragma unroll
        for (int j = 0; j < 4; j++) {
            int u = tid + j * 256;
            int arr = u >> 9;
            int r = (u >> 2) & 127;
            int seg = u & 3;
            uint32_t dst = stg + (uint32_t)(2 + arr) * ABY + r * (SP * 2) + seg * 16;
            const __nv_bfloat16* src = (arr == 0)
                ? (Qh + (size_t)(n0 + r) * HK + k0 + seg * 8)
                : (Ql + (size_t)(n0 + r) * HK + k0 + seg * 8);
            CP16(dst, src);
        }
    };
    auto ldgA = [&](int c) {
        int k0 = c * 32;
#pragma unroll
        for (int i = 0; i < 4; i++) {
            int idx = tid + i * 256;
            int r = idx >> 3, c4 = idx & 7;
            ra[i] = *(const float4*)(Ap + (size_t)(m0 + r) * HK + k0 + c4 * 4);
        }
    };
    auto stsA = [&](int c) {
        int k0 = c * 32;
        char* st = smem + (c & 1) * STG;
#pragma unroll
        for (int i = 0; i < 4; i++) {
            int idx = tid + i * 256;
            int r = idx >> 3, c4 = idx & 7;
            float4 w = *(const float4*)(wrow + k0 + c4 * 4);
            float4 x = ra[i];
            x.x *= w.x; x.y *= w.y; x.z *= w.z; x.w *= w.w;
            uint2 hi, lo;
            split2(x.x, x.y, hi.x, lo.x);
            split2(x.z, x.w, hi.y, lo.y);
            uint32_t off = (uint32_t)r * (SP * 2) + c4 * 8;
            *(uint2*)(st + off) = hi;
            *(uint2*)(st + ABY + off) = lo;
        }
    };

    cpB(0);
    CP_COMMIT();
    ldgA(0);

    for (int c = 0; c < CH; ++c) {
        CP_WAIT0();
        stsA(c);
        __syncthreads();
        if (c + 1 < CH) { cpB(c + 1); CP_COMMIT(); ldgA(c + 1); }

        uint32_t stg = sb + (uint32_t)(c & 1) * STG;
        uint32_t aAh = stg + aoff;
        uint32_t aBh = stg + 2 * ABY + boff;
#pragma unroll
        for (int ks = 0; ks < 2; ks++) {
            uint32_t ah[4][4], al[4][4];
#pragma unroll
            for (int mi = 0; mi < 4; mi++) {
                uint32_t ad = aAh + mi * (16 * SP * 2) + ks * 32;
                LDMX4(ah[mi], ad);
                LDMX4(al[mi], ad + ABY);
            }
            uint32_t bh[2][4], bl[2][4];
#pragma unroll
            for (int np = 0; np < 2; np++) {
                uint32_t bd = aBh + np * (16 * SP * 2) + ks * 32;
                LDMX4(bh[np], bd);
                LDMX4(bl[np], bd + ABY);
            }
#pragma unroll
            for (int mi = 0; mi < 4; mi++)
#pragma unroll
                for (int nj = 0; nj < 4; nj++) {
                    uint32_t b0h = bh[nj >> 1][(nj & 1) * 2];
                    uint32_t b1h = bh[nj >> 1][(nj & 1) * 2 + 1];
                    uint32_t b0l = bl[nj >> 1][(nj & 1) * 2];
                    uint32_t b1l = bl[nj >> 1][(nj & 1) * 2 + 1];
                    MMA16816(acc[mi][nj], ah[mi], b0h, b1h);
                    MMA16816(acc[mi][nj], al[mi], b0h, b1h);
                    MMA16816(acc[mi][nj], ah[mi], b0l, b1l);
                }
        }
    }

    const int gid = lane >> 2, tig = lane & 3;
    float NI = __int_as_float(0xff800000);
    float hb = h_bias[hz];
    float* dst = attout + (((size_t)bz * HOUT + hz) * VN + m0) * QN + n0;
#pragma unroll
    for (int mi = 0; mi < 4; mi++) {
#pragma unroll
        for (int nj = 0; nj < 4; nj++) {
            int rl = wm * 64 + mi * 16 + gid;
            int cl = wn * 32 + nj * 8 + tig * 2;
            bool vm0 = g_vmask[bz * VN + m0 + rl] != 0;
            bool vm1 = g_vmask[bz * VN + m0 + rl + 8] != 0;
            bool qm0 = g_qmask[bz * QN + n0 + cl] != 0;
            bool qm1 = g_qmask[bz * QN + n0 + cl + 1] != 0;
            float v0 = (vm0 || qm0) ? NI : acc[mi][nj][0] + hb;
            float v1 = (vm0 || qm1) ? NI : acc[mi][nj][1] + hb;
            float v2 = (vm1 || qm0) ? NI : acc[mi][nj][2] + hb;
            float v3 = (vm1 || qm1) ? NI : acc[mi][nj][3] + hb;
            *(float2*)(dst + (size_t)rl * QN + cl) = make_float2(v0, v1);
            *(float2*)(dst + (size_t)(rl + 8) * QN + cl) = make_float2(v2, v3);
        }
    }
}

// ---------------- S = sum over heads of att, split to bf16 hi/lo -------------
__global__ void sumS_kernel(const float* __restrict__ att) {
    int i = blockIdx.x * blockDim.x + threadIdx.x;
    const int per = VN * QN / 4;
    int b = i / per, off = i - b * per;
    const float4* a = (const float4*)att;
    size_t base = (size_t)b * HOUT * per + off;
    float4 s = a[base];
#pragma unroll
    for (int h = 1; h < HOUT; h++) {
        float4 x = a[base + (size_t)h * per];
        s.x += x.x; s.y += x.y; s.z += x.z; s.w += x.w;
    }
    uint2 hi, lo;
    split2(s.x, s.y, hi.x, lo.x);
    split2(s.z, s.w, hi.y, lo.y);
    size_t o = ((size_t)b * per + off) * 4;
    *(uint2*)(g_ssh + o) = hi;
    *(uint2*)(g_ssl + o) = lo;
}

// ---------------- pool via MMA: logits_k = sum_v v_ .* (S @ q_) --------------
// Per block: one b, one 128-wide k-tile. A = S[v,q] (contraction q), B = q_[q,k]
// via ldmatrix.trans. After GEMM, multiply by v_ fp32 and reduce over v.
#define PBSP 136
#define PBBY (32 * PBSP * 2)            // 8704
#define PSTG (2 * ABY + 2 * PBBY)       // 37888
#define PSMB (2 * PSTG + 1024)          // 76800

__global__ __launch_bounds__(256, 2) void pool_mma_kernel() {
    extern __shared__ char smem[];
    const uint32_t sb = smem_u32(smem);
    float* red = (float*)(smem + 2 * PSTG);
    const int tid = threadIdx.x;
    const int lane = tid & 31;
    const int wid = tid >> 5;
    const int wm = wid >> 2, wn = wid & 3;
    const int gid = lane >> 2, tig = lane & 3;

    const int bz = blockIdx.y;
    const int k0 = blockIdx.x * 128;

    const __nv_bfloat16* Sh = g_ssh + (size_t)bz * VN * QN;
    const __nv_bfloat16* Sl = g_ssl + (size_t)bz * VN * QN;
    const __nv_bfloat16* Qh = g_qh + (size_t)bz * QN * HK;
    const __nv_bfloat16* Ql = g_ql + (size_t)bz * QN * HK;
    const float* Vp = g_v + (size_t)bz * VN * HK;

    const int arow = wm * 64 + (lane & 15);
    const int acol = (lane & 16) ? 8 : 0;
    const uint32_t aoff = (uint32_t)(arow * SP + acol) * 2;
    // B (.trans): lane groups g=lane>>3: m0:k r, nb0 | m1:k r+8, nb0 | m2:k r, nb1 | m3:k r+8, nb1
    const int bg = lane >> 3, br = lane & 7;
    const uint32_t btoff = (uint32_t)(((bg & 1) * 8 + br) * PBSP +
                                     wn * 32 + (bg >> 1) * 8) * 2;

    float ps[4][2];
#pragma unroll
    for (int j = 0; j < 4; j++) { ps[j][0] = 0.f; ps[j][1] = 0.f; }

    auto cp_chunk = [&](int mt, int c) {
        int q0 = c * 32;
        uint32_t stg = sb + (uint32_t)(c & 1) * PSTG;
        // A: S hi/lo [128 v x 32 q]
#pragma unroll
        for (int j = 0; j < 4; j++) {
            int u = tid + j * 256;
            int arr = u >> 9;
            int r = (u >> 2) & 127;
            int seg = u & 3;
            uint32_t dst = stg + (uint32_t)arr * ABY + r * (SP * 2) + seg * 16;
            const __nv_bfloat16* src = (arr ? Sl : Sh) +
                (size_t)(mt * 128 + r) * QN + q0 + seg * 8;
            CP16(dst, src);
        }
        // B: q_ hi/lo [32 q x 128 k]
#pragma unroll
        for (int j = 0; j < 4; j++) {
            int u = tid + j * 256;
            int arr = u >> 9;
            int r = (u >> 4) & 31;
            int seg = u & 15;
            uint32_t dst = stg + 2 * ABY + (uint32_t)arr * PBBY + r * (PBSP * 2) + seg * 16;
            const __nv_bfloat16* src = (arr ? Ql : Qh) +
                (size_t)(q0 + r) * HK + k0 + seg * 8;
            CP16(dst, src);
        }
    };

    for (int mt = 0; mt < 2; mt++) {
        float acc[4][4][4];
#pragma unroll
        for (int i = 0; i < 4; i++)
#pragma unroll
            for (int j = 0; j < 4; j++)
#pragma unroll
                for (int e = 0; e < 4; e++) acc[i][j][e] = 0.f;

        cp_chunk(mt, 0);
        CP_COMMIT();

        for (int c = 0; c < 8; ++c) {
            CP_WAIT0();
            __syncthreads();
            if (c + 1 < 8) { cp_chunk(mt, c + 1); CP_COMMIT(); }

            uint32_t stg = sb + (uint32_t)(c & 1) * PSTG;
            uint32_t aAh = stg + aoff;
            uint32_t aBh = stg + 2 * ABY + btoff;
#pragma unroll
            for (int ks = 0; ks < 2; ks++) {
                uint32_t ah[4][4], al[4][4];
#pragma unroll
                for (int mi = 0; mi < 4; mi++) {
                    uint32_t ad = aAh + mi * (16 * SP * 2) + ks * 32;
                    LDMX4(ah[mi], ad);
                    LDMX4(al[mi], ad + ABY);
                }
                uint32_t bh[2][4], bl[2][4];
#pragma unroll
                for (int np = 0; np < 2; np++) {
                    uint32_t bd = aBh + ks * 16 * (PBSP * 2) + np * 32;
                    LDMX4T(bh[np], bd);
                    LDMX4T(bl[np], bd + PBBY);
                }
#pragma unroll
                for (int mi = 0; mi < 4; mi++)
#pragma unroll
                    for (int np = 0; np < 2; np++) {
                        MMA16816(acc[mi][np * 2],     ah[mi], bh[np][0], bh[np][1]);
                        MMA16816(acc[mi][np * 2],     al[mi], bh[np][0], bh[np][1]);
                        MMA16816(acc[mi][np * 2],     ah[mi], bl[np][0], bl[np][1]);
                        MMA16816(acc[mi][np * 2 + 1], ah[mi], bh[np][2], bh[np][3]);
                        MMA16816(acc[mi][np * 2 + 1], al[mi], bh[np][2], bh[np][3]);
                        MMA16816(acc[mi][np * 2 + 1], ah[mi], bl[np][2], bl[np][3]);
                    }
            }
        }

        // elementwise * v_ and accumulate over rows
#pragma unroll
        for (int mi = 0; mi < 4; mi++) {
#pragma unroll
            for (int nj = 0; nj < 4; nj++) {
                int row = mt * 128 + wm * 64 + mi * 16 + gid;
                int col = k0 + wn * 32 + nj * 8 + tig * 2;
                float2 v0 = *(const float2*)(Vp + (size_t)row * HK + col);
                float2 v1 = *(const float2*)(Vp + (size_t)(row + 8) * HK + col);
                ps[nj][0] = fmaf(acc[mi][nj][0], v0.x, ps[nj][0]);
                ps[nj][1] = fmaf(acc[mi][nj][1], v0.y, ps[nj][1]);
                ps[nj][0] = fmaf(acc[mi][nj][2], v1.x, ps[nj][0]);
                ps[nj][1] = fmaf(acc[mi][nj][3], v1.y, ps[nj][1]);
            }
        }
        __syncthreads();
    }

    // reduce over gid lanes (lane bits 2..4)
#pragma unroll
    for (int nj = 0; nj < 4; nj++)
#pragma unroll
        for (int e = 0; e < 2; e++) {
            float s = ps[nj][e];
            s += __shfl_xor_sync(0xffffffffu, s, 4);
            s += __shfl_xor_sync(0xffffffffu, s, 8);
            s += __shfl_xor_sync(0xffffffffu, s, 16);
            ps[nj][e] = s;
        }
    if (gid == 0) {
#pragma unroll
        for (int nj = 0; nj < 4; nj++) {
            red[wid * 32 + nj * 8 + tig * 2 + 0] = ps[nj][0];
            red[wid * 32 + nj * 8 + tig * 2 + 1] = ps[nj][1];
        }
    }
    __syncthreads();
    if (tid < 128) {
        int wn2 = tid >> 5, cc = tid & 31;
        float s = red[wn2 * 32 + cc] + red[(wn2 + 4) * 32 + cc];
        g_lk[bz * HK + k0 + tid] = s;
    }
}

// ---------------- pool-of-3 + BatchNorm --------------------------------------
__global__ void bn_kernel(const float* __restrict__ gamma, const float* __restrict__ beta,
                          float* __restrict__ out) {
    int c = blockIdx.x * blockDim.x + threadIdx.x;
    if (c >= HD) return;
    float x[B];
    float mu = 0.f;
#pragma unroll
    for (int b = 0; b < B; b++) {
        const float* p = g_lk + b * HK + c * KP;
        x[b] = p[0] + p[1] + p[2];
        mu += x[b];
    }
    mu *= (1.f / B);
    float var = 0.f;
#pragma unroll
    for (int b = 0; b < B; b++) {
        float d = x[b] - mu;
        var = fmaf(d, d, var);
    }
    var *= (1.f / B);
    float scale = rsqrtf(var + 1e-5f) * gamma[c];
    float bet = beta[c];
#pragma unroll
    for (int b = 0; b < B; b++) out[b * HD + c] = (x[b] - mu) * scale + bet;
}

// ---------------- launcher ----------------------------------------------------
extern "C" void kernel_launch(void* const* d_in, const int* in_sizes, int n_in,
                              void* d_out, int out_size) {
    const float* v      = (const float*)d_in[0];
    const float* q      = (const float*)d_in[1];
    const float* Wv     = (const float*)d_in[2];
    const float* bv     = (const float*)d_in[3];
    const float* Wq     = (const float*)d_in[4];
    const float* bq     = (const float*)d_in[5];
    const float* h_mat  = (const float*)d_in[6];
    const float* h_bias = (const float*)d_in[7];
    const float* gamma  = (const float*)d_in[8];
    const float* beta   = (const float*)d_in[9];

    float* out    = (float*)d_out;
    float* logits = out;
    float* att    = out + B * HD;

    cudaFuncSetAttribute(gemm01_kernel<0, VD>,
                         cudaFuncAttributeMaxDynamicSharedMemorySize, SMB);
    cudaFuncSetAttribute(gemm01_kernel<1, QD>,
                         cudaFuncAttributeMaxDynamicSharedMemorySize, SMB);
    cudaFuncSetAttribute(att_kernel,
                         cudaFuncAttributeMaxDynamicSharedMemorySize, SMB);
    cudaFuncSetAttribute(pool_mma_kernel,
                         cudaFuncAttributeMaxDynamicSharedMemorySize, PSMB);

    mask_kernel<<<1024, 256>>>(v, q);
    hw_kernel<<<(HK + 255) / 256, 256>>>(h_mat);

    split_kernel<0><<<(B * VN * VD / 4 + 255) / 256, 256>>>(v, B * VN * VD / 4);
    split_kernel<1><<<(B * QN * QD / 4 + 255) / 256, 256>>>(q, B * QN * QD / 4);
    split_kernel<2><<<(HK * VD / 4 + 255) / 256, 256>>>(Wv, HK * VD / 4);
    split_kernel<3><<<(HK * QD / 4 + 255) / 256, 256>>>(Wq, HK * QD / 4);

    gemm01_kernel<0, VD><<<dim3(HK / 128, (B * VN) / 128), 256, SMB>>>(bv);
    gemm01_kernel<1, QD><<<dim3(HK / 128, (B * QN) / 128), 256, SMB>>>(bq);

    att_kernel<<<dim3(QN / 128, VN / 128, B * HOUT), 256, SMB>>>(h_bias, att);

    sumS_kernel<<<(B * VN * QN / 4) / 256, 256>>>(att);
    pool_mma_kernel<<<dim3(HK / 128, B), 256, PSMB>>>();
    bn_kernel<<<(HD + 255) / 256, 256>>>(gamma, beta, logits);
}

// round 8
// speedup vs baseline: 3.9373x; 1.4285x over previous
#include <cuda_runtime.h>
#include <cuda_fp16.h>
#include <stdint.h>
#include <math.h>

#define B    16
#define VN   256
#define QN   256
#define VD   512
#define QD   768
#define HK   1536
#define HOUT 8
#define HD   512
#define KP   3

// ---------------- scratch (device globals) ----------------------------------
__device__ float g_v[B * VN * HK];                 // v_ fp32
__device__ __half g_qh[B * QN * HK];               // q_ fp16 (hi only)
__device__ __half g_ssh[B * VN * QN];              // S fp16 hi
__device__ __half g_ssl[B * VN * QN];              // S fp16 lo
__device__ float g_lk[B * HK];
__device__ float g_hw[HOUT * HK];
__device__ unsigned char g_vmask[B * VN];
__device__ unsigned char g_qmask[B * QN];
// pre-split operands
__device__ __half g_vsh[B * VN * VD], g_vsl[B * VN * VD];
__device__ __half g_qsh[B * QN * QD], g_qsl[B * QN * QD];
__device__ __half g_wvh[HK * VD];
__device__ __half g_wqh[HK * QD];

static __device__ __forceinline__ uint32_t smem_u32(const void* p) {
    uint32_t a;
    asm("{ .reg .u64 t; cvta.to.shared.u64 t, %1; cvt.u32.u64 %0, t; }"
        : "=r"(a) : "l"(p));
    return a;
}

#define LDMX4(d, addr) \
    asm volatile("ldmatrix.sync.aligned.m8n8.x4.shared.b16 {%0,%1,%2,%3}, [%4];" \
                 : "=r"((d)[0]), "=r"((d)[1]), "=r"((d)[2]), "=r"((d)[3]) \
                 : "r"(addr))

#define LDMX4T(d, addr) \
    asm volatile("ldmatrix.sync.aligned.m8n8.x4.trans.shared.b16 {%0,%1,%2,%3}, [%4];" \
                 : "=r"((d)[0]), "=r"((d)[1]), "=r"((d)[2]), "=r"((d)[3]) \
                 : "r"(addr))

#define MMA16816(c, a, b0, b1) \
    asm volatile("mma.sync.aligned.m16n8k16.row.col.f32.f16.f16.f32 " \
                 "{%0,%1,%2,%3}, {%4,%5,%6,%7}, {%8,%9}, {%0,%1,%2,%3};" \
                 : "+f"((c)[0]), "+f"((c)[1]), "+f"((c)[2]), "+f"((c)[3]) \
                 : "r"((a)[0]), "r"((a)[1]), "r"((a)[2]), "r"((a)[3]), \
                   "r"(b0), "r"(b1))

#define CP16(dst, src) \
    asm volatile("cp.async.cg.shared.global [%0], [%1], 16;" \
                 :: "r"(dst), "l"(src))
#define CP_COMMIT() asm volatile("cp.async.commit_group;" ::: "memory")
#define CP_WAIT0()  asm volatile("cp.async.wait_group 0;" ::: "memory")

static __device__ __forceinline__ uint32_t pack2h(float a, float b) {
    __half2 h = __floats2half2_rn(a, b);
    return *(uint32_t*)&h;
}
static __device__ __forceinline__ void split2h(float x0, float x1,
                                               uint32_t& hi, uint32_t& lo) {
    __half h0 = __float2half_rn(x0);
    __half h1 = __float2half_rn(x1);
    float l0 = x0 - __half2float(h0);
    float l1 = x1 - __half2float(h1);
    __half2 hh = __halves2half2(h0, h1);
    hi = *(uint32_t*)&hh;
    lo = pack2h(l0, l1);
}

// ---------------- prep kernels ----------------------------------------------
__global__ void mask_kernel(const float* __restrict__ v, const float* __restrict__ q) {
    int warp = (blockIdx.x * blockDim.x + threadIdx.x) >> 5;
    int lane = threadIdx.x & 31;
    if (warp < B * VN) {
        const float* row = v + (size_t)warp * VD;
        float s = 0.f;
        for (int i = lane; i < VD; i += 32) s += fabsf(row[i]);
        for (int o = 16; o; o >>= 1) s += __shfl_xor_sync(0xffffffffu, s, o);
        if (lane == 0) g_vmask[warp] = (s == 0.f) ? 1 : 0;
    } else {
        int r = warp - B * VN;
        if (r < B * QN) {
            const float* row = q + (size_t)r * QD;
            float s = 0.f;
            for (int i = lane; i < QD; i += 32) s += fabsf(row[i]);
            for (int o = 16; o; o >>= 1) s += __shfl_xor_sync(0xffffffffu, s, o);
            if (lane == 0) g_qmask[r] = (s == 0.f) ? 1 : 0;
        }
    }
}

__global__ void hw_kernel(const float* __restrict__ h_mat) {
    int k = blockIdx.x * blockDim.x + threadIdx.x;
    if (k < HK) {
#pragma unroll
        for (int h = 0; h < HOUT; h++) g_hw[h * HK + k] = h_mat[h * HK + k];
    }
}

// W: 0 -> v hi/lo, 1 -> q hi/lo, 2 -> Wv hi only, 3 -> Wq hi only
template <int W>
__global__ void split_kernel(const float* __restrict__ src, int n4) {
    int i = blockIdx.x * blockDim.x + threadIdx.x;
    if (i >= n4) return;
    float4 x = ((const float4*)src)[i];
    if (W <= 1) {
        __half* dh = (W == 0) ? g_vsh : g_qsh;
        __half* dl = (W == 0) ? g_vsl : g_qsl;
        uint2 hi, lo;
        split2h(x.x, x.y, hi.x, lo.x);
        split2h(x.z, x.w, hi.y, lo.y);
        *(uint2*)(dh + (size_t)i * 4) = hi;
        *(uint2*)(dl + (size_t)i * 4) = lo;
    } else {
        __half* dh = (W == 2) ? g_wvh : g_wqh;
        uint2 hi;
        hi.x = pack2h(x.x, x.y);
        hi.y = pack2h(x.z, x.w);
        *(uint2*)(dh + (size_t)i * 4) = hi;
    }
}

// ---------------- smem geometry (MMA kernels) --------------------------------
#define SP   40
#define ABY  (128 * SP * 2)     // 10240 B per array
#define STG  (3 * ABY)          // 30720 B per stage (Ah, Al, Bh)
#define SMB  (2 * STG)          // 61440

// ---------------- proj GEMM: A = input hi+lo, B = W hi -----------------------
template <int MODE, int KD>
__global__ __launch_bounds__(256, 2) void gemm01_kernel(const float* __restrict__ bias) {
    extern __shared__ char smem[];
    const uint32_t sb = smem_u32(smem);
    const int tid = threadIdx.x;
    const int lane = tid & 31;
    const int wid = tid >> 5;
    const int wm = wid >> 2, wn = wid & 3;
    const int CH = KD / 32;
    const int m0 = blockIdx.y * 128;
    const int n0 = blockIdx.x * 128;

    const __half* Agh = (MODE == 0) ? g_vsh : g_qsh;
    const __half* Agl = (MODE == 0) ? g_vsl : g_qsl;
    const __half* Bgh = (MODE == 0) ? g_wvh : g_wqh;

    const int arow = wm * 64 + (lane & 15);
    const int acol = (lane & 16) ? 8 : 0;
    const uint32_t aoff = (uint32_t)(arow * SP + acol) * 2;
    const int brow = wn * 32 + (lane & 7) + ((lane & 16) ? 8 : 0);
    const int bcol = (lane & 8) ? 8 : 0;
    const uint32_t boff = (uint32_t)(brow * SP + bcol) * 2;

    float acc[4][4][4];
#pragma unroll
    for (int i = 0; i < 4; i++)
#pragma unroll
        for (int j = 0; j < 4; j++)
#pragma unroll
            for (int e = 0; e < 4; e++) acc[i][j][e] = 0.f;

    auto cp_chunk = [&](int c) {
        int k0 = c * 32;
        uint32_t stg = sb + (uint32_t)(c & 1) * STG;
#pragma unroll
        for (int j = 0; j < 6; j++) {
            int u = tid + j * 256;
            int arr = u >> 9;               // 0..2
            int r = (u >> 2) & 127;
            int seg = u & 3;
            uint32_t dst = stg + (uint32_t)arr * ABY + r * (SP * 2) + seg * 16;
            const __half* src;
            if (arr == 0)      src = Agh + (size_t)(m0 + r) * KD + k0 + seg * 8;
            else if (arr == 1) src = Agl + (size_t)(m0 + r) * KD + k0 + seg * 8;
            else               src = Bgh + (size_t)(n0 + r) * KD + k0 + seg * 8;
            CP16(dst, src);
        }
    };

    cp_chunk(0);
    CP_COMMIT();

    for (int c = 0; c < CH; ++c) {
        CP_WAIT0();
        __syncthreads();
        if (c + 1 < CH) { cp_chunk(c + 1); CP_COMMIT(); }

        uint32_t stg = sb + (uint32_t)(c & 1) * STG;
        uint32_t aAh = stg + aoff;
        uint32_t aBh = stg + 2 * ABY + boff;
#pragma unroll
        for (int ks = 0; ks < 2; ks++) {
            uint32_t ah[4][4], al[4][4];
#pragma unroll
            for (int mi = 0; mi < 4; mi++) {
                uint32_t ad = aAh + mi * (16 * SP * 2) + ks * 32;
                LDMX4(ah[mi], ad);
                LDMX4(al[mi], ad + ABY);
            }
            uint32_t bh[2][4];
#pragma unroll
            for (int np = 0; np < 2; np++) {
                uint32_t bd = aBh + np * (16 * SP * 2) + ks * 32;
                LDMX4(bh[np], bd);
            }
#pragma unroll
            for (int mi = 0; mi < 4; mi++)
#pragma unroll
                for (int nj = 0; nj < 4; nj++) {
                    uint32_t b0h = bh[nj >> 1][(nj & 1) * 2];
                    uint32_t b1h = bh[nj >> 1][(nj & 1) * 2 + 1];
                    MMA16816(acc[mi][nj], ah[mi], b0h, b1h);
                    MMA16816(acc[mi][nj], al[mi], b0h, b1h);
                }
        }
    }

    const int gid = lane >> 2, tig = lane & 3;
#pragma unroll
    for (int mi = 0; mi < 4; mi++) {
#pragma unroll
        for (int nj = 0; nj < 4; nj++) {
            int row = m0 + wm * 64 + mi * 16 + gid;
            int col = n0 + wn * 32 + nj * 8 + tig * 2;
            float b0 = bias[col], b1 = bias[col + 1];
            float v0 = fmaxf(acc[mi][nj][0] + b0, 0.f);
            float v1 = fmaxf(acc[mi][nj][1] + b1, 0.f);
            float v2 = fmaxf(acc[mi][nj][2] + b0, 0.f);
            float v3 = fmaxf(acc[mi][nj][3] + b1, 0.f);
            size_t o0 = (size_t)row * HK + col;
            size_t o1 = (size_t)(row + 8) * HK + col;
            if (MODE == 0) {
                *(float2*)(g_v + o0) = make_float2(v0, v1);
                *(float2*)(g_v + o1) = make_float2(v2, v3);
            } else {
                *(uint32_t*)(g_qh + o0) = pack2h(v0, v1);
                *(uint32_t*)(g_qh + o1) = pack2h(v2, v3);
            }
        }
    }
}

// ---------------- att GEMM: A = v_ .* h_w[h] (fold+split), B = q_ hi ---------
__global__ __launch_bounds__(256, 2) void att_kernel(
    const float* __restrict__ h_bias, float* __restrict__ attout) {
    extern __shared__ char smem[];
    const uint32_t sb = smem_u32(smem);
    const int tid = threadIdx.x;
    const int lane = tid & 31;
    const int wid = tid >> 5;
    const int wm = wid >> 2, wn = wid & 3;
    const int CH = HK / 32;

    const int bz = blockIdx.z >> 3;
    const int hz = blockIdx.z & 7;
    const int m0 = blockIdx.y * 128;
    const int n0 = blockIdx.x * 128;

    const float* Ap = g_v + (size_t)bz * VN * HK;
    const float* wrow = g_hw + hz * HK;
    const __half* Qh = g_qh + (size_t)bz * QN * HK;

    const int arow = wm * 64 + (lane & 15);
    const int acol = (lane & 16) ? 8 : 0;
    const uint32_t aoff = (uint32_t)(arow * SP + acol) * 2;
    const int brow = wn * 32 + (lane & 7) + ((lane & 16) ? 8 : 0);
    const int bcol = (lane & 8) ? 8 : 0;
    const uint32_t boff = (uint32_t)(brow * SP + bcol) * 2;

    float acc[4][4][4];
#pragma unroll
    for (int i = 0; i < 4; i++)
#pragma unroll
        for (int j = 0; j < 4; j++)
#pragma unroll
            for (int e = 0; e < 4; e++) acc[i][j][e] = 0.f;

    float4 ra[4];

    auto cpB = [&](int c) {
        int k0 = c * 32;
        uint32_t stg = sb + (uint32_t)(c & 1) * STG;
#pragma unroll
        for (int j = 0; j < 2; j++) {
            int u = tid + j * 256;
            int r = u >> 2;
            int seg = u & 3;
            uint32_t dst = stg + 2 * ABY + r * (SP * 2) + seg * 16;
            CP16(dst, Qh + (size_t)(n0 + r) * HK + k0 + seg * 8);
        }
    };
    auto ldgA = [&](int c) {
        int k0 = c * 32;
#pragma unroll
        for (int i = 0; i < 4; i++) {
            int idx = tid + i * 256;
            int r = idx >> 3, c4 = idx & 7;
            ra[i] = *(const float4*)(Ap + (size_t)(m0 + r) * HK + k0 + c4 * 4);
        }
    };
    auto stsA = [&](int c) {
        int k0 = c * 32;
        char* st = smem + (c & 1) * STG;
#pragma unroll
        for (int i = 0; i < 4; i++) {
            int idx = tid + i * 256;
            int r = idx >> 3, c4 = idx & 7;
            float4 w = *(const float4*)(wrow + k0 + c4 * 4);
            float4 x = ra[i];
            x.x *= w.x; x.y *= w.y; x.z *= w.z; x.w *= w.w;
            uint2 hi, lo;
            split2h(x.x, x.y, hi.x, lo.x);
            split2h(x.z, x.w, hi.y, lo.y);
            uint32_t off = (uint32_t)r * (SP * 2) + c4 * 8;
            *(uint2*)(st + off) = hi;
            *(uint2*)(st + ABY + off) = lo;
        }
    };

    cpB(0);
    CP_COMMIT();
    ldgA(0);

    for (int c = 0; c < CH; ++c) {
        CP_WAIT0();
        stsA(c);
        __syncthreads();
        if (c + 1 < CH) { cpB(c + 1); CP_COMMIT(); ldgA(c + 1); }

        uint32_t stg = sb + (uint32_t)(c & 1) * STG;
        uint32_t aAh = stg + aoff;
        uint32_t aBh = stg + 2 * ABY + boff;
#pragma unroll
        for (int ks = 0; ks < 2; ks++) {
            uint32_t ah[4][4], al[4][4];
#pragma unroll
            for (int mi = 0; mi < 4; mi++) {
                uint32_t ad = aAh + mi * (16 * SP * 2) + ks * 32;
                LDMX4(ah[mi], ad);
                LDMX4(al[mi], ad + ABY);
            }
            uint32_t bh[2][4];
#pragma unroll
            for (int np = 0; np < 2; np++) {
                uint32_t bd = aBh + np * (16 * SP * 2) + ks * 32;
                LDMX4(bh[np], bd);
            }
#pragma unroll
            for (int mi = 0; mi < 4; mi++)
#pragma unroll
                for (int nj = 0; nj < 4; nj++) {
                    uint32_t b0h = bh[nj >> 1][(nj & 1) * 2];
                    uint32_t b1h = bh[nj >> 1][(nj & 1) * 2 + 1];
                    MMA16816(acc[mi][nj], ah[mi], b0h, b1h);
                    MMA16816(acc[mi][nj], al[mi], b0h, b1h);
                }
        }
    }

    const int gid = lane >> 2, tig = lane & 3;
    float NI = __int_as_float(0xff800000);
    float hb = h_bias[hz];
    float* dst = attout + (((size_t)bz * HOUT + hz) * VN + m0) * QN + n0;
#pragma unroll
    for (int mi = 0; mi < 4; mi++) {
#pragma unroll
        for (int nj = 0; nj < 4; nj++) {
            int rl = wm * 64 + mi * 16 + gid;
            int cl = wn * 32 + nj * 8 + tig * 2;
            bool vm0 = g_vmask[bz * VN + m0 + rl] != 0;
            bool vm1 = g_vmask[bz * VN + m0 + rl + 8] != 0;
            bool qm0 = g_qmask[bz * QN + n0 + cl] != 0;
            bool qm1 = g_qmask[bz * QN + n0 + cl + 1] != 0;
            float v0 = (vm0 || qm0) ? NI : acc[mi][nj][0] + hb;
            float v1 = (vm0 || qm1) ? NI : acc[mi][nj][1] + hb;
            float v2 = (vm1 || qm0) ? NI : acc[mi][nj][2] + hb;
            float v3 = (vm1 || qm1) ? NI : acc[mi][nj][3] + hb;
            *(float2*)(dst + (size_t)rl * QN + cl) = make_float2(v0, v1);
            *(float2*)(dst + (size_t)(rl + 8) * QN + cl) = make_float2(v2, v3);
        }
    }
}

// ---------------- S = sum over heads of att, split fp16 hi/lo ----------------
__global__ void sumS_kernel(const float* __restrict__ att) {
    int i = blockIdx.x * blockDim.x + threadIdx.x;
    const int per = VN * QN / 4;
    int b = i / per, off = i - b * per;
    const float4* a = (const float4*)att;
    size_t base = (size_t)b * HOUT * per + off;
    float4 s = a[base];
#pragma unroll
    for (int h = 1; h < HOUT; h++) {
        float4 x = a[base + (size_t)h * per];
        s.x += x.x; s.y += x.y; s.z += x.z; s.w += x.w;
    }
    uint2 hi, lo;
    split2h(s.x, s.y, hi.x, lo.x);
    split2h(s.z, s.w, hi.y, lo.y);
    size_t o = ((size_t)b * per + off) * 4;
    *(uint2*)(g_ssh + o) = hi;
    *(uint2*)(g_ssl + o) = lo;
}

// ---------------- pool via MMA: logits_k = sum_v v_ .* (S @ q_) --------------
#define PBSP 136
#define PBBY (32 * PBSP * 2)            // 8704
#define PSTG (2 * ABY + PBBY)           // 29184
#define PSMB (2 * PSTG + 1024)          // 59392

__global__ __launch_bounds__(256, 2) void pool_mma_kernel() {
    extern __shared__ char smem[];
    const uint32_t sb = smem_u32(smem);
    float* red = (float*)(smem + 2 * PSTG);
    const int tid = threadIdx.x;
    const int lane = tid & 31;
    const int wid = tid >> 5;
    const int wm = wid >> 2, wn = wid & 3;
    const int gid = lane >> 2, tig = lane & 3;

    const int bz = blockIdx.y;
    const int k0 = blockIdx.x * 128;

    const __half* Sh = g_ssh + (size_t)bz * VN * QN;
    const __half* Sl = g_ssl + (size_t)bz * VN * QN;
    const __half* Qh = g_qh + (size_t)bz * QN * HK;
    const float* Vp = g_v + (size_t)bz * VN * HK;

    const int arow = wm * 64 + (lane & 15);
    const int acol = (lane & 16) ? 8 : 0;
    const uint32_t aoff = (uint32_t)(arow * SP + acol) * 2;
    const int bg = lane >> 3, br = lane & 7;
    const uint32_t btoff = (uint32_t)(((bg & 1) * 8 + br) * PBSP +
                                     wn * 32 + (bg >> 1) * 8) * 2;

    float ps[4][2];
#pragma unroll
    for (int j = 0; j < 4; j++) { ps[j][0] = 0.f; ps[j][1] = 0.f; }

    auto cp_chunk = [&](int mt, int c) {
        int q0 = c * 32;
        uint32_t stg = sb + (uint32_t)(c & 1) * PSTG;
#pragma unroll
        for (int j = 0; j < 4; j++) {
            int u = tid + j * 256;
            int arr = u >> 9;
            int r = (u >> 2) & 127;
            int seg = u & 3;
            uint32_t dst = stg + (uint32_t)arr * ABY + r * (SP * 2) + seg * 16;
            const __half* src = (arr ? Sl : Sh) +
                (size_t)(mt * 128 + r) * QN + q0 + seg * 8;
            CP16(dst, src);
        }
#pragma unroll
        for (int j = 0; j < 2; j++) {
            int u = tid + j * 256;
            int r = (u >> 4) & 31;
            int seg = u & 15;
            uint32_t dst = stg + 2 * ABY + r * (PBSP * 2) + seg * 16;
            CP16(dst, Qh + (size_t)(q0 + r) * HK + k0 + seg * 8);
        }
    };

    for (int mt = 0; mt < 2; mt++) {
        float acc[4][4][4];
#pragma unroll
        for (int i = 0; i < 4; i++)
#pragma unroll
            for (int j = 0; j < 4; j++)
#pragma unroll
                for (int e = 0; e < 4; e++) acc[i][j][e] = 0.f;

        cp_chunk(mt, 0);
        CP_COMMIT();

        for (int c = 0; c < 8; ++c) {
            CP_WAIT0();
            __syncthreads();
            if (c + 1 < 8) { cp_chunk(mt, c + 1); CP_COMMIT(); }

            uint32_t stg = sb + (uint32_t)(c & 1) * PSTG;
            uint32_t aAh = stg + aoff;
            uint32_t aBh = stg + 2 * ABY + btoff;
#pragma unroll
            for (int ks = 0; ks < 2; ks++) {
                uint32_t ah[4][4], al[4][4];
#pragma unroll
                for (int mi = 0; mi < 4; mi++) {
                    uint32_t ad = aAh + mi * (16 * SP * 2) + ks * 32;
                    LDMX4(ah[mi], ad);
                    LDMX4(al[mi], ad + ABY);
                }
                uint32_t bh[2][4];
#pragma unroll
                for (int np = 0; np < 2; np++) {
                    uint32_t bd = aBh + ks * 16 * (PBSP * 2) + np * 32;
                    LDMX4T(bh[np], bd);
                }
#pragma unroll
                for (int mi = 0; mi < 4; mi++)
#pragma unroll
                    for (int np = 0; np < 2; np++) {
                        MMA16816(acc[mi][np * 2],     ah[mi], bh[np][0], bh[np][1]);
                        MMA16816(acc[mi][np * 2],     al[mi], bh[np][0], bh[np][1]);
                        MMA16816(acc[mi][np * 2 + 1], ah[mi], bh[np][2], bh[np][3]);
                        MMA16816(acc[mi][np * 2 + 1], al[mi], bh[np][2], bh[np][3]);
                    }
            }
        }

#pragma unroll
        for (int mi = 0; mi < 4; mi++) {
#pragma unroll
            for (int nj = 0; nj < 4; nj++) {
                int row = mt * 128 + wm * 64 + mi * 16 + gid;
                int col = k0 + wn * 32 + nj * 8 + tig * 2;
                float2 v0 = *(const float2*)(Vp + (size_t)row * HK + col);
                float2 v1 = *(const float2*)(Vp + (size_t)(row + 8) * HK + col);
                ps[nj][0] = fmaf(acc[mi][nj][0], v0.x, ps[nj][0]);
                ps[nj][1] = fmaf(acc[mi][nj][1], v0.y, ps[nj][1]);
                ps[nj][0] = fmaf(acc[mi][nj][2], v1.x, ps[nj][0]);
                ps[nj][1] = fmaf(acc[mi][nj][3], v1.y, ps[nj][1]);
            }
        }
        __syncthreads();
    }

#pragma unroll
    for (int nj = 0; nj < 4; nj++)
#pragma unroll
        for (int e = 0; e < 2; e++) {
            float s = ps[nj][e];
            s += __shfl_xor_sync(0xffffffffu, s, 4);
            s += __shfl_xor_sync(0xffffffffu, s, 8);
            s += __shfl_xor_sync(0xffffffffu, s, 16);
            ps[nj][e] = s;
        }
    if (gid == 0) {
#pragma unroll
        for (int nj = 0; nj < 4; nj++) {
            red[wid * 32 + nj * 8 + tig * 2 + 0] = ps[nj][0];
            red[wid * 32 + nj * 8 + tig * 2 + 1] = ps[nj][1];
        }
    }
    __syncthreads();
    if (tid < 128) {
        int wn2 = tid >> 5, cc = tid & 31;
        float s = red[wn2 * 32 + cc] + red[(wn2 + 4) * 32 + cc];
        g_lk[bz * HK + k0 + tid] = s;
    }
}

// ---------------- pool-of-3 + BatchNorm --------------------------------------
__global__ void bn_kernel(const float* __restrict__ gamma, const float* __restrict__ beta,
                          float* __restrict__ out) {
    int c = blockIdx.x * blockDim.x + threadIdx.x;
    if (c >= HD) return;
    float x[B];
    float mu = 0.f;
#pragma unroll
    for (int b = 0; b < B; b++) {
        const float* p = g_lk + b * HK + c * KP;
        x[b] = p[0] + p[1] + p[2];
        mu += x[b];
    }
    mu *= (1.f / B);
    float var = 0.f;
#pragma unroll
    for (int b = 0; b < B; b++) {
        float d = x[b] - mu;
        var = fmaf(d, d, var);
    }
    var *= (1.f / B);
    float scale = rsqrtf(var + 1e-5f) * gamma[c];
    float bet = beta[c];
#pragma unroll
    for (int b = 0; b < B; b++) out[b * HD + c] = (x[b] - mu) * scale + bet;
}

// ---------------- launcher ----------------------------------------------------
extern "C" void kernel_launch(void* const* d_in, const int* in_sizes, int n_in,
                              void* d_out, int out_size) {
    const float* v      = (const float*)d_in[0];
    const float* q      = (const float*)d_in[1];
    const float* Wv     = (const float*)d_in[2];
    const float* bv     = (const float*)d_in[3];
    const float* Wq     = (const float*)d_in[4];
    const float* bq     = (const float*)d_in[5];
    const float* h_mat  = (const float*)d_in[6];
    const float* h_bias = (const float*)d_in[7];
    const float* gamma  = (const float*)d_in[8];
    const float* beta   = (const float*)d_in[9];

    float* out    = (float*)d_out;
    float* logits = out;
    float* att    = out + B * HD;

    cudaFuncSetAttribute(gemm01_kernel<0, VD>,
                         cudaFuncAttributeMaxDynamicSharedMemorySize, SMB);
    cudaFuncSetAttribute(gemm01_kernel<1, QD>,
                         cudaFuncAttributeMaxDynamicSharedMemorySize, SMB);
    cudaFuncSetAttribute(att_kernel,
                         cudaFuncAttributeMaxDynamicSharedMemorySize, SMB);
    cudaFuncSetAttribute(pool_mma_kernel,
                         cudaFuncAttributeMaxDynamicSharedMemorySize, PSMB);

    mask_kernel<<<1024, 256>>>(v, q);
    hw_kernel<<<(HK + 255) / 256, 256>>>(h_mat);

    split_kernel<0><<<(B * VN * VD / 4 + 255) / 256, 256>>>(v, B * VN * VD / 4);
    split_kernel<1><<<(B * QN * QD / 4 + 255) / 256, 256>>>(q, B * QN * QD / 4);
    split_kernel<2><<<(HK * VD / 4 + 255) / 256, 256>>>(Wv, HK * VD / 4);
    split_kernel<3><<<(HK * QD / 4 + 255) / 256, 256>>>(Wq, HK * QD / 4);

    gemm01_kernel<0, VD><<<dim3(HK / 128, (B * VN) / 128), 256, SMB>>>(bv);
    gemm01_kernel<1, QD><<<dim3(HK / 128, (B * QN) / 128), 256, SMB>>>(bq);

    att_kernel<<<dim3(QN / 128, VN / 128, B * HOUT), 256, SMB>>>(h_bias, att);

    sumS_kernel<<<(B * VN * QN / 4) / 256, 256>>>(att);
    pool_mma_kernel<<<dim3(HK / 128, B), 256, PSMB>>>();
    bn_kernel<<<(HD + 255) / 256, 256>>>(gamma, beta, logits);
}

// round 9
// speedup vs baseline: 5.6727x; 1.4408x over previous
#include <cuda_runtime.h>
#include <cuda_fp16.h>
#include <stdint.h>
#include <math.h>

#define B    16
#define VN   256
#define QN   256
#define VD   512
#define QD   768
#define HK   1536
#define HOUT 8
#define HD   512
#define KP   3

// ---------------- scratch (device globals) ----------------------------------
__device__ float g_v[B * VN * HK];                 // v_ fp32 (for pool epilogue)
__device__ __half g_vh[B * VN * HK];               // v_ fp16 (for att A)
__device__ __half g_qh[B * QN * HK];               // q_ fp16
__device__ __half g_ssh[B * VN * QN];              // S fp16 hi
__device__ __half g_ssl[B * VN * QN];              // S fp16 lo
__device__ float g_lk[B * HK];
__device__ __half g_hwh[HOUT * HK];                // head weights fp16
__device__ unsigned char g_vmask[B * VN];
__device__ unsigned char g_qmask[B * QN];
// pre-rounded fp16 operands
__device__ __half g_vsh[B * VN * VD];
__device__ __half g_qsh[B * QN * QD];
__device__ __half g_wvh[HK * VD];
__device__ __half g_wqh[HK * QD];

static __device__ __forceinline__ uint32_t smem_u32(const void* p) {
    uint32_t a;
    asm("{ .reg .u64 t; cvta.to.shared.u64 t, %1; cvt.u32.u64 %0, t; }"
        : "=r"(a) : "l"(p));
    return a;
}

#define LDMX4(d, addr) \
    asm volatile("ldmatrix.sync.aligned.m8n8.x4.shared.b16 {%0,%1,%2,%3}, [%4];" \
                 : "=r"((d)[0]), "=r"((d)[1]), "=r"((d)[2]), "=r"((d)[3]) \
                 : "r"(addr))

#define LDMX4T(d, addr) \
    asm volatile("ldmatrix.sync.aligned.m8n8.x4.trans.shared.b16 {%0,%1,%2,%3}, [%4];" \
                 : "=r"((d)[0]), "=r"((d)[1]), "=r"((d)[2]), "=r"((d)[3]) \
                 : "r"(addr))

#define MMA16816(c, a, b0, b1) \
    asm volatile("mma.sync.aligned.m16n8k16.row.col.f32.f16.f16.f32 " \
                 "{%0,%1,%2,%3}, {%4,%5,%6,%7}, {%8,%9}, {%0,%1,%2,%3};" \
                 : "+f"((c)[0]), "+f"((c)[1]), "+f"((c)[2]), "+f"((c)[3]) \
                 : "r"((a)[0]), "r"((a)[1]), "r"((a)[2]), "r"((a)[3]), \
                   "r"(b0), "r"(b1))

#define CP16(dst, src) \
    asm volatile("cp.async.cg.shared.global [%0], [%1], 16;" \
                 :: "r"(dst), "l"(src))
#define CP_COMMIT() asm volatile("cp.async.commit_group;" ::: "memory")
#define CP_WAIT0()  asm volatile("cp.async.wait_group 0;" ::: "memory")

static __device__ __forceinline__ uint32_t pack2h(float a, float b) {
    __half2 h = __floats2half2_rn(a, b);
    return *(uint32_t*)&h;
}
static __device__ __forceinline__ void split2h(float x0, float x1,
                                               uint32_t& hi, uint32_t& lo) {
    __half h0 = __float2half_rn(x0);
    __half h1 = __float2half_rn(x1);
    float l0 = x0 - __half2float(h0);
    float l1 = x1 - __half2float(h1);
    __half2 hh = __halves2half2(h0, h1);
    hi = *(uint32_t*)&hh;
    lo = pack2h(l0, l1);
}

// ---------------- prep kernels ----------------------------------------------
__global__ void mask_kernel(const float* __restrict__ v, const float* __restrict__ q) {
    int warp = (blockIdx.x * blockDim.x + threadIdx.x) >> 5;
    int lane = threadIdx.x & 31;
    if (warp < B * VN) {
        const float* row = v + (size_t)warp * VD;
        float s = 0.f;
        for (int i = lane; i < VD; i += 32) s += fabsf(row[i]);
        for (int o = 16; o; o >>= 1) s += __shfl_xor_sync(0xffffffffu, s, o);
        if (lane == 0) g_vmask[warp] = (s == 0.f) ? 1 : 0;
    } else {
        int r = warp - B * VN;
        if (r < B * QN) {
            const float* row = q + (size_t)r * QD;
            float s = 0.f;
            for (int i = lane; i < QD; i += 32) s += fabsf(row[i]);
            for (int o = 16; o; o >>= 1) s += __shfl_xor_sync(0xffffffffu, s, o);
            if (lane == 0) g_qmask[r] = (s == 0.f) ? 1 : 0;
        }
    }
}

__global__ void hw_kernel(const float* __restrict__ h_mat) {
    int k = blockIdx.x * blockDim.x + threadIdx.x;
    if (k < HK) {
#pragma unroll
        for (int h = 0; h < HOUT; h++)
            g_hwh[h * HK + k] = __float2half_rn(h_mat[h * HK + k]);
    }
}

// round fp32 -> fp16 (W selects destination)
template <int W>
__global__ void split_kernel(const float* __restrict__ src, int n4) {
    int i = blockIdx.x * blockDim.x + threadIdx.x;
    if (i >= n4) return;
    float4 x = ((const float4*)src)[i];
    __half* dh;
    if (W == 0) dh = g_vsh;
    else if (W == 1) dh = g_qsh;
    else if (W == 2) dh = g_wvh;
    else dh = g_wqh;
    uint2 hi;
    hi.x = pack2h(x.x, x.y);
    hi.y = pack2h(x.z, x.w);
    *(uint2*)(dh + (size_t)i * 4) = hi;
}

// ---------------- smem geometry ----------------------------------------------
#define SP   40
#define ABY  (128 * SP * 2)     // 10240 B per array
#define STG2 (2 * ABY)          // 20480 B per stage (Ah, Bh)
#define SMB2 (2 * STG2)         // 40960

// ---------------- proj GEMM: pure fp16 ---------------------------------------
template <int MODE, int KD>
__global__ __launch_bounds__(256, 2) void gemm01_kernel(const float* __restrict__ bias) {
    extern __shared__ char smem[];
    const uint32_t sb = smem_u32(smem);
    const int tid = threadIdx.x;
    const int lane = tid & 31;
    const int wid = tid >> 5;
    const int wm = wid >> 2, wn = wid & 3;
    const int CH = KD / 32;
    const int m0 = blockIdx.y * 128;
    const int n0 = blockIdx.x * 128;

    const __half* Agh = (MODE == 0) ? g_vsh : g_qsh;
    const __half* Bgh = (MODE == 0) ? g_wvh : g_wqh;

    const int arow = wm * 64 + (lane & 15);
    const int acol = (lane & 16) ? 8 : 0;
    const uint32_t aoff = (uint32_t)(arow * SP + acol) * 2;
    const int brow = wn * 32 + (lane & 7) + ((lane & 16) ? 8 : 0);
    const int bcol = (lane & 8) ? 8 : 0;
    const uint32_t boff = (uint32_t)(brow * SP + bcol) * 2;

    float acc[4][4][4];
#pragma unroll
    for (int i = 0; i < 4; i++)
#pragma unroll
        for (int j = 0; j < 4; j++)
#pragma unroll
            for (int e = 0; e < 4; e++) acc[i][j][e] = 0.f;

    auto cp_chunk = [&](int c) {
        int k0 = c * 32;
        uint32_t stg = sb + (uint32_t)(c & 1) * STG2;
#pragma unroll
        for (int j = 0; j < 4; j++) {
            int u = tid + j * 256;
            int arr = u >> 9;               // 0=A, 1=B
            int r = (u >> 2) & 127;
            int seg = u & 3;
            uint32_t dst = stg + (uint32_t)arr * ABY + r * (SP * 2) + seg * 16;
            const __half* src = (arr == 0)
                ? (Agh + (size_t)(m0 + r) * KD + k0 + seg * 8)
                : (Bgh + (size_t)(n0 + r) * KD + k0 + seg * 8);
            CP16(dst, src);
        }
    };

    cp_chunk(0);
    CP_COMMIT();

    for (int c = 0; c < CH; ++c) {
        CP_WAIT0();
        __syncthreads();
        if (c + 1 < CH) { cp_chunk(c + 1); CP_COMMIT(); }

        uint32_t stg = sb + (uint32_t)(c & 1) * STG2;
        uint32_t aAh = stg + aoff;
        uint32_t aBh = stg + ABY + boff;
#pragma unroll
        for (int ks = 0; ks < 2; ks++) {
            uint32_t ah[4][4];
#pragma unroll
            for (int mi = 0; mi < 4; mi++)
                LDMX4(ah[mi], aAh + mi * (16 * SP * 2) + ks * 32);
            uint32_t bh[2][4];
#pragma unroll
            for (int np = 0; np < 2; np++)
                LDMX4(bh[np], aBh + np * (16 * SP * 2) + ks * 32);
#pragma unroll
            for (int mi = 0; mi < 4; mi++)
#pragma unroll
                for (int nj = 0; nj < 4; nj++) {
                    uint32_t b0h = bh[nj >> 1][(nj & 1) * 2];
                    uint32_t b1h = bh[nj >> 1][(nj & 1) * 2 + 1];
                    MMA16816(acc[mi][nj], ah[mi], b0h, b1h);
                }
        }
    }

    const int gid = lane >> 2, tig = lane & 3;
#pragma unroll
    for (int mi = 0; mi < 4; mi++) {
#pragma unroll
        for (int nj = 0; nj < 4; nj++) {
            int row = m0 + wm * 64 + mi * 16 + gid;
            int col = n0 + wn * 32 + nj * 8 + tig * 2;
            float b0 = bias[col], b1 = bias[col + 1];
            float v0 = fmaxf(acc[mi][nj][0] + b0, 0.f);
            float v1 = fmaxf(acc[mi][nj][1] + b1, 0.f);
            float v2 = fmaxf(acc[mi][nj][2] + b0, 0.f);
            float v3 = fmaxf(acc[mi][nj][3] + b1, 0.f);
            size_t o0 = (size_t)row * HK + col;
            size_t o1 = (size_t)(row + 8) * HK + col;
            if (MODE == 0) {
                *(float2*)(g_v + o0) = make_float2(v0, v1);
                *(float2*)(g_v + o1) = make_float2(v2, v3);
                *(uint32_t*)(g_vh + o0) = pack2h(v0, v1);
                *(uint32_t*)(g_vh + o1) = pack2h(v2, v3);
            } else {
                *(uint32_t*)(g_qh + o0) = pack2h(v0, v1);
                *(uint32_t*)(g_qh + o1) = pack2h(v2, v3);
            }
        }
    }
}

// ---------------- att GEMM: A = fp16(v_h * w_h), B = q_ fp16 -----------------
__global__ __launch_bounds__(256, 2) void att_kernel(
    const float* __restrict__ h_bias, float* __restrict__ attout) {
    extern __shared__ char smem[];
    const uint32_t sb = smem_u32(smem);
    const int tid = threadIdx.x;
    const int lane = tid & 31;
    const int wid = tid >> 5;
    const int wm = wid >> 2, wn = wid & 3;
    const int CH = HK / 32;

    const int bz = blockIdx.z >> 3;
    const int hz = blockIdx.z & 7;
    const int m0 = blockIdx.y * 128;
    const int n0 = blockIdx.x * 128;

    const __half* Ap = g_vh + (size_t)bz * VN * HK;
    const __half* Wrow = g_hwh + hz * HK;
    const __half* Qh = g_qh + (size_t)bz * QN * HK;

    const int arow = wm * 64 + (lane & 15);
    const int acol = (lane & 16) ? 8 : 0;
    const uint32_t aoff = (uint32_t)(arow * SP + acol) * 2;
    const int brow = wn * 32 + (lane & 7) + ((lane & 16) ? 8 : 0);
    const int bcol = (lane & 8) ? 8 : 0;
    const uint32_t boff = (uint32_t)(brow * SP + bcol) * 2;

    float acc[4][4][4];
#pragma unroll
    for (int i = 0; i < 4; i++)
#pragma unroll
        for (int j = 0; j < 4; j++)
#pragma unroll
            for (int e = 0; e < 4; e++) acc[i][j][e] = 0.f;

    uint4 ra[2];

    auto cpB = [&](int c) {
        int k0 = c * 32;
        uint32_t stg = sb + (uint32_t)(c & 1) * STG2;
#pragma unroll
        for (int j = 0; j < 2; j++) {
            int u = tid + j * 256;
            int r = u >> 2;
            int seg = u & 3;
            uint32_t dst = stg + ABY + r * (SP * 2) + seg * 16;
            CP16(dst, Qh + (size_t)(n0 + r) * HK + k0 + seg * 8);
        }
    };
    auto ldgA = [&](int c) {
        int k0 = c * 32;
#pragma unroll
        for (int i = 0; i < 2; i++) {
            int idx = tid + i * 256;
            int r = idx >> 2, seg = idx & 3;
            ra[i] = *(const uint4*)(Ap + (size_t)(m0 + r) * HK + k0 + seg * 8);
        }
    };
    auto stsA = [&](int c) {
        int k0 = c * 32;
        char* st = smem + (c & 1) * STG2;
#pragma unroll
        for (int i = 0; i < 2; i++) {
            int idx = tid + i * 256;
            int r = idx >> 2, seg = idx & 3;
            uint4 w = *(const uint4*)(Wrow + k0 + seg * 8);
            uint4 a = ra[i];
            __half2 r0 = __hmul2(*(__half2*)&a.x, *(__half2*)&w.x);
            __half2 r1 = __hmul2(*(__half2*)&a.y, *(__half2*)&w.y);
            __half2 r2 = __hmul2(*(__half2*)&a.z, *(__half2*)&w.z);
            __half2 r3 = __hmul2(*(__half2*)&a.w, *(__half2*)&w.w);
            uint4 o;
            o.x = *(uint32_t*)&r0; o.y = *(uint32_t*)&r1;
            o.z = *(uint32_t*)&r2; o.w = *(uint32_t*)&r3;
            *(uint4*)(st + (uint32_t)r * (SP * 2) + seg * 16) = o;
        }
    };

    cpB(0);
    CP_COMMIT();
    ldgA(0);

    for (int c = 0; c < CH; ++c) {
        CP_WAIT0();
        stsA(c);
        __syncthreads();
        if (c + 1 < CH) { cpB(c + 1); CP_COMMIT(); ldgA(c + 1); }

        uint32_t stg = sb + (uint32_t)(c & 1) * STG2;
        uint32_t aAh = stg + aoff;
        uint32_t aBh = stg + ABY + boff;
#pragma unroll
        for (int ks = 0; ks < 2; ks++) {
            uint32_t ah[4][4];
#pragma unroll
            for (int mi = 0; mi < 4; mi++)
                LDMX4(ah[mi], aAh + mi * (16 * SP * 2) + ks * 32);
            uint32_t bh[2][4];
#pragma unroll
            for (int np = 0; np < 2; np++)
                LDMX4(bh[np], aBh + np * (16 * SP * 2) + ks * 32);
#pragma unroll
            for (int mi = 0; mi < 4; mi++)
#pragma unroll
                for (int nj = 0; nj < 4; nj++) {
                    uint32_t b0h = bh[nj >> 1][(nj & 1) * 2];
                    uint32_t b1h = bh[nj >> 1][(nj & 1) * 2 + 1];
                    MMA16816(acc[mi][nj], ah[mi], b0h, b1h);
                }
        }
    }

    const int gid = lane >> 2, tig = lane & 3;
    float NI = __int_as_float(0xff800000);
    float hb = h_bias[hz];
    float* dst = attout + (((size_t)bz * HOUT + hz) * VN + m0) * QN + n0;
#pragma unroll
    for (int mi = 0; mi < 4; mi++) {
#pragma unroll
        for (int nj = 0; nj < 4; nj++) {
            int rl = wm * 64 + mi * 16 + gid;
            int cl = wn * 32 + nj * 8 + tig * 2;
            bool vm0 = g_vmask[bz * VN + m0 + rl] != 0;
            bool vm1 = g_vmask[bz * VN + m0 + rl + 8] != 0;
            bool qm0 = g_qmask[bz * QN + n0 + cl] != 0;
            bool qm1 = g_qmask[bz * QN + n0 + cl + 1] != 0;
            float v0 = (vm0 || qm0) ? NI : acc[mi][nj][0] + hb;
            float v1 = (vm0 || qm1) ? NI : acc[mi][nj][1] + hb;
            float v2 = (vm1 || qm0) ? NI : acc[mi][nj][2] + hb;
            float v3 = (vm1 || qm1) ? NI : acc[mi][nj][3] + hb;
            *(float2*)(dst + (size_t)rl * QN + cl) = make_float2(v0, v1);
            *(float2*)(dst + (size_t)(rl + 8) * QN + cl) = make_float2(v2, v3);
        }
    }
}

// ---------------- S = sum over heads of att, split fp16 hi/lo ----------------
__global__ void sumS_kernel(const float* __restrict__ att) {
    int i = blockIdx.x * blockDim.x + threadIdx.x;
    const int per = VN * QN / 4;
    int b = i / per, off = i - b * per;
    const float4* a = (const float4*)att;
    size_t base = (size_t)b * HOUT * per + off;
    float4 s = a[base];
#pragma unroll
    for (int h = 1; h < HOUT; h++) {
        float4 x = a[base + (size_t)h * per];
        s.x += x.x; s.y += x.y; s.z += x.z; s.w += x.w;
    }
    uint2 hi, lo;
    split2h(s.x, s.y, hi.x, lo.x);
    split2h(s.z, s.w, hi.y, lo.y);
    size_t o = ((size_t)b * per + off) * 4;
    *(uint2*)(g_ssh + o) = hi;
    *(uint2*)(g_ssl + o) = lo;
}

// ---------------- pool via MMA: logits_k = sum_v v_ .* (S @ q_) --------------
#define PBSP 136
#define PBBY (32 * PBSP * 2)            // 8704
#define PSTG (2 * ABY + PBBY)           // 29184
#define PSMB (2 * PSTG + 1024)          // 59392

__global__ __launch_bounds__(256, 2) void pool_mma_kernel() {
    extern __shared__ char smem[];
    const uint32_t sb = smem_u32(smem);
    float* red = (float*)(smem + 2 * PSTG);
    const int tid = threadIdx.x;
    const int lane = tid & 31;
    const int wid = tid >> 5;
    const int wm = wid >> 2, wn = wid & 3;
    const int gid = lane >> 2, tig = lane & 3;

    const int bz = blockIdx.y;
    const int k0 = blockIdx.x * 128;

    const __half* Sh = g_ssh + (size_t)bz * VN * QN;
    const __half* Sl = g_ssl + (size_t)bz * VN * QN;
    const __half* Qh = g_qh + (size_t)bz * QN * HK;
    const float* Vp = g_v + (size_t)bz * VN * HK;

    const int arow = wm * 64 + (lane & 15);
    const int acol = (lane & 16) ? 8 : 0;
    const uint32_t aoff = (uint32_t)(arow * SP + acol) * 2;
    const int bg = lane >> 3, br = lane & 7;
    const uint32_t btoff = (uint32_t)(((bg & 1) * 8 + br) * PBSP +
                                     wn * 32 + (bg >> 1) * 8) * 2;

    float ps[4][2];
#pragma unroll
    for (int j = 0; j < 4; j++) { ps[j][0] = 0.f; ps[j][1] = 0.f; }

    auto cp_chunk = [&](int mt, int c) {
        int q0 = c * 32;
        uint32_t stg = sb + (uint32_t)(c & 1) * PSTG;
#pragma unroll
        for (int j = 0; j < 4; j++) {
            int u = tid + j * 256;
            int arr = u >> 9;
            int r = (u >> 2) & 127;
            int seg = u & 3;
            uint32_t dst = stg + (uint32_t)arr * ABY + r * (SP * 2) + seg * 16;
            const __half* src = (arr ? Sl : Sh) +
                (size_t)(mt * 128 + r) * QN + q0 + seg * 8;
            CP16(dst, src);
        }
#pragma unroll
        for (int j = 0; j < 2; j++) {
            int u = tid + j * 256;
            int r = (u >> 4) & 31;
            int seg = u & 15;
            uint32_t dst = stg + 2 * ABY + r * (PBSP * 2) + seg * 16;
            CP16(dst, Qh + (size_t)(q0 + r) * HK + k0 + seg * 8);
        }
    };

    for (int mt = 0; mt < 2; mt++) {
        float acc[4][4][4];
#pragma unroll
        for (int i = 0; i < 4; i++)
#pragma unroll
            for (int j = 0; j < 4; j++)
#pragma unroll
                for (int e = 0; e < 4; e++) acc[i][j][e] = 0.f;

        cp_chunk(mt, 0);
        CP_COMMIT();

        for (int c = 0; c < 8; ++c) {
            CP_WAIT0();
            __syncthreads();
            if (c + 1 < 8) { cp_chunk(mt, c + 1); CP_COMMIT(); }

            uint32_t stg = sb + (uint32_t)(c & 1) * PSTG;
            uint32_t aAh = stg + aoff;
            uint32_t aBh = stg + 2 * ABY + btoff;
#pragma unroll
            for (int ks = 0; ks < 2; ks++) {
                uint32_t ah[4][4], al[4][4];
#pragma unroll
                for (int mi = 0; mi < 4; mi++) {
                    uint32_t ad = aAh + mi * (16 * SP * 2) + ks * 32;
                    LDMX4(ah[mi], ad);
                    LDMX4(al[mi], ad + ABY);
                }
                uint32_t bh[2][4];
#pragma unroll
                for (int np = 0; np < 2; np++) {
                    uint32_t bd = aBh + ks * 16 * (PBSP * 2) + np * 32;
                    LDMX4T(bh[np], bd);
                }
#pragma unroll
                for (int mi = 0; mi < 4; mi++)
#pragma unroll
                    for (int np = 0; np < 2; np++) {
                        MMA16816(acc[mi][np * 2],     ah[mi], bh[np][0], bh[np][1]);
                        MMA16816(acc[mi][np * 2],     al[mi], bh[np][0], bh[np][1]);
                        MMA16816(acc[mi][np * 2 + 1], ah[mi], bh[np][2], bh[np][3]);
                        MMA16816(acc[mi][np * 2 + 1], al[mi], bh[np][2], bh[np][3]);
                    }
            }
        }

#pragma unroll
        for (int mi = 0; mi < 4; mi++) {
#pragma unroll
            for (int nj = 0; nj < 4; nj++) {
                int row = mt * 128 + wm * 64 + mi * 16 + gid;
                int col = k0 + wn * 32 + nj * 8 + tig * 2;
                float2 v0 = *(const float2*)(Vp + (size_t)row * HK + col);
                float2 v1 = *(const float2*)(Vp + (size_t)(row + 8) * HK + col);
                ps[nj][0] = fmaf(acc[mi][nj][0], v0.x, ps[nj][0]);
                ps[nj][1] = fmaf(acc[mi][nj][1], v0.y, ps[nj][1]);
                ps[nj][0] = fmaf(acc[mi][nj][2], v1.x, ps[nj][0]);
                ps[nj][1] = fmaf(acc[mi][nj][3], v1.y, ps[nj][1]);
            }
        }
        __syncthreads();
    }

#pragma unroll
    for (int nj = 0; nj < 4; nj++)
#pragma unroll
        for (int e = 0; e < 2; e++) {
            float s = ps[nj][e];
            s += __shfl_xor_sync(0xffffffffu, s, 4);
            s += __shfl_xor_sync(0xffffffffu, s, 8);
            s += __shfl_xor_sync(0xffffffffu, s, 16);
            ps[nj][e] = s;
        }
    if (gid == 0) {
#pragma unroll
        for (int nj = 0; nj < 4; nj++) {
            red[wid * 32 + nj * 8 + tig * 2 + 0] = ps[nj][0];
            red[wid * 32 + nj * 8 + tig * 2 + 1] = ps[nj][1];
        }
    }
    __syncthreads();
    if (tid < 128) {
        int wn2 = tid >> 5, cc = tid & 31;
        float s = red[wn2 * 32 + cc] + red[(wn2 + 4) * 32 + cc];
        g_lk[bz * HK + k0 + tid] = s;
    }
}

// ---------------- pool-of-3 + BatchNorm --------------------------------------
__global__ void bn_kernel(const float* __restrict__ gamma, const float* __restrict__ beta,
                          float* __restrict__ out) {
    int c = blockIdx.x * blockDim.x + threadIdx.x;
    if (c >= HD) return;
    float x[B];
    float mu = 0.f;
#pragma unroll
    for (int b = 0; b < B; b++) {
        const float* p = g_lk + b * HK + c * KP;
        x[b] = p[0] + p[1] + p[2];
        mu += x[b];
    }
    mu *= (1.f / B);
    float var = 0.f;
#pragma unroll
    for (int b = 0; b < B; b++) {
        float d = x[b] - mu;
        var = fmaf(d, d, var);
    }
    var *= (1.f / B);
    float scale = rsqrtf(var + 1e-5f) * gamma[c];
    float bet = beta[c];
#pragma unroll
    for (int b = 0; b < B; b++) out[b * HD + c] = (x[b] - mu) * scale + bet;
}

// ---------------- launcher ----------------------------------------------------
extern "C" void kernel_launch(void* const* d_in, const int* in_sizes, int n_in,
                              void* d_out, int out_size) {
    const float* v      = (const float*)d_in[0];
    const float* q      = (const float*)d_in[1];
    const float* Wv     = (const float*)d_in[2];
    const float* bv     = (const float*)d_in[3];
    const float* Wq     = (const float*)d_in[4];
    const float* bq     = (const float*)d_in[5];
    const float* h_mat  = (const float*)d_in[6];
    const float* h_bias = (const float*)d_in[7];
    const float* gamma  = (const float*)d_in[8];
    const float* beta   = (const float*)d_in[9];

    float* out    = (float*)d_out;
    float* logits = out;
    float* att    = out + B * HD;

    cudaFuncSetAttribute(gemm01_kernel<0, VD>,
                         cudaFuncAttributeMaxDynamicSharedMemorySize, SMB2);
    cudaFuncSetAttribute(gemm01_kernel<1, QD>,
                         cudaFuncAttributeMaxDynamicSharedMemorySize, SMB2);
    cudaFuncSetAttribute(att_kernel,
                         cudaFuncAttributeMaxDynamicSharedMemorySize, SMB2);
    cudaFuncSetAttribute(pool_mma_kernel,
                         cudaFuncAttributeMaxDynamicSharedMemorySize, PSMB);

    mask_kernel<<<1024, 256>>>(v, q);
    hw_kernel<<<(HK + 255) / 256, 256>>>(h_mat);

    split_kernel<0><<<(B * VN * VD / 4 + 255) / 256, 256>>>(v, B * VN * VD / 4);
    split_kernel<1><<<(B * QN * QD / 4 + 255) / 256, 256>>>(q, B * QN * QD / 4);
    split_kernel<2><<<(HK * VD / 4 + 255) / 256, 256>>>(Wv, HK * VD / 4);
    split_kernel<3><<<(HK * QD / 4 + 255) / 256, 256>>>(Wq, HK * QD / 4);

    gemm01_kernel<0, VD><<<dim3(HK / 128, (B * VN) / 128), 256, SMB2>>>(bv);
    gemm01_kernel<1, QD><<<dim3(HK / 128, (B * QN) / 128), 256, SMB2>>>(bq);

    att_kernel<<<dim3(QN / 128, VN / 128, B * HOUT), 256, SMB2>>>(h_bias, att);

    sumS_kernel<<<(B * VN * QN / 4) / 256, 256>>>(att);
    pool_mma_kernel<<<dim3(HK / 128, B), 256, PSMB>>>();
    bn_kernel<<<(HD + 255) / 256, 256>>>(gamma, beta, logits);
}

// round 10
// speedup vs baseline: 6.3186x; 1.1139x over previous
#include <cuda_runtime.h>
#include <cuda_fp16.h>
#include <stdint.h>
#include <math.h>

#define B    16
#define VN   256
#define QN   256
#define VD   512
#define QD   768
#define HK   1536
#define HOUT 8
#define HD   512
#define KP   3

// ---------------- scratch (device globals) ----------------------------------
__device__ float g_v[B * VN * HK];                 // v_ fp32 (pool epilogue)
__device__ __half g_vh[B * VN * HK];               // v_ fp16 (att A)
__device__ __half g_qh[B * QN * HK];               // q_ fp16
__device__ __half g_ssh[B * VN * QN];              // S fp16 hi
__device__ __half g_ssl[B * VN * QN];              // S fp16 lo
__device__ float g_lk[B * HK];
__device__ __half g_hwh[(HOUT + 1) * HK];          // 8 head rows + sum row
__device__ float g_hbsum;
__device__ unsigned char g_vmask[B * VN];
__device__ unsigned char g_qmask[B * QN];
__device__ __half g_vsh[B * VN * VD];
__device__ __half g_qsh[B * QN * QD];
__device__ __half g_wvh[HK * VD];
__device__ __half g_wqh[HK * QD];

static __device__ __forceinline__ uint32_t smem_u32(const void* p) {
    uint32_t a;
    asm("{ .reg .u64 t; cvta.to.shared.u64 t, %1; cvt.u32.u64 %0, t; }"
        : "=r"(a) : "l"(p));
    return a;
}

#define LDMX4(d, addr) \
    asm volatile("ldmatrix.sync.aligned.m8n8.x4.shared.b16 {%0,%1,%2,%3}, [%4];" \
                 : "=r"((d)[0]), "=r"((d)[1]), "=r"((d)[2]), "=r"((d)[3]) \
                 : "r"(addr))

#define LDMX4T(d, addr) \
    asm volatile("ldmatrix.sync.aligned.m8n8.x4.trans.shared.b16 {%0,%1,%2,%3}, [%4];" \
                 : "=r"((d)[0]), "=r"((d)[1]), "=r"((d)[2]), "=r"((d)[3]) \
                 : "r"(addr))

#define MMA16816(c, a, b0, b1) \
    asm volatile("mma.sync.aligned.m16n8k16.row.col.f32.f16.f16.f32 " \
                 "{%0,%1,%2,%3}, {%4,%5,%6,%7}, {%8,%9}, {%0,%1,%2,%3};" \
                 : "+f"((c)[0]), "+f"((c)[1]), "+f"((c)[2]), "+f"((c)[3]) \
                 : "r"((a)[0]), "r"((a)[1]), "r"((a)[2]), "r"((a)[3]), \
                   "r"(b0), "r"(b1))

#define CP16(dst, src) \
    asm volatile("cp.async.cg.shared.global [%0], [%1], 16;" \
                 :: "r"(dst), "l"(src))
#define CP_COMMIT() asm volatile("cp.async.commit_group;" ::: "memory")
#define CP_WAIT0()  asm volatile("cp.async.wait_group 0;" ::: "memory")

static __device__ __forceinline__ uint32_t pack2h(float a, float b) {
    __half2 h = __floats2half2_rn(a, b);
    return *(uint32_t*)&h;
}
// split with -inf guard (lo forced to 0 for non-finite values)
static __device__ __forceinline__ void split2h_safe(float x0, float x1,
                                                    uint32_t& hi, uint32_t& lo) {
    __half h0 = __float2half_rn(x0);
    __half h1 = __float2half_rn(x1);
    float l0 = isfinite(x0) ? (x0 - __half2float(h0)) : 0.f;
    float l1 = isfinite(x1) ? (x1 - __half2float(h1)) : 0.f;
    __half2 hh = __halves2half2(h0, h1);
    hi = *(uint32_t*)&hh;
    lo = pack2h(l0, l1);
}

// ---------------- fused prep: masks + fp16 rounds + head weights -------------
// blocks [0,512): v rows (round + mask); [512,1024): q rows; [1024,1216): Wv;
// [1216,1504): Wq; 1504: head weights + sum row + hbsum.
__global__ void prep_kernel(const float* __restrict__ v, const float* __restrict__ q,
                            const float* __restrict__ Wv, const float* __restrict__ Wq,
                            const float* __restrict__ h_mat,
                            const float* __restrict__ h_bias) {
    const int bid = blockIdx.x;
    const int tid = threadIdx.x;
    if (bid < 512) {
        int wid = tid >> 5, lane = tid & 31;
        int row = bid * 8 + wid;
        const float4* src = (const float4*)(v + (size_t)row * VD);
        uint2* dst = (uint2*)(g_vsh + (size_t)row * VD);
        float s = 0.f;
#pragma unroll
        for (int j = 0; j < 4; j++) {
            float4 x = src[j * 32 + lane];
            s += fabsf(x.x) + fabsf(x.y) + fabsf(x.z) + fabsf(x.w);
            uint2 h;
            h.x = pack2h(x.x, x.y);
            h.y = pack2h(x.z, x.w);
            dst[j * 32 + lane] = h;
        }
        for (int o = 16; o; o >>= 1) s += __shfl_xor_sync(0xffffffffu, s, o);
        if (lane == 0) g_vmask[row] = (s == 0.f) ? 1 : 0;
    } else if (bid < 1024) {
        int wid = tid >> 5, lane = tid & 31;
        int row = (bid - 512) * 8 + wid;
        const float4* src = (const float4*)(q + (size_t)row * QD);
        uint2* dst = (uint2*)(g_qsh + (size_t)row * QD);
        float s = 0.f;
#pragma unroll
        for (int j = 0; j < 6; j++) {
            float4 x = src[j * 32 + lane];
            s += fabsf(x.x) + fabsf(x.y) + fabsf(x.z) + fabsf(x.w);
            uint2 h;
            h.x = pack2h(x.x, x.y);
            h.y = pack2h(x.z, x.w);
            dst[j * 32 + lane] = h;
        }
        for (int o = 16; o; o >>= 1) s += __shfl_xor_sync(0xffffffffu, s, o);
        if (lane == 0) g_qmask[row] = (s == 0.f) ? 1 : 0;
    } else if (bid < 1216) {
        int base = (bid - 1024) * 1024;
#pragma unroll
        for (int j = 0; j < 4; j++) {
            int i = base + j * 256 + tid;
            float4 x = ((const float4*)Wv)[i];
            uint2 h;
            h.x = pack2h(x.x, x.y);
            h.y = pack2h(x.z, x.w);
            *(uint2*)(g_wvh + (size_t)i * 4) = h;
        }
    } else if (bid < 1504) {
        int base = (bid - 1216) * 1024;
#pragma unroll
        for (int j = 0; j < 4; j++) {
            int i = base + j * 256 + tid;
            float4 x = ((const float4*)Wq)[i];
            uint2 h;
            h.x = pack2h(x.x, x.y);
            h.y = pack2h(x.z, x.w);
            *(uint2*)(g_wqh + (size_t)i * 4) = h;
        }
    } else {
        for (int k = tid; k < HK; k += 256) {
            float s = 0.f;
#pragma unroll
            for (int h = 0; h < HOUT; h++) {
                float w = h_mat[h * HK + k];
                g_hwh[h * HK + k] = __float2half_rn(w);
                s += w;
            }
            g_hwh[HOUT * HK + k] = __float2half_rn(s);
        }
        if (tid == 0) {
            float s = 0.f;
#pragma unroll
            for (int h = 0; h < HOUT; h++) s += h_bias[h];
            g_hbsum = s;
        }
    }
}

// ---------------- smem geometry ----------------------------------------------
#define SP   40
#define ABY  (128 * SP * 2)     // 10240 B per array
#define STG2 (2 * ABY)          // 20480 B per stage (Ah, Bh)
#define SMB2 (2 * STG2)         // 40960

// ---------------- merged proj GEMM (mode = blockIdx.z) -----------------------
__global__ __launch_bounds__(256, 2) void proj_kernel(
    const float* __restrict__ bv, const float* __restrict__ bq) {
    extern __shared__ char smem[];
    const uint32_t sb = smem_u32(smem);
    const int tid = threadIdx.x;
    const int lane = tid & 31;
    const int wid = tid >> 5;
    const int wm = wid >> 2, wn = wid & 3;
    const int mode = blockIdx.z;
    const int KD = mode ? QD : VD;
    const int CH = KD / 32;
    const int m0 = blockIdx.y * 128;
    const int n0 = blockIdx.x * 128;

    const __half* Agh = mode ? g_qsh : g_vsh;
    const __half* Bgh = mode ? g_wqh : g_wvh;
    const float* bias = mode ? bq : bv;

    const int arow = wm * 64 + (lane & 15);
    const int acol = (lane & 16) ? 8 : 0;
    const uint32_t aoff = (uint32_t)(arow * SP + acol) * 2;
    const int brow = wn * 32 + (lane & 7) + ((lane & 16) ? 8 : 0);
    const int bcol = (lane & 8) ? 8 : 0;
    const uint32_t boff = (uint32_t)(brow * SP + bcol) * 2;

    float acc[4][4][4];
#pragma unroll
    for (int i = 0; i < 4; i++)
#pragma unroll
        for (int j = 0; j < 4; j++)
#pragma unroll
            for (int e = 0; e < 4; e++) acc[i][j][e] = 0.f;

    auto cp_chunk = [&](int c) {
        int k0 = c * 32;
        uint32_t stg = sb + (uint32_t)(c & 1) * STG2;
#pragma unroll
        for (int j = 0; j < 4; j++) {
            int u = tid + j * 256;
            int arr = u >> 9;
            int r = (u >> 2) & 127;
            int seg = u & 3;
            uint32_t dst = stg + (uint32_t)arr * ABY + r * (SP * 2) + seg * 16;
            const __half* src = (arr == 0)
                ? (Agh + (size_t)(m0 + r) * KD + k0 + seg * 8)
                : (Bgh + (size_t)(n0 + r) * KD + k0 + seg * 8);
            CP16(dst, src);
        }
    };

    cp_chunk(0);
    CP_COMMIT();

    for (int c = 0; c < CH; ++c) {
        CP_WAIT0();
        __syncthreads();
        if (c + 1 < CH) { cp_chunk(c + 1); CP_COMMIT(); }

        uint32_t stg = sb + (uint32_t)(c & 1) * STG2;
        uint32_t aAh = stg + aoff;
        uint32_t aBh = stg + ABY + boff;
#pragma unroll
        for (int ks = 0; ks < 2; ks++) {
            uint32_t ah[4][4];
#pragma unroll
            for (int mi = 0; mi < 4; mi++)
                LDMX4(ah[mi], aAh + mi * (16 * SP * 2) + ks * 32);
            uint32_t bh[2][4];
#pragma unroll
            for (int np = 0; np < 2; np++)
                LDMX4(bh[np], aBh + np * (16 * SP * 2) + ks * 32);
#pragma unroll
            for (int mi = 0; mi < 4; mi++)
#pragma unroll
                for (int nj = 0; nj < 4; nj++) {
                    uint32_t b0h = bh[nj >> 1][(nj & 1) * 2];
                    uint32_t b1h = bh[nj >> 1][(nj & 1) * 2 + 1];
                    MMA16816(acc[mi][nj], ah[mi], b0h, b1h);
                }
        }
    }

    const int gid = lane >> 2, tig = lane & 3;
#pragma unroll
    for (int mi = 0; mi < 4; mi++) {
#pragma unroll
        for (int nj = 0; nj < 4; nj++) {
            int row = m0 + wm * 64 + mi * 16 + gid;
            int col = n0 + wn * 32 + nj * 8 + tig * 2;
            float b0 = bias[col], b1 = bias[col + 1];
            float v0 = fmaxf(acc[mi][nj][0] + b0, 0.f);
            float v1 = fmaxf(acc[mi][nj][1] + b1, 0.f);
            float v2 = fmaxf(acc[mi][nj][2] + b0, 0.f);
            float v3 = fmaxf(acc[mi][nj][3] + b1, 0.f);
            size_t o0 = (size_t)row * HK + col;
            size_t o1 = (size_t)(row + 8) * HK + col;
            if (mode == 0) {
                *(float2*)(g_v + o0) = make_float2(v0, v1);
                *(float2*)(g_v + o1) = make_float2(v2, v3);
                *(uint32_t*)(g_vh + o0) = pack2h(v0, v1);
                *(uint32_t*)(g_vh + o1) = pack2h(v2, v3);
            } else {
                *(uint32_t*)(g_qh + o0) = pack2h(v0, v1);
                *(uint32_t*)(g_qh + o1) = pack2h(v2, v3);
            }
        }
    }
}

// ---------------- att GEMM: 9 heads (hz==8 -> S fp16 hi/lo) ------------------
__global__ __launch_bounds__(256, 2) void att_kernel(
    const float* __restrict__ h_bias, float* __restrict__ attout) {
    extern __shared__ char smem[];
    const uint32_t sb = smem_u32(smem);
    const int tid = threadIdx.x;
    const int lane = tid & 31;
    const int wid = tid >> 5;
    const int wm = wid >> 2, wn = wid & 3;
    const int CH = HK / 32;

    const int bz = blockIdx.z / 9;
    const int hz = blockIdx.z - bz * 9;
    const int m0 = blockIdx.y * 128;
    const int n0 = blockIdx.x * 128;

    const __half* Ap = g_vh + (size_t)bz * VN * HK;
    const __half* Wrow = g_hwh + hz * HK;
    const __half* Qh = g_qh + (size_t)bz * QN * HK;

    const int arow = wm * 64 + (lane & 15);
    const int acol = (lane & 16) ? 8 : 0;
    const uint32_t aoff = (uint32_t)(arow * SP + acol) * 2;
    const int brow = wn * 32 + (lane & 7) + ((lane & 16) ? 8 : 0);
    const int bcol = (lane & 8) ? 8 : 0;
    const uint32_t boff = (uint32_t)(brow * SP + bcol) * 2;

    float acc[4][4][4];
#pragma unroll
    for (int i = 0; i < 4; i++)
#pragma unroll
        for (int j = 0; j < 4; j++)
#pragma unroll
            for (int e = 0; e < 4; e++) acc[i][j][e] = 0.f;

    uint4 ra[2];

    auto cpB = [&](int c) {
        int k0 = c * 32;
        uint32_t stg = sb + (uint32_t)(c & 1) * STG2;
#pragma unroll
        for (int j = 0; j < 2; j++) {
            int u = tid + j * 256;
            int r = u >> 2;
            int seg = u & 3;
            uint32_t dst = stg + ABY + r * (SP * 2) + seg * 16;
            CP16(dst, Qh + (size_t)(n0 + r) * HK + k0 + seg * 8);
        }
    };
    auto ldgA = [&](int c) {
        int k0 = c * 32;
#pragma unroll
        for (int i = 0; i < 2; i++) {
            int idx = tid + i * 256;
            int r = idx >> 2, seg = idx & 3;
            ra[i] = *(const uint4*)(Ap + (size_t)(m0 + r) * HK + k0 + seg * 8);
        }
    };
    auto stsA = [&](int c) {
        int k0 = c * 32;
        char* st = smem + (c & 1) * STG2;
#pragma unroll
        for (int i = 0; i < 2; i++) {
            int idx = tid + i * 256;
            int r = idx >> 2, seg = idx & 3;
            uint4 w = *(const uint4*)(Wrow + k0 + seg * 8);
            uint4 a = ra[i];
            __half2 r0 = __hmul2(*(__half2*)&a.x, *(__half2*)&w.x);
            __half2 r1 = __hmul2(*(__half2*)&a.y, *(__half2*)&w.y);
            __half2 r2 = __hmul2(*(__half2*)&a.z, *(__half2*)&w.z);
            __half2 r3 = __hmul2(*(__half2*)&a.w, *(__half2*)&w.w);
            uint4 o;
            o.x = *(uint32_t*)&r0; o.y = *(uint32_t*)&r1;
            o.z = *(uint32_t*)&r2; o.w = *(uint32_t*)&r3;
            *(uint4*)(st + (uint32_t)r * (SP * 2) + seg * 16) = o;
        }
    };

    cpB(0);
    CP_COMMIT();
    ldgA(0);

    for (int c = 0; c < CH; ++c) {
        CP_WAIT0();
        stsA(c);
        __syncthreads();
        if (c + 1 < CH) { cpB(c + 1); CP_COMMIT(); ldgA(c + 1); }

        uint32_t stg = sb + (uint32_t)(c & 1) * STG2;
        uint32_t aAh = stg + aoff;
        uint32_t aBh = stg + ABY + boff;
#pragma unroll
        for (int ks = 0; ks < 2; ks++) {
            uint32_t ah[4][4];
#pragma unroll
            for (int mi = 0; mi < 4; mi++)
                LDMX4(ah[mi], aAh + mi * (16 * SP * 2) + ks * 32);
            uint32_t bh[2][4];
#pragma unroll
            for (int np = 0; np < 2; np++)
                LDMX4(bh[np], aBh + np * (16 * SP * 2) + ks * 32);
#pragma unroll
            for (int mi = 0; mi < 4; mi++)
#pragma unroll
                for (int nj = 0; nj < 4; nj++) {
                    uint32_t b0h = bh[nj >> 1][(nj & 1) * 2];
                    uint32_t b1h = bh[nj >> 1][(nj & 1) * 2 + 1];
                    MMA16816(acc[mi][nj], ah[mi], b0h, b1h);
                }
        }
    }

    const int gid = lane >> 2, tig = lane & 3;
    float NI = __int_as_float(0xff800000);
    if (hz < 8) {
        float hb = h_bias[hz];
        float* dst = attout + (((size_t)bz * HOUT + hz) * VN + m0) * QN + n0;
#pragma unroll
        for (int mi = 0; mi < 4; mi++) {
#pragma unroll
            for (int nj = 0; nj < 4; nj++) {
                int rl = wm * 64 + mi * 16 + gid;
                int cl = wn * 32 + nj * 8 + tig * 2;
                bool vm0 = g_vmask[bz * VN + m0 + rl] != 0;
                bool vm1 = g_vmask[bz * VN + m0 + rl + 8] != 0;
                bool qm0 = g_qmask[bz * QN + n0 + cl] != 0;
                bool qm1 = g_qmask[bz * QN + n0 + cl + 1] != 0;
                float v0 = (vm0 || qm0) ? NI : acc[mi][nj][0] + hb;
                float v1 = (vm0 || qm1) ? NI : acc[mi][nj][1] + hb;
                float v2 = (vm1 || qm0) ? NI : acc[mi][nj][2] + hb;
                float v3 = (vm1 || qm1) ? NI : acc[mi][nj][3] + hb;
                *(float2*)(dst + (size_t)rl * QN + cl) = make_float2(v0, v1);
                *(float2*)(dst + (size_t)(rl + 8) * QN + cl) = make_float2(v2, v3);
            }
        }
    } else {
        float hb = g_hbsum;
        __half* dh = g_ssh + ((size_t)bz * VN + m0) * QN + n0;
        __half* dl = g_ssl + ((size_t)bz * VN + m0) * QN + n0;
#pragma unroll
        for (int mi = 0; mi < 4; mi++) {
#pragma unroll
            for (int nj = 0; nj < 4; nj++) {
                int rl = wm * 64 + mi * 16 + gid;
                int cl = wn * 32 + nj * 8 + tig * 2;
                bool vm0 = g_vmask[bz * VN + m0 + rl] != 0;
                bool vm1 = g_vmask[bz * VN + m0 + rl + 8] != 0;
                bool qm0 = g_qmask[bz * QN + n0 + cl] != 0;
                bool qm1 = g_qmask[bz * QN + n0 + cl + 1] != 0;
                float s0 = (vm0 || qm0) ? NI : acc[mi][nj][0] + hb;
                float s1 = (vm0 || qm1) ? NI : acc[mi][nj][1] + hb;
                float s2 = (vm1 || qm0) ? NI : acc[mi][nj][2] + hb;
                float s3 = (vm1 || qm1) ? NI : acc[mi][nj][3] + hb;
                uint32_t h0, l0, h1, l1;
                split2h_safe(s0, s1, h0, l0);
                split2h_safe(s2, s3, h1, l1);
                *(uint32_t*)(dh + (size_t)rl * QN + cl) = h0;
                *(uint32_t*)(dl + (size_t)rl * QN + cl) = l0;
                *(uint32_t*)(dh + (size_t)(rl + 8) * QN + cl) = h1;
                *(uint32_t*)(dl + (size_t)(rl + 8) * QN + cl) = l1;
            }
        }
    }
}

// ---------------- pool via MMA: logits_k = sum_v v_ .* (S @ q_) --------------
#define PBSP 136
#define PBBY (32 * PBSP * 2)            // 8704
#define PSTG (2 * ABY + PBBY)           // 29184
#define PSMB (2 * PSTG + 1024)          // 59392

__global__ __launch_bounds__(256, 2) void pool_mma_kernel() {
    extern __shared__ char smem[];
    const uint32_t sb = smem_u32(smem);
    float* red = (float*)(smem + 2 * PSTG);
    const int tid = threadIdx.x;
    const int lane = tid & 31;
    const int wid = tid >> 5;
    const int wm = wid >> 2, wn = wid & 3;
    const int gid = lane >> 2, tig = lane & 3;

    const int bz = blockIdx.y;
    const int k0 = blockIdx.x * 128;

    const __half* Sh = g_ssh + (size_t)bz * VN * QN;
    const __half* Sl = g_ssl + (size_t)bz * VN * QN;
    const __half* Qh = g_qh + (size_t)bz * QN * HK;
    const float* Vp = g_v + (size_t)bz * VN * HK;

    const int arow = wm * 64 + (lane & 15);
    const int acol = (lane & 16) ? 8 : 0;
    const uint32_t aoff = (uint32_t)(arow * SP + acol) * 2;
    const int bg = lane >> 3, br = lane & 7;
    const uint32_t btoff = (uint32_t)(((bg & 1) * 8 + br) * PBSP +
                                     wn * 32 + (bg >> 1) * 8) * 2;

    float ps[4][2];
#pragma unroll
    for (int j = 0; j < 4; j++) { ps[j][0] = 0.f; ps[j][1] = 0.f; }

    auto cp_chunk = [&](int mt, int c) {
        int q0 = c * 32;
        uint32_t stg = sb + (uint32_t)(c & 1) * PSTG;
#pragma unroll
        for (int j = 0; j < 4; j++) {
            int u = tid + j * 256;
            int arr = u >> 9;
            int r = (u >> 2) & 127;
            int seg = u & 3;
            uint32_t dst = stg + (uint32_t)arr * ABY + r * (SP * 2) + seg * 16;
            const __half* src = (arr ? Sl : Sh) +
                (size_t)(mt * 128 + r) * QN + q0 + seg * 8;
            CP16(dst, src);
        }
#pragma unroll
        for (int j = 0; j < 2; j++) {
            int u = tid + j * 256;
            int r = (u >> 4) & 31;
            int seg = u & 15;
            uint32_t dst = stg + 2 * ABY + r * (PBSP * 2) + seg * 16;
            CP16(dst, Qh + (size_t)(q0 + r) * HK + k0 + seg * 8);
        }
    };

    for (int mt = 0; mt < 2; mt++) {
        float acc[4][4][4];
#pragma unroll
        for (int i = 0; i < 4; i++)
#pragma unroll
            for (int j = 0; j < 4; j++)
#pragma unroll
                for (int e = 0; e < 4; e++) acc[i][j][e] = 0.f;

        cp_chunk(mt, 0);
        CP_COMMIT();

        for (int c = 0; c < 8; ++c) {
            CP_WAIT0();
            __syncthreads();
            if (c + 1 < 8) { cp_chunk(mt, c + 1); CP_COMMIT(); }

            uint32_t stg = sb + (uint32_t)(c & 1) * PSTG;
            uint32_t aAh = stg + aoff;
            uint32_t aBh = stg + 2 * ABY + btoff;
#pragma unroll
            for (int ks = 0; ks < 2; ks++) {
                uint32_t ah[4][4], al[4][4];
#pragma unroll
                for (int mi = 0; mi < 4; mi++) {
                    uint32_t ad = aAh + mi * (16 * SP * 2) + ks * 32;
                    LDMX4(ah[mi], ad);
                    LDMX4(al[mi], ad + ABY);
                }
                uint32_t bh[2][4];
#pragma unroll
                for (int np = 0; np < 2; np++) {
                    uint32_t bd = aBh + ks * 16 * (PBSP * 2) + np * 32;
                    LDMX4T(bh[np], bd);
                }
#pragma unroll
                for (int mi = 0; mi < 4; mi++)
#pragma unroll
                    for (int np = 0; np < 2; np++) {
                        MMA16816(acc[mi][np * 2],     ah[mi], bh[np][0], bh[np][1]);
                        MMA16816(acc[mi][np * 2],     al[mi], bh[np][0], bh[np][1]);
                        MMA16816(acc[mi][np * 2 + 1], ah[mi], bh[np][2], bh[np][3]);
                        MMA16816(acc[mi][np * 2 + 1], al[mi], bh[np][2], bh[np][3]);
                    }
            }
        }

#pragma unroll
        for (int mi = 0; mi < 4; mi++) {
#pragma unroll
            for (int nj = 0; nj < 4; nj++) {
                int row = mt * 128 + wm * 64 + mi * 16 + gid;
                int col = k0 + wn * 32 + nj * 8 + tig * 2;
                float2 v0 = *(const float2*)(Vp + (size_t)row * HK + col);
                float2 v1 = *(const float2*)(Vp + (size_t)(row + 8) * HK + col);
                ps[nj][0] = fmaf(acc[mi][nj][0], v0.x, ps[nj][0]);
                ps[nj][1] = fmaf(acc[mi][nj][1], v0.y, ps[nj][1]);
                ps[nj][0] = fmaf(acc[mi][nj][2], v1.x, ps[nj][0]);
                ps[nj][1] = fmaf(acc[mi][nj][3], v1.y, ps[nj][1]);
            }
        }
        __syncthreads();
    }

#pragma unroll
    for (int nj = 0; nj < 4; nj++)
#pragma unroll
        for (int e = 0; e < 2; e++) {
            float s = ps[nj][e];
            s += __shfl_xor_sync(0xffffffffu, s, 4);
            s += __shfl_xor_sync(0xffffffffu, s, 8);
            s += __shfl_xor_sync(0xffffffffu, s, 16);
            ps[nj][e] = s;
        }
    if (gid == 0) {
#pragma unroll
        for (int nj = 0; nj < 4; nj++) {
            red[wid * 32 + nj * 8 + tig * 2 + 0] = ps[nj][0];
            red[wid * 32 + nj * 8 + tig * 2 + 1] = ps[nj][1];
        }
    }
    __syncthreads();
    if (tid < 128) {
        int wn2 = tid >> 5, cc = tid & 31;
        float s = red[wn2 * 32 + cc] + red[(wn2 + 4) * 32 + cc];
        g_lk[bz * HK + k0 + tid] = s;
    }
}

// ---------------- pool-of-3 + BatchNorm --------------------------------------
__global__ void bn_kernel(const float* __restrict__ gamma, const float* __restrict__ beta,
                          float* __restrict__ out) {
    int c = blockIdx.x * blockDim.x + threadIdx.x;
    if (c >= HD) return;
    float x[B];
    float mu = 0.f;
#pragma unroll
    for (int b = 0; b < B; b++) {
        const float* p = g_lk + b * HK + c * KP;
        x[b] = p[0] + p[1] + p[2];
        mu += x[b];
    }
    mu *= (1.f / B);
    float var = 0.f;
#pragma unroll
    for (int b = 0; b < B; b++) {
        float d = x[b] - mu;
        var = fmaf(d, d, var);
    }
    var *= (1.f / B);
    float scale = rsqrtf(var + 1e-5f) * gamma[c];
    float bet = beta[c];
#pragma unroll
    for (int b = 0; b < B; b++) out[b * HD + c] = (x[b] - mu) * scale + bet;
}

// ---------------- launcher ----------------------------------------------------
extern "C" void kernel_launch(void* const* d_in, const int* in_sizes, int n_in,
                              void* d_out, int out_size) {
    const float* v      = (const float*)d_in[0];
    const float* q      = (const float*)d_in[1];
    const float* Wv     = (const float*)d_in[2];
    const float* bv     = (const float*)d_in[3];
    const float* Wq     = (const float*)d_in[4];
    const float* bq     = (const float*)d_in[5];
    const float* h_mat  = (const float*)d_in[6];
    const float* h_bias = (const float*)d_in[7];
    const float* gamma  = (const float*)d_in[8];
    const float* beta   = (const float*)d_in[9];

    float* out    = (float*)d_out;
    float* logits = out;
    float* att    = out + B * HD;

    cudaFuncSetAttribute(proj_kernel,
                         cudaFuncAttributeMaxDynamicSharedMemorySize, SMB2);
    cudaFuncSetAttribute(att_kernel,
                         cudaFuncAttributeMaxDynamicSharedMemorySize, SMB2);
    cudaFuncSetAttribute(pool_mma_kernel,
                         cudaFuncAttributeMaxDynamicSharedMemorySize, PSMB);

    prep_kernel<<<1505, 256>>>(v, q, Wv, Wq, h_mat, h_bias);
    proj_kernel<<<dim3(HK / 128, (B * VN) / 128, 2), 256, SMB2>>>(bv, bq);
    att_kernel<<<dim3(QN / 128, VN / 128, B * 9), 256, SMB2>>>(h_bias, att);
    pool_mma_kernel<<<dim3(HK / 128, B), 256, PSMB>>>();
    bn_kernel<<<(HD + 255) / 256, 256>>>(gamma, beta, logits);
}

// round 11
// speedup vs baseline: 6.4420x; 1.0195x over previous
#include <cuda_runtime.h>
#include <cuda_fp16.h>
#include <stdint.h>
#include <math.h>

#define B    16
#define VN   256
#define QN   256
#define VD   512
#define QD   768
#define HK   1536
#define HOUT 8
#define HD   512
#define KP   3

// ---------------- scratch (device globals) ----------------------------------
__device__ float g_v[B * VN * HK];                 // v_ fp32 (pool epilogue)
__device__ __half g_vh[B * VN * HK];               // v_ fp16 (att A)
__device__ __half g_qh[B * QN * HK];               // q_ fp16
__device__ __half g_ssh[B * VN * QN];              // S fp16 hi
__device__ __half g_ssl[B * VN * QN];              // S fp16 lo
__device__ float g_lk[B * HK];
__device__ __half g_hwh[(HOUT + 1) * HK];          // 8 head rows + sum row
__device__ float g_hbsum;
__device__ unsigned char g_vmask[B * VN];
__device__ unsigned char g_qmask[B * QN];
__device__ __half g_vsh[B * VN * VD];
__device__ __half g_qsh[B * QN * QD];
__device__ __half g_wvh[HK * VD];
__device__ __half g_wqh[HK * QD];

static __device__ __forceinline__ uint32_t smem_u32(const void* p) {
    uint32_t a;
    asm("{ .reg .u64 t; cvta.to.shared.u64 t, %1; cvt.u32.u64 %0, t; }"
        : "=r"(a) : "l"(p));
    return a;
}

#define LDMX4(d, addr) \
    asm volatile("ldmatrix.sync.aligned.m8n8.x4.shared.b16 {%0,%1,%2,%3}, [%4];" \
                 : "=r"((d)[0]), "=r"((d)[1]), "=r"((d)[2]), "=r"((d)[3]) \
                 : "r"(addr))

#define LDMX4T(d, addr) \
    asm volatile("ldmatrix.sync.aligned.m8n8.x4.trans.shared.b16 {%0,%1,%2,%3}, [%4];" \
                 : "=r"((d)[0]), "=r"((d)[1]), "=r"((d)[2]), "=r"((d)[3]) \
                 : "r"(addr))

#define MMA16816(c, a, b0, b1) \
    asm volatile("mma.sync.aligned.m16n8k16.row.col.f32.f16.f16.f32 " \
                 "{%0,%1,%2,%3}, {%4,%5,%6,%7}, {%8,%9}, {%0,%1,%2,%3};" \
                 : "+f"((c)[0]), "+f"((c)[1]), "+f"((c)[2]), "+f"((c)[3]) \
                 : "r"((a)[0]), "r"((a)[1]), "r"((a)[2]), "r"((a)[3]), \
                   "r"(b0), "r"(b1))

#define CP16(dst, src) \
    asm volatile("cp.async.cg.shared.global [%0], [%1], 16;" \
                 :: "r"(dst), "l"(src))
#define CP_COMMIT() asm volatile("cp.async.commit_group;" ::: "memory")
#define CP_WAIT0()  asm volatile("cp.async.wait_group 0;" ::: "memory")
#define CP_WAIT1()  asm volatile("cp.async.wait_group 1;" ::: "memory")

static __device__ __forceinline__ uint32_t pack2h(float a, float b) {
    __half2 h = __floats2half2_rn(a, b);
    return *(uint32_t*)&h;
}
static __device__ __forceinline__ void split2h_safe(float x0, float x1,
                                                    uint32_t& hi, uint32_t& lo) {
    __half h0 = __float2half_rn(x0);
    __half h1 = __float2half_rn(x1);
    float l0 = isfinite(x0) ? (x0 - __half2float(h0)) : 0.f;
    float l1 = isfinite(x1) ? (x1 - __half2float(h1)) : 0.f;
    __half2 hh = __halves2half2(h0, h1);
    hi = *(uint32_t*)&hh;
    lo = pack2h(l0, l1);
}

// ---------------- fused prep ----------------------------------------------
// [0,512): v rows; [512,1024): q rows; [1024,1216): Wv; [1216,1504): Wq;
// 1504: head weights; [1505,1529): zero g_lk.
__global__ void prep_kernel(const float* __restrict__ v, const float* __restrict__ q,
                            const float* __restrict__ Wv, const float* __restrict__ Wq,
                            const float* __restrict__ h_mat,
                            const float* __restrict__ h_bias) {
    const int bid = blockIdx.x;
    const int tid = threadIdx.x;
    if (bid < 512) {
        int wid = tid >> 5, lane = tid & 31;
        int row = bid * 8 + wid;
        const float4* src = (const float4*)(v + (size_t)row * VD);
        uint2* dst = (uint2*)(g_vsh + (size_t)row * VD);
        float s = 0.f;
#pragma unroll
        for (int j = 0; j < 4; j++) {
            float4 x = src[j * 32 + lane];
            s += fabsf(x.x) + fabsf(x.y) + fabsf(x.z) + fabsf(x.w);
            uint2 h;
            h.x = pack2h(x.x, x.y);
            h.y = pack2h(x.z, x.w);
            dst[j * 32 + lane] = h;
        }
        for (int o = 16; o; o >>= 1) s += __shfl_xor_sync(0xffffffffu, s, o);
        if (lane == 0) g_vmask[row] = (s == 0.f) ? 1 : 0;
    } else if (bid < 1024) {
        int wid = tid >> 5, lane = tid & 31;
        int row = (bid - 512) * 8 + wid;
        const float4* src = (const float4*)(q + (size_t)row * QD);
        uint2* dst = (uint2*)(g_qsh + (size_t)row * QD);
        float s = 0.f;
#pragma unroll
        for (int j = 0; j < 6; j++) {
            float4 x = src[j * 32 + lane];
            s += fabsf(x.x) + fabsf(x.y) + fabsf(x.z) + fabsf(x.w);
            uint2 h;
            h.x = pack2h(x.x, x.y);
            h.y = pack2h(x.z, x.w);
            dst[j * 32 + lane] = h;
        }
        for (int o = 16; o; o >>= 1) s += __shfl_xor_sync(0xffffffffu, s, o);
        if (lane == 0) g_qmask[row] = (s == 0.f) ? 1 : 0;
    } else if (bid < 1216) {
        int base = (bid - 1024) * 1024;
#pragma unroll
        for (int j = 0; j < 4; j++) {
            int i = base + j * 256 + tid;
            float4 x = ((const float4*)Wv)[i];
            uint2 h;
            h.x = pack2h(x.x, x.y);
            h.y = pack2h(x.z, x.w);
            *(uint2*)(g_wvh + (size_t)i * 4) = h;
        }
    } else if (bid < 1504) {
        int base = (bid - 1216) * 1024;
#pragma unroll
        for (int j = 0; j < 4; j++) {
            int i = base + j * 256 + tid;
            float4 x = ((const float4*)Wq)[i];
            uint2 h;
            h.x = pack2h(x.x, x.y);
            h.y = pack2h(x.z, x.w);
            *(uint2*)(g_wqh + (size_t)i * 4) = h;
        }
    } else if (bid == 1504) {
        for (int k = tid; k < HK; k += 256) {
            float s = 0.f;
#pragma unroll
            for (int h = 0; h < HOUT; h++) {
                float w = h_mat[h * HK + k];
                g_hwh[h * HK + k] = __float2half_rn(w);
                s += w;
            }
            g_hwh[HOUT * HK + k] = __float2half_rn(s);
        }
        if (tid == 0) {
            float s = 0.f;
#pragma unroll
            for (int h = 0; h < HOUT; h++) s += h_bias[h];
            g_hbsum = s;
        }
    } else {
        int i = (bid - 1505) * 256 + tid;     // float4 index, 6144 total
        ((float4*)g_lk)[i] = make_float4(0.f, 0.f, 0.f, 0.f);
    }
}

// ---------------- smem geometry ----------------------------------------------
#define SP   40
#define ABY  (128 * SP * 2)     // 10240 B per array
#define STG2 (2 * ABY)          // 20480 B per stage (Ah, Bh)
#define SMB3 (3 * STG2)         // 61440  (proj: 3-stage)

// ---------------- merged proj GEMM (mode = blockIdx.z), 3-stage --------------
__global__ __launch_bounds__(256, 2) void proj_kernel(
    const float* __restrict__ bv, const float* __restrict__ bq) {
    extern __shared__ char smem[];
    const uint32_t sb = smem_u32(smem);
    const int tid = threadIdx.x;
    const int lane = tid & 31;
    const int wid = tid >> 5;
    const int wm = wid >> 2, wn = wid & 3;
    const int mode = blockIdx.z;
    const int KD = mode ? QD : VD;
    const int CH = KD / 32;
    const int m0 = blockIdx.y * 128;
    const int n0 = blockIdx.x * 128;

    const __half* Agh = mode ? g_qsh : g_vsh;
    const __half* Bgh = mode ? g_wqh : g_wvh;
    const float* bias = mode ? bq : bv;

    const int arow = wm * 64 + (lane & 15);
    const int acol = (lane & 16) ? 8 : 0;
    const uint32_t aoff = (uint32_t)(arow * SP + acol) * 2;
    const int brow = wn * 32 + (lane & 7) + ((lane & 16) ? 8 : 0);
    const int bcol = (lane & 8) ? 8 : 0;
    const uint32_t boff = (uint32_t)(brow * SP + bcol) * 2;

    float acc[4][4][4];
#pragma unroll
    for (int i = 0; i < 4; i++)
#pragma unroll
        for (int j = 0; j < 4; j++)
#pragma unroll
            for (int e = 0; e < 4; e++) acc[i][j][e] = 0.f;

    auto cp_chunk = [&](int c) {
        int k0 = c * 32;
        uint32_t stg = sb + (uint32_t)(c % 3) * STG2;
#pragma unroll
        for (int j = 0; j < 4; j++) {
            int u = tid + j * 256;
            int arr = u >> 9;
            int r = (u >> 2) & 127;
            int seg = u & 3;
            uint32_t dst = stg + (uint32_t)arr * ABY + r * (SP * 2) + seg * 16;
            const __half* src = (arr == 0)
                ? (Agh + (size_t)(m0 + r) * KD + k0 + seg * 8)
                : (Bgh + (size_t)(n0 + r) * KD + k0 + seg * 8);
            CP16(dst, src);
        }
    };

    cp_chunk(0);
    CP_COMMIT();
    cp_chunk(1);
    CP_COMMIT();

    for (int c = 0; c < CH; ++c) {
        CP_WAIT1();
        __syncthreads();
        if (c + 2 < CH) { cp_chunk(c + 2); CP_COMMIT(); }

        uint32_t stg = sb + (uint32_t)(c % 3) * STG2;
        uint32_t aAh = stg + aoff;
        uint32_t aBh = stg + ABY + boff;
#pragma unroll
        for (int ks = 0; ks < 2; ks++) {
            uint32_t ah[4][4];
#pragma unroll
            for (int mi = 0; mi < 4; mi++)
                LDMX4(ah[mi], aAh + mi * (16 * SP * 2) + ks * 32);
            uint32_t bh[2][4];
#pragma unroll
            for (int np = 0; np < 2; np++)
                LDMX4(bh[np], aBh + np * (16 * SP * 2) + ks * 32);
#pragma unroll
            for (int mi = 0; mi < 4; mi++)
#pragma unroll
                for (int nj = 0; nj < 4; nj++) {
                    uint32_t b0h = bh[nj >> 1][(nj & 1) * 2];
                    uint32_t b1h = bh[nj >> 1][(nj & 1) * 2 + 1];
                    MMA16816(acc[mi][nj], ah[mi], b0h, b1h);
                }
        }
    }

    const int gid = lane >> 2, tig = lane & 3;
#pragma unroll
    for (int mi = 0; mi < 4; mi++) {
#pragma unroll
        for (int nj = 0; nj < 4; nj++) {
            int row = m0 + wm * 64 + mi * 16 + gid;
            int col = n0 + wn * 32 + nj * 8 + tig * 2;
            float b0 = bias[col], b1 = bias[col + 1];
            float v0 = fmaxf(acc[mi][nj][0] + b0, 0.f);
            float v1 = fmaxf(acc[mi][nj][1] + b1, 0.f);
            float v2 = fmaxf(acc[mi][nj][2] + b0, 0.f);
            float v3 = fmaxf(acc[mi][nj][3] + b1, 0.f);
            size_t o0 = (size_t)row * HK + col;
            size_t o1 = (size_t)(row + 8) * HK + col;
            if (mode == 0) {
                *(float2*)(g_v + o0) = make_float2(v0, v1);
                *(float2*)(g_v + o1) = make_float2(v2, v3);
                *(uint32_t*)(g_vh + o0) = pack2h(v0, v1);
                *(uint32_t*)(g_vh + o1) = pack2h(v2, v3);
            } else {
                *(uint32_t*)(g_qh + o0) = pack2h(v0, v1);
                *(uint32_t*)(g_qh + o1) = pack2h(v2, v3);
            }
        }
    }
}

// ---------------- att GEMM: 9 heads (hz==8 -> S fp16 hi/lo), 2-stage ---------
#define SMB2 (2 * STG2)
__global__ __launch_bounds__(256, 2) void att_kernel(
    const float* __restrict__ h_bias, float* __restrict__ attout) {
    extern __shared__ char smem[];
    const uint32_t sb = smem_u32(smem);
    const int tid = threadIdx.x;
    const int lane = tid & 31;
    const int wid = tid >> 5;
    const int wm = wid >> 2, wn = wid & 3;
    const int CH = HK / 32;

    const int bz = blockIdx.z / 9;
    const int hz = blockIdx.z - bz * 9;
    const int m0 = blockIdx.y * 128;
    const int n0 = blockIdx.x * 128;

    const __half* Ap = g_vh + (size_t)bz * VN * HK;
    const __half* Wrow = g_hwh + hz * HK;
    const __half* Qh = g_qh + (size_t)bz * QN * HK;

    const int arow = wm * 64 + (lane & 15);
    const int acol = (lane & 16) ? 8 : 0;
    const uint32_t aoff = (uint32_t)(arow * SP + acol) * 2;
    const int brow = wn * 32 + (lane & 7) + ((lane & 16) ? 8 : 0);
    const int bcol = (lane & 8) ? 8 : 0;
    const uint32_t boff = (uint32_t)(brow * SP + bcol) * 2;

    float acc[4][4][4];
#pragma unroll
    for (int i = 0; i < 4; i++)
#pragma unroll
        for (int j = 0; j < 4; j++)
#pragma unroll
            for (int e = 0; e < 4; e++) acc[i][j][e] = 0.f;

    uint4 ra[2];

    auto cpB = [&](int c) {
        int k0 = c * 32;
        uint32_t stg = sb + (uint32_t)(c & 1) * STG2;
#pragma unroll
        for (int j = 0; j < 2; j++) {
            int u = tid + j * 256;
            int r = u >> 2;
            int seg = u & 3;
            uint32_t dst = stg + ABY + r * (SP * 2) + seg * 16;
            CP16(dst, Qh + (size_t)(n0 + r) * HK + k0 + seg * 8);
        }
    };
    auto ldgA = [&](int c) {
        int k0 = c * 32;
#pragma unroll
        for (int i = 0; i < 2; i++) {
            int idx = tid + i * 256;
            int r = idx >> 2, seg = idx & 3;
            ra[i] = *(const uint4*)(Ap + (size_t)(m0 + r) * HK + k0 + seg * 8);
        }
    };
    auto stsA = [&](int c) {
        int k0 = c * 32;
        char* st = smem + (c & 1) * STG2;
#pragma unroll
        for (int i = 0; i < 2; i++) {
            int idx = tid + i * 256;
            int r = idx >> 2, seg = idx & 3;
            uint4 w = *(const uint4*)(Wrow + k0 + seg * 8);
            uint4 a = ra[i];
            __half2 r0 = __hmul2(*(__half2*)&a.x, *(__half2*)&w.x);
            __half2 r1 = __hmul2(*(__half2*)&a.y, *(__half2*)&w.y);
            __half2 r2 = __hmul2(*(__half2*)&a.z, *(__half2*)&w.z);
            __half2 r3 = __hmul2(*(__half2*)&a.w, *(__half2*)&w.w);
            uint4 o;
            o.x = *(uint32_t*)&r0; o.y = *(uint32_t*)&r1;
            o.z = *(uint32_t*)&r2; o.w = *(uint32_t*)&r3;
            *(uint4*)(st + (uint32_t)r * (SP * 2) + seg * 16) = o;
        }
    };

    cpB(0);
    CP_COMMIT();
    ldgA(0);

    for (int c = 0; c < CH; ++c) {
        CP_WAIT0();
        stsA(c);
        __syncthreads();
        if (c + 1 < CH) { cpB(c + 1); CP_COMMIT(); ldgA(c + 1); }

        uint32_t stg = sb + (uint32_t)(c & 1) * STG2;
        uint32_t aAh = stg + aoff;
        uint32_t aBh = stg + ABY + boff;
#pragma unroll
        for (int ks = 0; ks < 2; ks++) {
            uint32_t ah[4][4];
#pragma unroll
            for (int mi = 0; mi < 4; mi++)
                LDMX4(ah[mi], aAh + mi * (16 * SP * 2) + ks * 32);
            uint32_t bh[2][4];
#pragma unroll
            for (int np = 0; np < 2; np++)
                LDMX4(bh[np], aBh + np * (16 * SP * 2) + ks * 32);
#pragma unroll
            for (int mi = 0; mi < 4; mi++)
#pragma unroll
                for (int nj = 0; nj < 4; nj++) {
                    uint32_t b0h = bh[nj >> 1][(nj & 1) * 2];
                    uint32_t b1h = bh[nj >> 1][(nj & 1) * 2 + 1];
                    MMA16816(acc[mi][nj], ah[mi], b0h, b1h);
                }
        }
    }

    const int gid = lane >> 2, tig = lane & 3;
    float NI = __int_as_float(0xff800000);
    if (hz < 8) {
        float hb = h_bias[hz];
        float* dst = attout + (((size_t)bz * HOUT + hz) * VN + m0) * QN + n0;
#pragma unroll
        for (int mi = 0; mi < 4; mi++) {
#pragma unroll
            for (int nj = 0; nj < 4; nj++) {
                int rl = wm * 64 + mi * 16 + gid;
                int cl = wn * 32 + nj * 8 + tig * 2;
                bool vm0 = g_vmask[bz * VN + m0 + rl] != 0;
                bool vm1 = g_vmask[bz * VN + m0 + rl + 8] != 0;
                bool qm0 = g_qmask[bz * QN + n0 + cl] != 0;
                bool qm1 = g_qmask[bz * QN + n0 + cl + 1] != 0;
                float v0 = (vm0 || qm0) ? NI : acc[mi][nj][0] + hb;
                float v1 = (vm0 || qm1) ? NI : acc[mi][nj][1] + hb;
                float v2 = (vm1 || qm0) ? NI : acc[mi][nj][2] + hb;
                float v3 = (vm1 || qm1) ? NI : acc[mi][nj][3] + hb;
                *(float2*)(dst + (size_t)rl * QN + cl) = make_float2(v0, v1);
                *(float2*)(dst + (size_t)(rl + 8) * QN + cl) = make_float2(v2, v3);
            }
        }
    } else {
        float hb = g_hbsum;
        __half* dh = g_ssh + ((size_t)bz * VN + m0) * QN + n0;
        __half* dl = g_ssl + ((size_t)bz * VN + m0) * QN + n0;
#pragma unroll
        for (int mi = 0; mi < 4; mi++) {
#pragma unroll
            for (int nj = 0; nj < 4; nj++) {
                int rl = wm * 64 + mi * 16 + gid;
                int cl = wn * 32 + nj * 8 + tig * 2;
                bool vm0 = g_vmask[bz * VN + m0 + rl] != 0;
                bool vm1 = g_vmask[bz * VN + m0 + rl + 8] != 0;
                bool qm0 = g_qmask[bz * QN + n0 + cl] != 0;
                bool qm1 = g_qmask[bz * QN + n0 + cl + 1] != 0;
                float s0 = (vm0 || qm0) ? NI : acc[mi][nj][0] + hb;
                float s1 = (vm0 || qm1) ? NI : acc[mi][nj][1] + hb;
                float s2 = (vm1 || qm0) ? NI : acc[mi][nj][2] + hb;
                float s3 = (vm1 || qm1) ? NI : acc[mi][nj][3] + hb;
                uint32_t h0, l0, h1, l1;
                split2h_safe(s0, s1, h0, l0);
                split2h_safe(s2, s3, h1, l1);
                *(uint32_t*)(dh + (size_t)rl * QN + cl) = h0;
                *(uint32_t*)(dl + (size_t)rl * QN + cl) = l0;
                *(uint32_t*)(dh + (size_t)(rl + 8) * QN + cl) = h1;
                *(uint32_t*)(dl + (size_t)(rl + 8) * QN + cl) = l1;
            }
        }
    }
}

// ---------------- pool via MMA, z-split over v-halves, 3-stage ---------------
#define PBSP 136
#define PBBY (32 * PBSP * 2)            // 8704
#define PSTG (2 * ABY + PBBY)           // 29184
#define PSMB (3 * PSTG + 1024)          // 88576

__global__ __launch_bounds__(256, 2) void pool_mma_kernel() {
    extern __shared__ char smem[];
    const uint32_t sb = smem_u32(smem);
    float* red = (float*)(smem + 3 * PSTG);
    const int tid = threadIdx.x;
    const int lane = tid & 31;
    const int wid = tid >> 5;
    const int wm = wid >> 2, wn = wid & 3;
    const int gid = lane >> 2, tig = lane & 3;

    const int bz = blockIdx.y;
    const int k0 = blockIdx.x * 128;
    const int mt = blockIdx.z;

    const __half* Sh = g_ssh + (size_t)bz * VN * QN;
    const __half* Sl = g_ssl + (size_t)bz * VN * QN;
    const __half* Qh = g_qh + (size_t)bz * QN * HK;
    const float* Vp = g_v + (size_t)bz * VN * HK;

    const int arow = wm * 64 + (lane & 15);
    const int acol = (lane & 16) ? 8 : 0;
    const uint32_t aoff = (uint32_t)(arow * SP + acol) * 2;
    const int bg = lane >> 3, br = lane & 7;
    const uint32_t btoff = (uint32_t)(((bg & 1) * 8 + br) * PBSP +
                                     wn * 32 + (bg >> 1) * 8) * 2;

    float ps[4][2];
#pragma unroll
    for (int j = 0; j < 4; j++) { ps[j][0] = 0.f; ps[j][1] = 0.f; }

    auto cp_chunk = [&](int c) {
        int q0 = c * 32;
        uint32_t stg = sb + (uint32_t)(c % 3) * PSTG;
#pragma unroll
        for (int j = 0; j < 4; j++) {
            int u = tid + j * 256;
            int arr = u >> 9;
            int r = (u >> 2) & 127;
            int seg = u & 3;
            uint32_t dst = stg + (uint32_t)arr * ABY + r * (SP * 2) + seg * 16;
            const __half* src = (arr ? Sl : Sh) +
                (size_t)(mt * 128 + r) * QN + q0 + seg * 8;
            CP16(dst, src);
        }
#pragma unroll
        for (int j = 0; j < 2; j++) {
            int u = tid + j * 256;
            int r = (u >> 4) & 31;
            int seg = u & 15;
            uint32_t dst = stg + 2 * ABY + r * (PBSP * 2) + seg * 16;
            CP16(dst, Qh + (size_t)(q0 + r) * HK + k0 + seg * 8);
        }
    };

    float acc[4][4][4];
#pragma unroll
    for (int i = 0; i < 4; i++)
#pragma unroll
        for (int j = 0; j < 4; j++)
#pragma unroll
            for (int e = 0; e < 4; e++) acc[i][j][e] = 0.f;

    cp_chunk(0);
    CP_COMMIT();
    cp_chunk(1);
    CP_COMMIT();

    for (int c = 0; c < 8; ++c) {
        CP_WAIT1();
        __syncthreads();
        if (c + 2 < 8) { cp_chunk(c + 2); CP_COMMIT(); }

        uint32_t stg = sb + (uint32_t)(c % 3) * PSTG;
        uint32_t aAh = stg + aoff;
        uint32_t aBh = stg + 2 * ABY + btoff;
#pragma unroll
        for (int ks = 0; ks < 2; ks++) {
            uint32_t ah[4][4], al[4][4];
#pragma unroll
            for (int mi = 0; mi < 4; mi++) {
                uint32_t ad = aAh + mi * (16 * SP * 2) + ks * 32;
                LDMX4(ah[mi], ad);
                LDMX4(al[mi], ad + ABY);
            }
            uint32_t bh[2][4];
#pragma unroll
            for (int np = 0; np < 2; np++) {
                uint32_t bd = aBh + ks * 16 * (PBSP * 2) + np * 32;
                LDMX4T(bh[np], bd);
            }
#pragma unroll
            for (int mi = 0; mi < 4; mi++)
#pragma unroll
                for (int np = 0; np < 2; np++) {
                    MMA16816(acc[mi][np * 2],     ah[mi], bh[np][0], bh[np][1]);
                    MMA16816(acc[mi][np * 2],     al[mi], bh[np][0], bh[np][1]);
                    MMA16816(acc[mi][np * 2 + 1], ah[mi], bh[np][2], bh[np][3]);
                    MMA16816(acc[mi][np * 2 + 1], al[mi], bh[np][2], bh[np][3]);
                }
        }
    }

#pragma unroll
    for (int mi = 0; mi < 4; mi++) {
#pragma unroll
        for (int nj = 0; nj < 4; nj++) {
            int row = mt * 128 + wm * 64 + mi * 16 + gid;
            int col = k0 + wn * 32 + nj * 8 + tig * 2;
            float2 v0 = *(const float2*)(Vp + (size_t)row * HK + col);
            float2 v1 = *(const float2*)(Vp + (size_t)(row + 8) * HK + col);
            ps[nj][0] = fmaf(acc[mi][nj][0], v0.x, ps[nj][0]);
            ps[nj][1] = fmaf(acc[mi][nj][1], v0.y, ps[nj][1]);
            ps[nj][0] = fmaf(acc[mi][nj][2], v1.x, ps[nj][0]);
            ps[nj][1] = fmaf(acc[mi][nj][3], v1.y, ps[nj][1]);
        }
    }

#pragma unroll
    for (int nj = 0; nj < 4; nj++)
#pragma unroll
        for (int e = 0; e < 2; e++) {
            float s = ps[nj][e];
            s += __shfl_xor_sync(0xffffffffu, s, 4);
            s += __shfl_xor_sync(0xffffffffu, s, 8);
            s += __shfl_xor_sync(0xffffffffu, s, 16);
            ps[nj][e] = s;
        }
    __syncthreads();
    if (gid == 0) {
#pragma unroll
        for (int nj = 0; nj < 4; nj++) {
            red[wid * 32 + nj * 8 + tig * 2 + 0] = ps[nj][0];
            red[wid * 32 + nj * 8 + tig * 2 + 1] = ps[nj][1];
        }
    }
    __syncthreads();
    if (tid < 128) {
        int wn2 = tid >> 5, cc = tid & 31;
        float s = red[wn2 * 32 + cc] + red[(wn2 + 4) * 32 + cc];
        atomicAdd(g_lk + bz * HK + k0 + tid, s);
    }
}

// ---------------- pool-of-3 + BatchNorm --------------------------------------
__global__ void bn_kernel(const float* __restrict__ gamma, const float* __restrict__ beta,
                          float* __restrict__ out) {
    int c = blockIdx.x * blockDim.x + threadIdx.x;
    if (c >= HD) return;
    float x[B];
    float mu = 0.f;
#pragma unroll
    for (int b = 0; b < B; b++) {
        const float* p = g_lk + b * HK + c * KP;
        x[b] = p[0] + p[1] + p[2];
        mu += x[b];
    }
    mu *= (1.f / B);
    float var = 0.f;
#pragma unroll
    for (int b = 0; b < B; b++) {
        float d = x[b] - mu;
        var = fmaf(d, d, var);
    }
    var *= (1.f / B);
    float scale = rsqrtf(var + 1e-5f) * gamma[c];
    float bet = beta[c];
#pragma unroll
    for (int b = 0; b < B; b++) out[b * HD + c] = (x[b] - mu) * scale + bet;
}

// ---------------- launcher ----------------------------------------------------
extern "C" void kernel_launch(void* const* d_in, const int* in_sizes, int n_in,
                              void* d_out, int out_size) {
    const float* v      = (const float*)d_in[0];
    const float* q      = (const float*)d_in[1];
    const float* Wv     = (const float*)d_in[2];
    const float* bv     = (const float*)d_in[3];
    const float* Wq     = (const float*)d_in[4];
    const float* bq     = (const float*)d_in[5];
    const float* h_mat  = (const float*)d_in[6];
    const float* h_bias = (const float*)d_in[7];
    const float* gamma  = (const float*)d_in[8];
    const float* beta   = (const float*)d_in[9];

    float* out    = (float*)d_out;
    float* logits = out;
    float* att    = out + B * HD;

    cudaFuncSetAttribute(proj_kernel,
                         cudaFuncAttributeMaxDynamicSharedMemorySize, SMB3);
    cudaFuncSetAttribute(att_kernel,
                         cudaFuncAttributeMaxDynamicSharedMemorySize, SMB2);
    cudaFuncSetAttribute(pool_mma_kernel,
                         cudaFuncAttributeMaxDynamicSharedMemorySize, PSMB);

    prep_kernel<<<1529, 256>>>(v, q, Wv, Wq, h_mat, h_bias);
    proj_kernel<<<dim3(HK / 128, (B * VN) / 128, 2), 256, SMB3>>>(bv, bq);
    att_kernel<<<dim3(QN / 128, VN / 128, B * 9), 256, SMB2>>>(h_bias, att);
    pool_mma_kernel<<<dim3(HK / 128, B, 2), 256, PSMB>>>();
    bn_kernel<<<(HD + 255) / 256, 256>>>(gamma, beta, logits);
}

// round 12
// speedup vs baseline: 6.4887x; 1.0073x over previous
#include <cuda_runtime.h>
#include <cuda_fp16.h>
#include <stdint.h>
#include <math.h>

#define B    16
#define VN   256
#define QN   256
#define VD   512
#define QD   768
#define HK   1536
#define HOUT 8
#define HD   512
#define KP   3

// ---------------- scratch (device globals) ----------------------------------
__device__ float g_v[B * VN * HK];                 // v_ fp32 (pool epilogue)
__device__ __half g_vh[B * VN * HK];               // v_ fp16 (att A)
__device__ __half g_qh[B * QN * HK];               // q_ fp16
__device__ __half g_ssh[B * VN * QN];              // S fp16 hi
__device__ __half g_ssl[B * VN * QN];              // S fp16 lo
__device__ float g_lk[B * HK];
__device__ __half g_hwh[(HOUT + 1) * HK];          // 8 head rows + sum row
__device__ float g_hbsum;
__device__ unsigned char g_vmask[B * VN];
__device__ unsigned char g_qmask[B * QN];
__device__ __half g_vsh[B * VN * VD];
__device__ __half g_qsh[B * QN * QD];
__device__ __half g_wvh[HK * VD];
__device__ __half g_wqh[HK * QD];

static __device__ __forceinline__ uint32_t smem_u32(const void* p) {
    uint32_t a;
    asm("{ .reg .u64 t; cvta.to.shared.u64 t, %1; cvt.u32.u64 %0, t; }"
        : "=r"(a) : "l"(p));
    return a;
}

#define LDMX4(d, addr) \
    asm volatile("ldmatrix.sync.aligned.m8n8.x4.shared.b16 {%0,%1,%2,%3}, [%4];" \
                 : "=r"((d)[0]), "=r"((d)[1]), "=r"((d)[2]), "=r"((d)[3]) \
                 : "r"(addr))

#define LDMX4T(d, addr) \
    asm volatile("ldmatrix.sync.aligned.m8n8.x4.trans.shared.b16 {%0,%1,%2,%3}, [%4];" \
                 : "=r"((d)[0]), "=r"((d)[1]), "=r"((d)[2]), "=r"((d)[3]) \
                 : "r"(addr))

#define MMA16816(c, a, b0, b1) \
    asm volatile("mma.sync.aligned.m16n8k16.row.col.f32.f16.f16.f32 " \
                 "{%0,%1,%2,%3}, {%4,%5,%6,%7}, {%8,%9}, {%0,%1,%2,%3};" \
                 : "+f"((c)[0]), "+f"((c)[1]), "+f"((c)[2]), "+f"((c)[3]) \
                 : "r"((a)[0]), "r"((a)[1]), "r"((a)[2]), "r"((a)[3]), \
                   "r"(b0), "r"(b1))

#define CP16(dst, src) \
    asm volatile("cp.async.cg.shared.global [%0], [%1], 16;" \
                 :: "r"(dst), "l"(src))
#define CP_COMMIT() asm volatile("cp.async.commit_group;" ::: "memory")
#define CP_WAIT0()  asm volatile("cp.async.wait_group 0;" ::: "memory")
#define CP_WAIT1()  asm volatile("cp.async.wait_group 1;" ::: "memory")

static __device__ __forceinline__ uint32_t pack2h(float a, float b) {
    __half2 h = __floats2half2_rn(a, b);
    return *(uint32_t*)&h;
}
static __device__ __forceinline__ void split2h_safe(float x0, float x1,
                                                    uint32_t& hi, uint32_t& lo) {
    __half h0 = __float2half_rn(x0);
    __half h1 = __float2half_rn(x1);
    float l0 = isfinite(x0) ? (x0 - __half2float(h0)) : 0.f;
    float l1 = isfinite(x1) ? (x1 - __half2float(h1)) : 0.f;
    __half2 hh = __halves2half2(h0, h1);
    hi = *(uint32_t*)&hh;
    lo = pack2h(l0, l1);
}

// ---------------- fused prep -------------------------------------------------
__global__ void prep_kernel(const float* __restrict__ v, const float* __restrict__ q,
                            const float* __restrict__ Wv, const float* __restrict__ Wq,
                            const float* __restrict__ h_mat,
                            const float* __restrict__ h_bias) {
    const int bid = blockIdx.x;
    const int tid = threadIdx.x;
    if (bid < 512) {
        int wid = tid >> 5, lane = tid & 31;
        int row = bid * 8 + wid;
        const float4* src = (const float4*)(v + (size_t)row * VD);
        uint2* dst = (uint2*)(g_vsh + (size_t)row * VD);
        float s = 0.f;
#pragma unroll
        for (int j = 0; j < 4; j++) {
            float4 x = src[j * 32 + lane];
            s += fabsf(x.x) + fabsf(x.y) + fabsf(x.z) + fabsf(x.w);
            uint2 h;
            h.x = pack2h(x.x, x.y);
            h.y = pack2h(x.z, x.w);
            dst[j * 32 + lane] = h;
        }
        for (int o = 16; o; o >>= 1) s += __shfl_xor_sync(0xffffffffu, s, o);
        if (lane == 0) g_vmask[row] = (s == 0.f) ? 1 : 0;
    } else if (bid < 1024) {
        int wid = tid >> 5, lane = tid & 31;
        int row = (bid - 512) * 8 + wid;
        const float4* src = (const float4*)(q + (size_t)row * QD);
        uint2* dst = (uint2*)(g_qsh + (size_t)row * QD);
        float s = 0.f;
#pragma unroll
        for (int j = 0; j < 6; j++) {
            float4 x = src[j * 32 + lane];
            s += fabsf(x.x) + fabsf(x.y) + fabsf(x.z) + fabsf(x.w);
            uint2 h;
            h.x = pack2h(x.x, x.y);
            h.y = pack2h(x.z, x.w);
            dst[j * 32 + lane] = h;
        }
        for (int o = 16; o; o >>= 1) s += __shfl_xor_sync(0xffffffffu, s, o);
        if (lane == 0) g_qmask[row] = (s == 0.f) ? 1 : 0;
    } else if (bid < 1216) {
        int base = (bid - 1024) * 1024;
#pragma unroll
        for (int j = 0; j < 4; j++) {
            int i = base + j * 256 + tid;
            float4 x = ((const float4*)Wv)[i];
            uint2 h;
            h.x = pack2h(x.x, x.y);
            h.y = pack2h(x.z, x.w);
            *(uint2*)(g_wvh + (size_t)i * 4) = h;
        }
    } else if (bid < 1504) {
        int base = (bid - 1216) * 1024;
#pragma unroll
        for (int j = 0; j < 4; j++) {
            int i = base + j * 256 + tid;
            float4 x = ((const float4*)Wq)[i];
            uint2 h;
            h.x = pack2h(x.x, x.y);
            h.y = pack2h(x.z, x.w);
            *(uint2*)(g_wqh + (size_t)i * 4) = h;
        }
    } else if (bid == 1504) {
        for (int k = tid; k < HK; k += 256) {
            float s = 0.f;
#pragma unroll
            for (int h = 0; h < HOUT; h++) {
                float w = h_mat[h * HK + k];
                g_hwh[h * HK + k] = __float2half_rn(w);
                s += w;
            }
            g_hwh[HOUT * HK + k] = __float2half_rn(s);
        }
        if (tid == 0) {
            float s = 0.f;
#pragma unroll
            for (int h = 0; h < HOUT; h++) s += h_bias[h];
            g_hbsum = s;
        }
    } else {
        int i = (bid - 1505) * 256 + tid;     // float4 index, 6144 total
        ((float4*)g_lk)[i] = make_float4(0.f, 0.f, 0.f, 0.f);
    }
}

// ---------------- smem geometry ----------------------------------------------
#define SP   40
#define ABY  (128 * SP * 2)     // 10240 B per array
#define STG2 (2 * ABY)          // 20480 B per stage (A, B)
#define SMB2 (2 * STG2)         // 40960  (proj: 2-stage)
#define SMB3 (3 * STG2)         // 61440  (att: 3-stage)

// ---------------- merged proj GEMM (mode = blockIdx.z), 2-stage --------------
__global__ __launch_bounds__(256, 2) void proj_kernel(
    const float* __restrict__ bv, const float* __restrict__ bq) {
    extern __shared__ char smem[];
    const uint32_t sb = smem_u32(smem);
    const int tid = threadIdx.x;
    const int lane = tid & 31;
    const int wid = tid >> 5;
    const int wm = wid >> 2, wn = wid & 3;
    const int mode = blockIdx.z;
    const int KD = mode ? QD : VD;
    const int CH = KD / 32;
    const int m0 = blockIdx.y * 128;
    const int n0 = blockIdx.x * 128;

    const __half* Agh = mode ? g_qsh : g_vsh;
    const __half* Bgh = mode ? g_wqh : g_wvh;
    const float* bias = mode ? bq : bv;

    const int arow = wm * 64 + (lane & 15);
    const int acol = (lane & 16) ? 8 : 0;
    const uint32_t aoff = (uint32_t)(arow * SP + acol) * 2;
    const int brow = wn * 32 + (lane & 7) + ((lane & 16) ? 8 : 0);
    const int bcol = (lane & 8) ? 8 : 0;
    const uint32_t boff = (uint32_t)(brow * SP + bcol) * 2;

    float acc[4][4][4];
#pragma unroll
    for (int i = 0; i < 4; i++)
#pragma unroll
        for (int j = 0; j < 4; j++)
#pragma unroll
            for (int e = 0; e < 4; e++) acc[i][j][e] = 0.f;

    auto cp_chunk = [&](int c) {
        int k0 = c * 32;
        uint32_t stg = sb + (uint32_t)(c & 1) * STG2;
#pragma unroll
        for (int j = 0; j < 4; j++) {
            int u = tid + j * 256;
            int arr = u >> 9;
            int r = (u >> 2) & 127;
            int seg = u & 3;
            uint32_t dst = stg + (uint32_t)arr * ABY + r * (SP * 2) + seg * 16;
            const __half* src = (arr == 0)
                ? (Agh + (size_t)(m0 + r) * KD + k0 + seg * 8)
                : (Bgh + (size_t)(n0 + r) * KD + k0 + seg * 8);
            CP16(dst, src);
        }
    };

    cp_chunk(0);
    CP_COMMIT();

    for (int c = 0; c < CH; ++c) {
        CP_WAIT0();
        __syncthreads();
        if (c + 1 < CH) { cp_chunk(c + 1); CP_COMMIT(); }

        uint32_t stg = sb + (uint32_t)(c & 1) * STG2;
        uint32_t aAh = stg + aoff;
        uint32_t aBh = stg + ABY + boff;
#pragma unroll
        for (int ks = 0; ks < 2; ks++) {
            uint32_t ah[4][4];
#pragma unroll
            for (int mi = 0; mi < 4; mi++)
                LDMX4(ah[mi], aAh + mi * (16 * SP * 2) + ks * 32);
            uint32_t bh[2][4];
#pragma unroll
            for (int np = 0; np < 2; np++)
                LDMX4(bh[np], aBh + np * (16 * SP * 2) + ks * 32);
#pragma unroll
            for (int mi = 0; mi < 4; mi++)
#pragma unroll
                for (int nj = 0; nj < 4; nj++) {
                    uint32_t b0h = bh[nj >> 1][(nj & 1) * 2];
                    uint32_t b1h = bh[nj >> 1][(nj & 1) * 2 + 1];
                    MMA16816(acc[mi][nj], ah[mi], b0h, b1h);
                }
        }
    }

    const int gid = lane >> 2, tig = lane & 3;
#pragma unroll
    for (int mi = 0; mi < 4; mi++) {
#pragma unroll
        for (int nj = 0; nj < 4; nj++) {
            int row = m0 + wm * 64 + mi * 16 + gid;
            int col = n0 + wn * 32 + nj * 8 + tig * 2;
            float b0 = bias[col], b1 = bias[col + 1];
            float v0 = fmaxf(acc[mi][nj][0] + b0, 0.f);
            float v1 = fmaxf(acc[mi][nj][1] + b1, 0.f);
            float v2 = fmaxf(acc[mi][nj][2] + b0, 0.f);
            float v3 = fmaxf(acc[mi][nj][3] + b1, 0.f);
            size_t o0 = (size_t)row * HK + col;
            size_t o1 = (size_t)(row + 8) * HK + col;
            if (mode == 0) {
                *(float2*)(g_v + o0) = make_float2(v0, v1);
                *(float2*)(g_v + o1) = make_float2(v2, v3);
                *(uint32_t*)(g_vh + o0) = pack2h(v0, v1);
                *(uint32_t*)(g_vh + o1) = pack2h(v2, v3);
            } else {
                *(uint32_t*)(g_qh + o0) = pack2h(v0, v1);
                *(uint32_t*)(g_qh + o1) = pack2h(v2, v3);
            }
        }
    }
}

// ---------------- att GEMM: A = v_h (pure cp.async, 3-stage), B = q_h*w ------
__global__ __launch_bounds__(256, 2) void att_kernel(
    const float* __restrict__ h_bias, float* __restrict__ attout) {
    extern __shared__ char smem[];
    const uint32_t sb = smem_u32(smem);
    const int tid = threadIdx.x;
    const int lane = tid & 31;
    const int wid = tid >> 5;
    const int wm = wid >> 2, wn = wid & 3;
    const int CH = HK / 32;

    const int bz = blockIdx.z / 9;
    const int hz = blockIdx.z - bz * 9;
    const int m0 = blockIdx.y * 128;
    const int n0 = blockIdx.x * 128;

    const __half* Ap = g_vh + (size_t)bz * VN * HK;
    const __half* Wrow = g_hwh + hz * HK;
    const __half* Qh = g_qh + (size_t)bz * QN * HK;

    const int arow = wm * 64 + (lane & 15);
    const int acol = (lane & 16) ? 8 : 0;
    const uint32_t aoff = (uint32_t)(arow * SP + acol) * 2;
    const int brow = wn * 32 + (lane & 7) + ((lane & 16) ? 8 : 0);
    const int bcol = (lane & 8) ? 8 : 0;
    const uint32_t boff = (uint32_t)(brow * SP + bcol) * 2;

    float acc[4][4][4];
#pragma unroll
    for (int i = 0; i < 4; i++)
#pragma unroll
        for (int j = 0; j < 4; j++)
#pragma unroll
            for (int e = 0; e < 4; e++) acc[i][j][e] = 0.f;

    uint4 rb[2];

    // A: cp.async v_h, 8 KB per chunk
    auto cpA = [&](int c) {
        int k0 = c * 32;
        uint32_t stg = sb + (uint32_t)(c % 3) * STG2;
#pragma unroll
        for (int j = 0; j < 2; j++) {
            int u = tid + j * 256;
            int r = u >> 2, seg = u & 3;
            uint32_t dst = stg + r * (SP * 2) + seg * 16;
            CP16(dst, Ap + (size_t)(m0 + r) * HK + k0 + seg * 8);
        }
    };
    // B: LDG q_h -> regs
    auto ldgB = [&](int c) {
        int k0 = c * 32;
#pragma unroll
        for (int i = 0; i < 2; i++) {
            int idx = tid + i * 256;
            int r = idx >> 2, seg = idx & 3;
            rb[i] = *(const uint4*)(Qh + (size_t)(n0 + r) * HK + k0 + seg * 8);
        }
    };
    // fold w into B, store to smem
    auto stsB = [&](int c) {
        int k0 = c * 32;
        char* st = smem + (c % 3) * STG2 + ABY;
#pragma unroll
        for (int i = 0; i < 2; i++) {
            int idx = tid + i * 256;
            int r = idx >> 2, seg = idx & 3;
            uint4 w = *(const uint4*)(Wrow + k0 + seg * 8);
            uint4 a = rb[i];
            __half2 r0 = __hmul2(*(__half2*)&a.x, *(__half2*)&w.x);
            __half2 r1 = __hmul2(*(__half2*)&a.y, *(__half2*)&w.y);
            __half2 r2 = __hmul2(*(__half2*)&a.z, *(__half2*)&w.z);
            __half2 r3 = __hmul2(*(__half2*)&a.w, *(__half2*)&w.w);
            uint4 o;
            o.x = *(uint32_t*)&r0; o.y = *(uint32_t*)&r1;
            o.z = *(uint32_t*)&r2; o.w = *(uint32_t*)&r3;
            *(uint4*)(st + (uint32_t)r * (SP * 2) + seg * 16) = o;
        }
    };

    cpA(0);
    CP_COMMIT();
    cpA(1);
    CP_COMMIT();
    ldgB(0);

    for (int c = 0; c < CH; ++c) {
        CP_WAIT1();
        stsB(c);
        __syncthreads();
        if (c + 1 < CH) ldgB(c + 1);
        if (c + 2 < CH) { cpA(c + 2); CP_COMMIT(); }

        uint32_t stg = sb + (uint32_t)(c % 3) * STG2;
        uint32_t aAh = stg + aoff;
        uint32_t aBh = stg + ABY + boff;
#pragma unroll
        for (int ks = 0; ks < 2; ks++) {
            uint32_t ah[4][4];
#pragma unroll
            for (int mi = 0; mi < 4; mi++)
                LDMX4(ah[mi], aAh + mi * (16 * SP * 2) + ks * 32);
            uint32_t bh[2][4];
#pragma unroll
            for (int np = 0; np < 2; np++)
                LDMX4(bh[np], aBh + np * (16 * SP * 2) + ks * 32);
#pragma unroll
            for (int mi = 0; mi < 4; mi++)
#pragma unroll
                for (int nj = 0; nj < 4; nj++) {
                    uint32_t b0h = bh[nj >> 1][(nj & 1) * 2];
                    uint32_t b1h = bh[nj >> 1][(nj & 1) * 2 + 1];
                    MMA16816(acc[mi][nj], ah[mi], b0h, b1h);
                }
        }
    }

    const int gid = lane >> 2, tig = lane & 3;
    float NI = __int_as_float(0xff800000);
    if (hz < 8) {
        float hb = h_bias[hz];
        float* dst = attout + (((size_t)bz * HOUT + hz) * VN + m0) * QN + n0;
#pragma unroll
        for (int mi = 0; mi < 4; mi++) {
#pragma unroll
            for (int nj = 0; nj < 4; nj++) {
                int rl = wm * 64 + mi * 16 + gid;
                int cl = wn * 32 + nj * 8 + tig * 2;
                bool vm0 = g_vmask[bz * VN + m0 + rl] != 0;
                bool vm1 = g_vmask[bz * VN + m0 + rl + 8] != 0;
                bool qm0 = g_qmask[bz * QN + n0 + cl] != 0;
                bool qm1 = g_qmask[bz * QN + n0 + cl + 1] != 0;
                float v0 = (vm0 || qm0) ? NI : acc[mi][nj][0] + hb;
                float v1 = (vm0 || qm1) ? NI : acc[mi][nj][1] + hb;
                float v2 = (vm1 || qm0) ? NI : acc[mi][nj][2] + hb;
                float v3 = (vm1 || qm1) ? NI : acc[mi][nj][3] + hb;
                *(float2*)(dst + (size_t)rl * QN + cl) = make_float2(v0, v1);
                *(float2*)(dst + (size_t)(rl + 8) * QN + cl) = make_float2(v2, v3);
            }
        }
    } else {
        float hb = g_hbsum;
        __half* dh = g_ssh + ((size_t)bz * VN + m0) * QN + n0;
        __half* dl = g_ssl + ((size_t)bz * VN + m0) * QN + n0;
#pragma unroll
        for (int mi = 0; mi < 4; mi++) {
#pragma unroll
            for (int nj = 0; nj < 4; nj++) {
                int rl = wm * 64 + mi * 16 + gid;
                int cl = wn * 32 + nj * 8 + tig * 2;
                bool vm0 = g_vmask[bz * VN + m0 + rl] != 0;
                bool vm1 = g_vmask[bz * VN + m0 + rl + 8] != 0;
                bool qm0 = g_qmask[bz * QN + n0 + cl] != 0;
                bool qm1 = g_qmask[bz * QN + n0 + cl + 1] != 0;
                float s0 = (vm0 || qm0) ? NI : acc[mi][nj][0] + hb;
                float s1 = (vm0 || qm1) ? NI : acc[mi][nj][1] + hb;
                float s2 = (vm1 || qm0) ? NI : acc[mi][nj][2] + hb;
                float s3 = (vm1 || qm1) ? NI : acc[mi][nj][3] + hb;
                uint32_t h0, l0, h1, l1;
                split2h_safe(s0, s1, h0, l0);
                split2h_safe(s2, s3, h1, l1);
                *(uint32_t*)(dh + (size_t)rl * QN + cl) = h0;
                *(uint32_t*)(dl + (size_t)rl * QN + cl) = l0;
                *(uint32_t*)(dh + (size_t)(rl + 8) * QN + cl) = h1;
                *(uint32_t*)(dl + (size_t)(rl + 8) * QN + cl) = l1;
            }
        }
    }
}

// ---------------- pool via MMA, z = (mt, q-half), 3-stage --------------------
#define PBSP 136
#define PBBY (32 * PBSP * 2)            // 8704
#define PSTG (2 * ABY + PBBY)           // 29184
#define PSMB (3 * PSTG + 1024)          // 88576

__global__ __launch_bounds__(256, 2) void pool_mma_kernel() {
    extern __shared__ char smem[];
    const uint32_t sb = smem_u32(smem);
    float* red = (float*)(smem + 3 * PSTG);
    const int tid = threadIdx.x;
    const int lane = tid & 31;
    const int wid = tid >> 5;
    const int wm = wid >> 2, wn = wid & 3;
    const int gid = lane >> 2, tig = lane & 3;

    const int bz = blockIdx.y;
    const int k0 = blockIdx.x * 128;
    const int mt = blockIdx.z >> 1;
    const int qbase = (blockIdx.z & 1) * 128;
    const int CC = 4;                     // 4 q-chunks of 32

    const __half* Sh = g_ssh + (size_t)bz * VN * QN;
    const __half* Sl = g_ssl + (size_t)bz * VN * QN;
    const __half* Qh = g_qh + (size_t)bz * QN * HK;
    const float* Vp = g_v + (size_t)bz * VN * HK;

    const int arow = wm * 64 + (lane & 15);
    const int acol = (lane & 16) ? 8 : 0;
    const uint32_t aoff = (uint32_t)(arow * SP + acol) * 2;
    const int bg = lane >> 3, br = lane & 7;
    const uint32_t btoff = (uint32_t)(((bg & 1) * 8 + br) * PBSP +
                                     wn * 32 + (bg >> 1) * 8) * 2;

    float ps[4][2];
#pragma unroll
    for (int j = 0; j < 4; j++) { ps[j][0] = 0.f; ps[j][1] = 0.f; }

    auto cp_chunk = [&](int c) {
        int q0 = qbase + c * 32;
        uint32_t stg = sb + (uint32_t)(c % 3) * PSTG;
#pragma unroll
        for (int j = 0; j < 4; j++) {
            int u = tid + j * 256;
            int arr = u >> 9;
            int r = (u >> 2) & 127;
            int seg = u & 3;
            uint32_t dst = stg + (uint32_t)arr * ABY + r * (SP * 2) + seg * 16;
            const __half* src = (arr ? Sl : Sh) +
                (size_t)(mt * 128 + r) * QN + q0 + seg * 8;
            CP16(dst, src);
        }
#pragma unroll
        for (int j = 0; j < 2; j++) {
            int u = tid + j * 256;
            int r = (u >> 4) & 31;
            int seg = u & 15;
            uint32_t dst = stg + 2 * ABY + r * (PBSP * 2) + seg * 16;
            CP16(dst, Qh + (size_t)(q0 + r) * HK + k0 + seg * 8);
        }
    };

    float acc[4][4][4];
#pragma unroll
    for (int i = 0; i < 4; i++)
#pragma unroll
        for (int j = 0; j < 4; j++)
#pragma unroll
            for (int e = 0; e < 4; e++) acc[i][j][e] = 0.f;

    cp_chunk(0);
    CP_COMMIT();
    cp_chunk(1);
    CP_COMMIT();

    for (int c = 0; c < CC; ++c) {
        CP_WAIT1();
        __syncthreads();
        if (c + 2 < CC) { cp_chunk(c + 2); CP_COMMIT(); }

        uint32_t stg = sb + (uint32_t)(c % 3) * PSTG;
        uint32_t aAh = stg + aoff;
        uint32_t aBh = stg + 2 * ABY + btoff;
#pragma unroll
        for (int ks = 0; ks < 2; ks++) {
            uint32_t ah[4][4], al[4][4];
#pragma unroll
            for (int mi = 0; mi < 4; mi++) {
                uint32_t ad = aAh + mi * (16 * SP * 2) + ks * 32;
                LDMX4(ah[mi], ad);
                LDMX4(al[mi], ad + ABY);
            }
            uint32_t bh[2][4];
#pragma unroll
            for (int np = 0; np < 2; np++) {
                uint32_t bd = aBh + ks * 16 * (PBSP * 2) + np * 32;
                LDMX4T(bh[np], bd);
            }
#pragma unroll
            for (int mi = 0; mi < 4; mi++)
#pragma unroll
                for (int np = 0; np < 2; np++) {
                    MMA16816(acc[mi][np * 2],     ah[mi], bh[np][0], bh[np][1]);
                    MMA16816(acc[mi][np * 2],     al[mi], bh[np][0], bh[np][1]);
                    MMA16816(acc[mi][np * 2 + 1], ah[mi], bh[np][2], bh[np][3]);
                    MMA16816(acc[mi][np * 2 + 1], al[mi], bh[np][2], bh[np][3]);
                }
        }
    }

#pragma unroll
    for (int mi = 0; mi < 4; mi++) {
#pragma unroll
        for (int nj = 0; nj < 4; nj++) {
            int row = mt * 128 + wm * 64 + mi * 16 + gid;
            int col = k0 + wn * 32 + nj * 8 + tig * 2;
            float2 v0 = *(const float2*)(Vp + (size_t)row * HK + col);
            float2 v1 = *(const float2*)(Vp + (size_t)(row + 8) * HK + col);
            ps[nj][0] = fmaf(acc[mi][nj][0], v0.x, ps[nj][0]);
            ps[nj][1] = fmaf(acc[mi][nj][1], v0.y, ps[nj][1]);
            ps[nj][0] = fmaf(acc[mi][nj][2], v1.x, ps[nj][0]);
            ps[nj][1] = fmaf(acc[mi][nj][3], v1.y, ps[nj][1]);
        }
    }

#pragma unroll
    for (int nj = 0; nj < 4; nj++)
#pragma unroll
        for (int e = 0; e < 2; e++) {
            float s = ps[nj][e];
            s += __shfl_xor_sync(0xffffffffu, s, 4);
            s += __shfl_xor_sync(0xffffffffu, s, 8);
            s += __shfl_xor_sync(0xffffffffu, s, 16);
            ps[nj][e] = s;
        }
    __syncthreads();
    if (gid == 0) {
#pragma unroll
        for (int nj = 0; nj < 4; nj++) {
            red[wid * 32 + nj * 8 + tig * 2 + 0] = ps[nj][0];
            red[wid * 32 + nj * 8 + tig * 2 + 1] = ps[nj][1];
        }
    }
    __syncthreads();
    if (tid < 128) {
        int wn2 = tid >> 5, cc = tid & 31;
        float s = red[wn2 * 32 + cc] + red[(wn2 + 4) * 32 + cc];
        atomicAdd(g_lk + bz * HK + k0 + tid, s);
    }
}

// ---------------- pool-of-3 + BatchNorm --------------------------------------
__global__ void bn_kernel(const float* __restrict__ gamma, const float* __restrict__ beta,
                          float* __restrict__ out) {
    int c = blockIdx.x * blockDim.x + threadIdx.x;
    if (c >= HD) return;
    float x[B];
    float mu = 0.f;
#pragma unroll
    for (int b = 0; b < B; b++) {
        const float* p = g_lk + b * HK + c * KP;
        x[b] = p[0] + p[1] + p[2];
        mu += x[b];
    }
    mu *= (1.f / B);
    float var = 0.f;
#pragma unroll
    for (int b = 0; b < B; b++) {
        float d = x[b] - mu;
        var = fmaf(d, d, var);
    }
    var *= (1.f / B);
    float scale = rsqrtf(var + 1e-5f) * gamma[c];
    float bet = beta[c];
#pragma unroll
    for (int b = 0; b < B; b++) out[b * HD + c] = (x[b] - mu) * scale + bet;
}

// ---------------- launcher ----------------------------------------------------
extern "C" void kernel_launch(void* const* d_in, const int* in_sizes, int n_in,
                              void* d_out, int out_size) {
    const float* v      = (const float*)d_in[0];
    const float* q      = (const float*)d_in[1];
    const float* Wv     = (const float*)d_in[2];
    const float* bv     = (const float*)d_in[3];
    const float* Wq     = (const float*)d_in[4];
    const float* bq     = (const float*)d_in[5];
    const float* h_mat  = (const float*)d_in[6];
    const float* h_bias = (const float*)d_in[7];
    const float* gamma  = (const float*)d_in[8];
    const float* beta   = (const float*)d_in[9];

    float* out    = (float*)d_out;
    float* logits = out;
    float* att    = out + B * HD;

    cudaFuncSetAttribute(proj_kernel,
                         cudaFuncAttributeMaxDynamicSharedMemorySize, SMB2);
    cudaFuncSetAttribute(att_kernel,
                         cudaFuncAttributeMaxDynamicSharedMemorySize, SMB3);
    cudaFuncSetAttribute(pool_mma_kernel,
                         cudaFuncAttributeMaxDynamicSharedMemorySize, PSMB);

    prep_kernel<<<1529, 256>>>(v, q, Wv, Wq, h_mat, h_bias);
    proj_kernel<<<dim3(HK / 128, (B * VN) / 128, 2), 256, SMB2>>>(bv, bq);
    att_kernel<<<dim3(QN / 128, VN / 128, B * 9), 256, SMB3>>>(h_bias, att);
    pool_mma_kernel<<<dim3(HK / 128, B, 4), 256, PSMB>>>();
    bn_kernel<<<(HD + 255) / 256, 256>>>(gamma, beta, logits);
}

// round 13
// speedup vs baseline: 6.7006x; 1.0326x over previous
#include <cuda_runtime.h>
#include <cuda_fp16.h>
#include <stdint.h>
#include <math.h>

#define B    16
#define VN   256
#define QN   256
#define VD   512
#define QD   768
#define HK   1536
#define HOUT 8
#define HD   512
#define KP   3

// ---------------- scratch (device globals) ----------------------------------
__device__ __half g_vh[B * VN * HK];               // v_ fp16 (att A + pool epi)
__device__ __half g_qh[B * QN * HK];               // q_ fp16
__device__ __half g_ssh[B * VN * QN];              // S fp16 hi
__device__ __half g_ssl[B * VN * QN];              // S fp16 lo
__device__ float g_lk[B * HK];
__device__ __half g_hwh[(HOUT + 1) * HK];          // 8 head rows + sum row
__device__ float g_hbsum;
__device__ unsigned char g_vmask[B * VN];
__device__ unsigned char g_qmask[B * QN];
__device__ __half g_vsh[B * VN * VD];
__device__ __half g_qsh[B * QN * QD];
__device__ __half g_wvh[HK * VD];
__device__ __half g_wqh[HK * QD];

static __device__ __forceinline__ uint32_t smem_u32(const void* p) {
    uint32_t a;
    asm("{ .reg .u64 t; cvta.to.shared.u64 t, %1; cvt.u32.u64 %0, t; }"
        : "=r"(a) : "l"(p));
    return a;
}

#define LDMX4(d, addr) \
    asm volatile("ldmatrix.sync.aligned.m8n8.x4.shared.b16 {%0,%1,%2,%3}, [%4];" \
                 : "=r"((d)[0]), "=r"((d)[1]), "=r"((d)[2]), "=r"((d)[3]) \
                 : "r"(addr))

#define LDMX4T(d, addr) \
    asm volatile("ldmatrix.sync.aligned.m8n8.x4.trans.shared.b16 {%0,%1,%2,%3}, [%4];" \
                 : "=r"((d)[0]), "=r"((d)[1]), "=r"((d)[2]), "=r"((d)[3]) \
                 : "r"(addr))

#define MMA16816(c, a, b0, b1) \
    asm volatile("mma.sync.aligned.m16n8k16.row.col.f32.f16.f16.f32 " \
                 "{%0,%1,%2,%3}, {%4,%5,%6,%7}, {%8,%9}, {%0,%1,%2,%3};" \
                 : "+f"((c)[0]), "+f"((c)[1]), "+f"((c)[2]), "+f"((c)[3]) \
                 : "r"((a)[0]), "r"((a)[1]), "r"((a)[2]), "r"((a)[3]), \
                   "r"(b0), "r"(b1))

#define CP16(dst, src) \
    asm volatile("cp.async.cg.shared.global [%0], [%1], 16;" \
                 :: "r"(dst), "l"(src))
#define CP_COMMIT() asm volatile("cp.async.commit_group;" ::: "memory")
#define CP_WAIT0()  asm volatile("cp.async.wait_group 0;" ::: "memory")
#define CP_WAIT1()  asm volatile("cp.async.wait_group 1;" ::: "memory")

static __device__ __forceinline__ uint32_t pack2h(float a, float b) {
    __half2 h = __floats2half2_rn(a, b);
    return *(uint32_t*)&h;
}
static __device__ __forceinline__ void split2h_safe(float x0, float x1,
                                                    uint32_t& hi, uint32_t& lo) {
    __half h0 = __float2half_rn(x0);
    __half h1 = __float2half_rn(x1);
    float l0 = isfinite(x0) ? (x0 - __half2float(h0)) : 0.f;
    float l1 = isfinite(x1) ? (x1 - __half2float(h1)) : 0.f;
    __half2 hh = __halves2half2(h0, h1);
    hi = *(uint32_t*)&hh;
    lo = pack2h(l0, l1);
}

// ---------------- fused prep -------------------------------------------------
__global__ void prep_kernel(const float* __restrict__ v, const float* __restrict__ q,
                            const float* __restrict__ Wv, const float* __restrict__ Wq,
                            const float* __restrict__ h_mat,
                            const float* __restrict__ h_bias) {
    const int bid = blockIdx.x;
    const int tid = threadIdx.x;
    if (bid < 512) {
        int wid = tid >> 5, lane = tid & 31;
        int row = bid * 8 + wid;
        const float4* src = (const float4*)(v + (size_t)row * VD);
        uint2* dst = (uint2*)(g_vsh + (size_t)row * VD);
        float s = 0.f;
#pragma unroll
        for (int j = 0; j < 4; j++) {
            float4 x = src[j * 32 + lane];
            s += fabsf(x.x) + fabsf(x.y) + fabsf(x.z) + fabsf(x.w);
            uint2 h;
            h.x = pack2h(x.x, x.y);
            h.y = pack2h(x.z, x.w);
            dst[j * 32 + lane] = h;
        }
        for (int o = 16; o; o >>= 1) s += __shfl_xor_sync(0xffffffffu, s, o);
        if (lane == 0) g_vmask[row] = (s == 0.f) ? 1 : 0;
    } else if (bid < 1024) {
        int wid = tid >> 5, lane = tid & 31;
        int row = (bid - 512) * 8 + wid;
        const float4* src = (const float4*)(q + (size_t)row * QD);
        uint2* dst = (uint2*)(g_qsh + (size_t)row * QD);
        float s = 0.f;
#pragma unroll
        for (int j = 0; j < 6; j++) {
            float4 x = src[j * 32 + lane];
            s += fabsf(x.x) + fabsf(x.y) + fabsf(x.z) + fabsf(x.w);
            uint2 h;
            h.x = pack2h(x.x, x.y);
            h.y = pack2h(x.z, x.w);
            dst[j * 32 + lane] = h;
        }
        for (int o = 16; o; o >>= 1) s += __shfl_xor_sync(0xffffffffu, s, o);
        if (lane == 0) g_qmask[row] = (s == 0.f) ? 1 : 0;
    } else if (bid < 1216) {
        int base = (bid - 1024) * 1024;
#pragma unroll
        for (int j = 0; j < 4; j++) {
            int i = base + j * 256 + tid;
            float4 x = ((const float4*)Wv)[i];
            uint2 h;
            h.x = pack2h(x.x, x.y);
            h.y = pack2h(x.z, x.w);
            *(uint2*)(g_wvh + (size_t)i * 4) = h;
        }
    } else if (bid < 1504) {
        int base = (bid - 1216) * 1024;
#pragma unroll
        for (int j = 0; j < 4; j++) {
            int i = base + j * 256 + tid;
            float4 x = ((const float4*)Wq)[i];
            uint2 h;
            h.x = pack2h(x.x, x.y);
            h.y = pack2h(x.z, x.w);
            *(uint2*)(g_wqh + (size_t)i * 4) = h;
        }
    } else if (bid == 1504) {
        for (int k = tid; k < HK; k += 256) {
            float s = 0.f;
#pragma unroll
            for (int h = 0; h < HOUT; h++) {
                float w = h_mat[h * HK + k];
                g_hwh[h * HK + k] = __float2half_rn(w);
                s += w;
            }
            g_hwh[HOUT * HK + k] = __float2half_rn(s);
        }
        if (tid == 0) {
            float s = 0.f;
#pragma unroll
            for (int h = 0; h < HOUT; h++) s += h_bias[h];
            g_hbsum = s;
        }
    } else {
        int i = (bid - 1505) * 256 + tid;     // float4 index, 6144 total
        ((float4*)g_lk)[i] = make_float4(0.f, 0.f, 0.f, 0.f);
    }
}

// ---------------- smem geometry ----------------------------------------------
#define SP   40
#define ABY  (128 * SP * 2)     // 10240 B per array
#define STG2 (2 * ABY)          // 20480 B per stage (A, B)
#define SMB2 (2 * STG2)         // 40960  (proj: 2-stage)
#define SMB3 (3 * STG2)         // 61440  (att: 3-stage)

// ---------------- merged proj GEMM (mode = blockIdx.z), 2-stage --------------
__global__ __launch_bounds__(256, 2) void proj_kernel(
    const float* __restrict__ bv, const float* __restrict__ bq) {
    extern __shared__ char smem[];
    const uint32_t sb = smem_u32(smem);
    const int tid = threadIdx.x;
    const int lane = tid & 31;
    const int wid = tid >> 5;
    const int wm = wid >> 2, wn = wid & 3;
    const int mode = blockIdx.z;
    const int KD = mode ? QD : VD;
    const int CH = KD / 32;
    const int m0 = blockIdx.y * 128;
    const int n0 = blockIdx.x * 128;

    const __half* Agh = mode ? g_qsh : g_vsh;
    const __half* Bgh = mode ? g_wqh : g_wvh;
    const float* bias = mode ? bq : bv;

    const int arow = wm * 64 + (lane & 15);
    const int acol = (lane & 16) ? 8 : 0;
    const uint32_t aoff = (uint32_t)(arow * SP + acol) * 2;
    const int brow = wn * 32 + (lane & 7) + ((lane & 16) ? 8 : 0);
    const int bcol = (lane & 8) ? 8 : 0;
    const uint32_t boff = (uint32_t)(brow * SP + bcol) * 2;

    float acc[4][4][4];
#pragma unroll
    for (int i = 0; i < 4; i++)
#pragma unroll
        for (int j = 0; j < 4; j++)
#pragma unroll
            for (int e = 0; e < 4; e++) acc[i][j][e] = 0.f;

    auto cp_chunk = [&](int c) {
        int k0 = c * 32;
        uint32_t stg = sb + (uint32_t)(c & 1) * STG2;
#pragma unroll
        for (int j = 0; j < 4; j++) {
            int u = tid + j * 256;
            int arr = u >> 9;
            int r = (u >> 2) & 127;
            int seg = u & 3;
            uint32_t dst = stg + (uint32_t)arr * ABY + r * (SP * 2) + seg * 16;
            const __half* src = (arr == 0)
                ? (Agh + (size_t)(m0 + r) * KD + k0 + seg * 8)
                : (Bgh + (size_t)(n0 + r) * KD + k0 + seg * 8);
            CP16(dst, src);
        }
    };

    cp_chunk(0);
    CP_COMMIT();

    for (int c = 0; c < CH; ++c) {
        CP_WAIT0();
        __syncthreads();
        if (c + 1 < CH) { cp_chunk(c + 1); CP_COMMIT(); }

        uint32_t stg = sb + (uint32_t)(c & 1) * STG2;
        uint32_t aAh = stg + aoff;
        uint32_t aBh = stg + ABY + boff;
#pragma unroll
        for (int ks = 0; ks < 2; ks++) {
            uint32_t ah[4][4];
#pragma unroll
            for (int mi = 0; mi < 4; mi++)
                LDMX4(ah[mi], aAh + mi * (16 * SP * 2) + ks * 32);
            uint32_t bh[2][4];
#pragma unroll
            for (int np = 0; np < 2; np++)
                LDMX4(bh[np], aBh + np * (16 * SP * 2) + ks * 32);
#pragma unroll
            for (int mi = 0; mi < 4; mi++)
#pragma unroll
                for (int nj = 0; nj < 4; nj++) {
                    uint32_t b0h = bh[nj >> 1][(nj & 1) * 2];
                    uint32_t b1h = bh[nj >> 1][(nj & 1) * 2 + 1];
                    MMA16816(acc[mi][nj], ah[mi], b0h, b1h);
                }
        }
    }

    const int gid = lane >> 2, tig = lane & 3;
#pragma unroll
    for (int mi = 0; mi < 4; mi++) {
#pragma unroll
        for (int nj = 0; nj < 4; nj++) {
            int row = m0 + wm * 64 + mi * 16 + gid;
            int col = n0 + wn * 32 + nj * 8 + tig * 2;
            float b0 = bias[col], b1 = bias[col + 1];
            float v0 = fmaxf(acc[mi][nj][0] + b0, 0.f);
            float v1 = fmaxf(acc[mi][nj][1] + b1, 0.f);
            float v2 = fmaxf(acc[mi][nj][2] + b0, 0.f);
            float v3 = fmaxf(acc[mi][nj][3] + b1, 0.f);
            size_t o0 = (size_t)row * HK + col;
            size_t o1 = (size_t)(row + 8) * HK + col;
            __half* dst = mode ? g_qh : g_vh;
            *(uint32_t*)(dst + o0) = pack2h(v0, v1);
            *(uint32_t*)(dst + o1) = pack2h(v2, v3);
        }
    }
}

// ---------------- att GEMM: A = v_h (pure cp.async, 3-stage), B = q_h*w ------
__global__ __launch_bounds__(256, 2) void att_kernel(
    const float* __restrict__ h_bias, float* __restrict__ attout) {
    extern __shared__ char smem[];
    const uint32_t sb = smem_u32(smem);
    const int tid = threadIdx.x;
    const int lane = tid & 31;
    const int wid = tid >> 5;
    const int wm = wid >> 2, wn = wid & 3;
    const int CH = HK / 32;

    const int bz = blockIdx.z / 9;
    const int hz = blockIdx.z - bz * 9;
    const int m0 = blockIdx.y * 128;
    const int n0 = blockIdx.x * 128;

    const __half* Ap = g_vh + (size_t)bz * VN * HK;
    const __half* Wrow = g_hwh + hz * HK;
    const __half* Qh = g_qh + (size_t)bz * QN * HK;

    const int arow = wm * 64 + (lane & 15);
    const int acol = (lane & 16) ? 8 : 0;
    const uint32_t aoff = (uint32_t)(arow * SP + acol) * 2;
    const int brow = wn * 32 + (lane & 7) + ((lane & 16) ? 8 : 0);
    const int bcol = (lane & 8) ? 8 : 0;
    const uint32_t boff = (uint32_t)(brow * SP + bcol) * 2;

    float acc[4][4][4];
#pragma unroll
    for (int i = 0; i < 4; i++)
#pragma unroll
        for (int j = 0; j < 4; j++)
#pragma unroll
            for (int e = 0; e < 4; e++) acc[i][j][e] = 0.f;

    uint4 rb[2];

    auto cpA = [&](int c) {
        int k0 = c * 32;
        uint32_t stg = sb + (uint32_t)(c % 3) * STG2;
#pragma unroll
        for (int j = 0; j < 2; j++) {
            int u = tid + j * 256;
            int r = u >> 2, seg = u & 3;
            uint32_t dst = stg + r * (SP * 2) + seg * 16;
            CP16(dst, Ap + (size_t)(m0 + r) * HK + k0 + seg * 8);
        }
    };
    auto ldgB = [&](int c) {
        int k0 = c * 32;
#pragma unroll
        for (int i = 0; i < 2; i++) {
            int idx = tid + i * 256;
            int r = idx >> 2, seg = idx & 3;
            rb[i] = *(const uint4*)(Qh + (size_t)(n0 + r) * HK + k0 + seg * 8);
        }
    };
    auto stsB = [&](int c) {
        int k0 = c * 32;
        char* st = smem + (c % 3) * STG2 + ABY;
#pragma unroll
        for (int i = 0; i < 2; i++) {
            int idx = tid + i * 256;
            int r = idx >> 2, seg = idx & 3;
            uint4 w = *(const uint4*)(Wrow + k0 + seg * 8);
            uint4 a = rb[i];
            __half2 r0 = __hmul2(*(__half2*)&a.x, *(__half2*)&w.x);
            __half2 r1 = __hmul2(*(__half2*)&a.y, *(__half2*)&w.y);
            __half2 r2 = __hmul2(*(__half2*)&a.z, *(__half2*)&w.z);
            __half2 r3 = __hmul2(*(__half2*)&a.w, *(__half2*)&w.w);
            uint4 o;
            o.x = *(uint32_t*)&r0; o.y = *(uint32_t*)&r1;
            o.z = *(uint32_t*)&r2; o.w = *(uint32_t*)&r3;
            *(uint4*)(st + (uint32_t)r * (SP * 2) + seg * 16) = o;
        }
    };

    cpA(0);
    CP_COMMIT();
    cpA(1);
    CP_COMMIT();
    ldgB(0);

    for (int c = 0; c < CH; ++c) {
        CP_WAIT1();
        stsB(c);
        __syncthreads();
        if (c + 1 < CH) ldgB(c + 1);
        if (c + 2 < CH) { cpA(c + 2); CP_COMMIT(); }

        uint32_t stg = sb + (uint32_t)(c % 3) * STG2;
        uint32_t aAh = stg + aoff;
        uint32_t aBh = stg + ABY + boff;
#pragma unroll
        for (int ks = 0; ks < 2; ks++) {
            uint32_t ah[4][4];
#pragma unroll
            for (int mi = 0; mi < 4; mi++)
                LDMX4(ah[mi], aAh + mi * (16 * SP * 2) + ks * 32);
            uint32_t bh[2][4];
#pragma unroll
            for (int np = 0; np < 2; np++)
                LDMX4(bh[np], aBh + np * (16 * SP * 2) + ks * 32);
#pragma unroll
            for (int mi = 0; mi < 4; mi++)
#pragma unroll
                for (int nj = 0; nj < 4; nj++) {
                    uint32_t b0h = bh[nj >> 1][(nj & 1) * 2];
                    uint32_t b1h = bh[nj >> 1][(nj & 1) * 2 + 1];
                    MMA16816(acc[mi][nj], ah[mi], b0h, b1h);
                }
        }
    }

    const int gid = lane >> 2, tig = lane & 3;
    float NI = __int_as_float(0xff800000);
    if (hz < 8) {
        float hb = h_bias[hz];
        float* dst = attout + (((size_t)bz * HOUT + hz) * VN + m0) * QN + n0;
#pragma unroll
        for (int mi = 0; mi < 4; mi++) {
#pragma unroll
            for (int nj = 0; nj < 4; nj++) {
                int rl = wm * 64 + mi * 16 + gid;
                int cl = wn * 32 + nj * 8 + tig * 2;
                bool vm0 = g_vmask[bz * VN + m0 + rl] != 0;
                bool vm1 = g_vmask[bz * VN + m0 + rl + 8] != 0;
                bool qm0 = g_qmask[bz * QN + n0 + cl] != 0;
                bool qm1 = g_qmask[bz * QN + n0 + cl + 1] != 0;
                float v0 = (vm0 || qm0) ? NI : acc[mi][nj][0] + hb;
                float v1 = (vm0 || qm1) ? NI : acc[mi][nj][1] + hb;
                float v2 = (vm1 || qm0) ? NI : acc[mi][nj][2] + hb;
                float v3 = (vm1 || qm1) ? NI : acc[mi][nj][3] + hb;
                *(float2*)(dst + (size_t)rl * QN + cl) = make_float2(v0, v1);
                *(float2*)(dst + (size_t)(rl + 8) * QN + cl) = make_float2(v2, v3);
            }
        }
    } else {
        float hb = g_hbsum;
        __half* dh = g_ssh + ((size_t)bz * VN + m0) * QN + n0;
        __half* dl = g_ssl + ((size_t)bz * VN + m0) * QN + n0;
#pragma unroll
        for (int mi = 0; mi < 4; mi++) {
#pragma unroll
            for (int nj = 0; nj < 4; nj++) {
                int rl = wm * 64 + mi * 16 + gid;
                int cl = wn * 32 + nj * 8 + tig * 2;
                bool vm0 = g_vmask[bz * VN + m0 + rl] != 0;
                bool vm1 = g_vmask[bz * VN + m0 + rl + 8] != 0;
                bool qm0 = g_qmask[bz * QN + n0 + cl] != 0;
                bool qm1 = g_qmask[bz * QN + n0 + cl + 1] != 0;
                float s0 = (vm0 || qm0) ? NI : acc[mi][nj][0] + hb;
                float s1 = (vm0 || qm1) ? NI : acc[mi][nj][1] + hb;
                float s2 = (vm1 || qm0) ? NI : acc[mi][nj][2] + hb;
                float s3 = (vm1 || qm1) ? NI : acc[mi][nj][3] + hb;
                uint32_t h0, l0, h1, l1;
                split2h_safe(s0, s1, h0, l0);
                split2h_safe(s2, s3, h1, l1);
                *(uint32_t*)(dh + (size_t)rl * QN + cl) = h0;
                *(uint32_t*)(dl + (size_t)rl * QN + cl) = l0;
                *(uint32_t*)(dh + (size_t)(rl + 8) * QN + cl) = h1;
                *(uint32_t*)(dl + (size_t)(rl + 8) * QN + cl) = l1;
            }
        }
    }
}

// ---------------- pool via MMA, z = mt, 3-stage ------------------------------
#define PBSP 136
#define PBBY (32 * PBSP * 2)            // 8704
#define PSTG (2 * ABY + PBBY)           // 29184
#define PSMB (3 * PSTG + 1024)          // 88576

__global__ __launch_bounds__(256, 2) void pool_mma_kernel() {
    extern __shared__ char smem[];
    const uint32_t sb = smem_u32(smem);
    float* red = (float*)(smem + 3 * PSTG);
    const int tid = threadIdx.x;
    const int lane = tid & 31;
    const int wid = tid >> 5;
    const int wm = wid >> 2, wn = wid & 3;
    const int gid = lane >> 2, tig = lane & 3;

    const int bz = blockIdx.y;
    const int k0 = blockIdx.x * 128;
    const int mt = blockIdx.z;

    const __half* Sh = g_ssh + (size_t)bz * VN * QN;
    const __half* Sl = g_ssl + (size_t)bz * VN * QN;
    const __half* Qh = g_qh + (size_t)bz * QN * HK;
    const __half* Vp = g_vh + (size_t)bz * VN * HK;

    const int arow = wm * 64 + (lane & 15);
    const int acol = (lane & 16) ? 8 : 0;
    const uint32_t aoff = (uint32_t)(arow * SP + acol) * 2;
    const int bg = lane >> 3, br = lane & 7;
    const uint32_t btoff = (uint32_t)(((bg & 1) * 8 + br) * PBSP +
                                     wn * 32 + (bg >> 1) * 8) * 2;

    float ps[4][2];
#pragma unroll
    for (int j = 0; j < 4; j++) { ps[j][0] = 0.f; ps[j][1] = 0.f; }

    auto cp_chunk = [&](int c) {
        int q0 = c * 32;
        uint32_t stg = sb + (uint32_t)(c % 3) * PSTG;
#pragma unroll
        for (int j = 0; j < 4; j++) {
            int u = tid + j * 256;
            int arr = u >> 9;
            int r = (u >> 2) & 127;
            int seg = u & 3;
            uint32_t dst = stg + (uint32_t)arr * ABY + r * (SP * 2) + seg * 16;
            const __half* src = (arr ? Sl : Sh) +
                (size_t)(mt * 128 + r) * QN + q0 + seg * 8;
            CP16(dst, src);
        }
#pragma unroll
        for (int j = 0; j < 2; j++) {
            int u = tid + j * 256;
            int r = (u >> 4) & 31;
            int seg = u & 15;
            uint32_t dst = stg + 2 * ABY + r * (PBSP * 2) + seg * 16;
            CP16(dst, Qh + (size_t)(q0 + r) * HK + k0 + seg * 8);
        }
    };

    float acc[4][4][4];
#pragma unroll
    for (int i = 0; i < 4; i++)
#pragma unroll
        for (int j = 0; j < 4; j++)
#pragma unroll
            for (int e = 0; e < 4; e++) acc[i][j][e] = 0.f;

    cp_chunk(0);
    CP_COMMIT();
    cp_chunk(1);
    CP_COMMIT();

    for (int c = 0; c < 8; ++c) {
        CP_WAIT1();
        __syncthreads();
        if (c + 2 < 8) { cp_chunk(c + 2); CP_COMMIT(); }

        uint32_t stg = sb + (uint32_t)(c % 3) * PSTG;
        uint32_t aAh = stg + aoff;
        uint32_t aBh = stg + 2 * ABY + btoff;
#pragma unroll
        for (int ks = 0; ks < 2; ks++) {
            uint32_t ah[4][4], al[4][4];
#pragma unroll
            for (int mi = 0; mi < 4; mi++) {
                uint32_t ad = aAh + mi * (16 * SP * 2) + ks * 32;
                LDMX4(ah[mi], ad);
                LDMX4(al[mi], ad + ABY);
            }
            uint32_t bh[2][4];
#pragma unroll
            for (int np = 0; np < 2; np++) {
                uint32_t bd = aBh + ks * 16 * (PBSP * 2) + np * 32;
                LDMX4T(bh[np], bd);
            }
#pragma unroll
            for (int mi = 0; mi < 4; mi++)
#pragma unroll
                for (int np = 0; np < 2; np++) {
                    MMA16816(acc[mi][np * 2],     ah[mi], bh[np][0], bh[np][1]);
                    MMA16816(acc[mi][np * 2],     al[mi], bh[np][0], bh[np][1]);
                    MMA16816(acc[mi][np * 2 + 1], ah[mi], bh[np][2], bh[np][3]);
                    MMA16816(acc[mi][np * 2 + 1], al[mi], bh[np][2], bh[np][3]);
                }
        }
    }

#pragma unroll
    for (int mi = 0; mi < 4; mi++) {
#pragma unroll
        for (int nj = 0; nj < 4; nj++) {
            int row = mt * 128 + wm * 64 + mi * 16 + gid;
            int col = k0 + wn * 32 + nj * 8 + tig * 2;
            float2 v0 = __half22float2(*(const __half2*)(Vp + (size_t)row * HK + col));
            float2 v1 = __half22float2(*(const __half2*)(Vp + (size_t)(row + 8) * HK + col));
            ps[nj][0] = fmaf(acc[mi][nj][0], v0.x, ps[nj][0]);
            ps[nj][1] = fmaf(acc[mi][nj][1], v0.y, ps[nj][1]);
            ps[nj][0] = fmaf(acc[mi][nj][2], v1.x, ps[nj][0]);
            ps[nj][1] = fmaf(acc[mi][nj][3], v1.y, ps[nj][1]);
        }
    }

#pragma unroll
    for (int nj = 0; nj < 4; nj++)
#pragma unroll
        for (int e = 0; e < 2; e++) {
            float s = ps[nj][e];
            s += __shfl_xor_sync(0xffffffffu, s, 4);
            s += __shfl_xor_sync(0xffffffffu, s, 8);
            s += __shfl_xor_sync(0xffffffffu, s, 16);
            ps[nj][e] = s;
        }
    __syncthreads();
    if (gid == 0) {
#pragma unroll
        for (int nj = 0; nj < 4; nj++) {
            red[wid * 32 + nj * 8 + tig * 2 + 0] = ps[nj][0];
            red[wid * 32 + nj * 8 + tig * 2 + 1] = ps[nj][1];
        }
    }
    __syncthreads();
    if (tid < 128) {
        int wn2 = tid >> 5, cc = tid & 31;
        float s = red[wn2 * 32 + cc] + red[(wn2 + 4) * 32 + cc];
        atomicAdd(g_lk + bz * HK + k0 + tid, s);
    }
}

// ---------------- pool-of-3 + BatchNorm --------------------------------------
__global__ void bn_kernel(const float* __restrict__ gamma, const float* __restrict__ beta,
                          float* __restrict__ out) {
    int c = blockIdx.x * blockDim.x + threadIdx.x;
    if (c >= HD) return;
    float x[B];
    float mu = 0.f;
#pragma unroll
    for (int b = 0; b < B; b++) {
        const float* p = g_lk + b * HK + c * KP;
        x[b] = p[0] + p[1] + p[2];
        mu += x[b];
    }
    mu *= (1.f / B);
    float var = 0.f;
#pragma unroll
    for (int b = 0; b < B; b++) {
        float d = x[b] - mu;
        var = fmaf(d, d, var);
    }
    var *= (1.f / B);
    float scale = rsqrtf(var + 1e-5f) * gamma[c];
    float bet = beta[c];
#pragma unroll
    for (int b = 0; b < B; b++) out[b * HD + c] = (x[b] - mu) * scale + bet;
}

// ---------------- launcher ----------------------------------------------------
extern "C" void kernel_launch(void* const* d_in, const int* in_sizes, int n_in,
                              void* d_out, int out_size) {
    const float* v      = (const float*)d_in[0];
    const float* q      = (const float*)d_in[1];
    const float* Wv     = (const float*)d_in[2];
    const float* bv     = (const float*)d_in[3];
    const float* Wq     = (const float*)d_in[4];
    const float* bq     = (const float*)d_in[5];
    const float* h_mat  = (const float*)d_in[6];
    const float* h_bias = (const float*)d_in[7];
    const float* gamma  = (const float*)d_in[8];
    const float* beta   = (const float*)d_in[9];

    float* out    = (float*)d_out;
    float* logits = out;
    float* att    = out + B * HD;

    cudaFuncSetAttribute(proj_kernel,
                         cudaFuncAttributeMaxDynamicSharedMemorySize, SMB2);
    cudaFuncSetAttribute(att_kernel,
                         cudaFuncAttributeMaxDynamicSharedMemorySize, SMB3);
    cudaFuncSetAttribute(pool_mma_kernel,
                         cudaFuncAttributeMaxDynamicSharedMemorySize, PSMB);

    prep_kernel<<<1529, 256>>>(v, q, Wv, Wq, h_mat, h_bias);
    proj_kernel<<<dim3(HK / 128, (B * VN) / 128, 2), 256, SMB2>>>(bv, bq);
    att_kernel<<<dim3(QN / 128, VN / 128, B * 9), 256, SMB3>>>(h_bias, att);
    pool_mma_kernel<<<dim3(HK / 128, B, 2), 256, PSMB>>>();
    bn_kernel<<<(HD + 255) / 256, 256>>>(gamma, beta, logits);
}

// round 14
// speedup vs baseline: 7.0554x; 1.0530x over previous
#include <cuda_runtime.h>
#include <cuda_fp16.h>
#include <stdint.h>
#include <math.h>

#define B    16
#define VN   256
#define QN   256
#define VD   512
#define QD   768
#define HK   1536
#define HOUT 8
#define HD   512
#define KP   3

// ---------------- scratch (device globals) ----------------------------------
__device__ __half g_vh[B * VN * HK];               // v_ fp16 (att A + pool epi)
__device__ __half g_qh[B * QN * HK];               // q_ fp16
__device__ __half g_ssh[B * VN * QN];              // S fp16
__device__ float g_lk[B * HK];
__device__ __half g_hwh[(HOUT + 1) * HK];          // 8 head rows + sum row
__device__ float g_hbsum;
__device__ unsigned char g_vmask[B * VN];
__device__ unsigned char g_qmask[B * QN];
__device__ __half g_vsh[B * VN * VD];
__device__ __half g_qsh[B * QN * QD];
__device__ __half g_wvh[HK * VD];
__device__ __half g_wqh[HK * QD];

static __device__ __forceinline__ uint32_t smem_u32(const void* p) {
    uint32_t a;
    asm("{ .reg .u64 t; cvta.to.shared.u64 t, %1; cvt.u32.u64 %0, t; }"
        : "=r"(a) : "l"(p));
    return a;
}

#define LDMX4(d, addr) \
    asm volatile("ldmatrix.sync.aligned.m8n8.x4.shared.b16 {%0,%1,%2,%3}, [%4];" \
                 : "=r"((d)[0]), "=r"((d)[1]), "=r"((d)[2]), "=r"((d)[3]) \
                 : "r"(addr))

#define LDMX4T(d, addr) \
    asm volatile("ldmatrix.sync.aligned.m8n8.x4.trans.shared.b16 {%0,%1,%2,%3}, [%4];" \
                 : "=r"((d)[0]), "=r"((d)[1]), "=r"((d)[2]), "=r"((d)[3]) \
                 : "r"(addr))

#define MMA16816(c, a, b0, b1) \
    asm volatile("mma.sync.aligned.m16n8k16.row.col.f32.f16.f16.f32 " \
                 "{%0,%1,%2,%3}, {%4,%5,%6,%7}, {%8,%9}, {%0,%1,%2,%3};" \
                 : "+f"((c)[0]), "+f"((c)[1]), "+f"((c)[2]), "+f"((c)[3]) \
                 : "r"((a)[0]), "r"((a)[1]), "r"((a)[2]), "r"((a)[3]), \
                   "r"(b0), "r"(b1))

#define CP16(dst, src) \
    asm volatile("cp.async.cg.shared.global [%0], [%1], 16;" \
                 :: "r"(dst), "l"(src))
#define CP_COMMIT() asm volatile("cp.async.commit_group;" ::: "memory")
#define CP_WAIT0()  asm volatile("cp.async.wait_group 0;" ::: "memory")
#define CP_WAIT1()  asm volatile("cp.async.wait_group 1;" ::: "memory")

static __device__ __forceinline__ uint32_t pack2h(float a, float b) {
    __half2 h = __floats2half2_rn(a, b);
    return *(uint32_t*)&h;
}

// ---------------- fused prep -------------------------------------------------
__global__ void prep_kernel(const float* __restrict__ v, const float* __restrict__ q,
                            const float* __restrict__ Wv, const float* __restrict__ Wq,
                            const float* __restrict__ h_mat,
                            const float* __restrict__ h_bias) {
    const int bid = blockIdx.x;
    const int tid = threadIdx.x;
    if (bid < 512) {
        int wid = tid >> 5, lane = tid & 31;
        int row = bid * 8 + wid;
        const float4* src = (const float4*)(v + (size_t)row * VD);
        uint2* dst = (uint2*)(g_vsh + (size_t)row * VD);
        float s = 0.f;
#pragma unroll
        for (int j = 0; j < 4; j++) {
            float4 x = src[j * 32 + lane];
            s += fabsf(x.x) + fabsf(x.y) + fabsf(x.z) + fabsf(x.w);
            uint2 h;
            h.x = pack2h(x.x, x.y);
            h.y = pack2h(x.z, x.w);
            dst[j * 32 + lane] = h;
        }
        for (int o = 16; o; o >>= 1) s += __shfl_xor_sync(0xffffffffu, s, o);
        if (lane == 0) g_vmask[row] = (s == 0.f) ? 1 : 0;
    } else if (bid < 1024) {
        int wid = tid >> 5, lane = tid & 31;
        int row = (bid - 512) * 8 + wid;
        const float4* src = (const float4*)(q + (size_t)row * QD);
        uint2* dst = (uint2*)(g_qsh + (size_t)row * QD);
        float s = 0.f;
#pragma unroll
        for (int j = 0; j < 6; j++) {
            float4 x = src[j * 32 + lane];
            s += fabsf(x.x) + fabsf(x.y) + fabsf(x.z) + fabsf(x.w);
            uint2 h;
            h.x = pack2h(x.x, x.y);
            h.y = pack2h(x.z, x.w);
            dst[j * 32 + lane] = h;
        }
        for (int o = 16; o; o >>= 1) s += __shfl_xor_sync(0xffffffffu, s, o);
        if (lane == 0) g_qmask[row] = (s == 0.f) ? 1 : 0;
    } else if (bid < 1216) {
        int base = (bid - 1024) * 1024;
#pragma unroll
        for (int j = 0; j < 4; j++) {
            int i = base + j * 256 + tid;
            float4 x = ((const float4*)Wv)[i];
            uint2 h;
            h.x = pack2h(x.x, x.y);
            h.y = pack2h(x.z, x.w);
            *(uint2*)(g_wvh + (size_t)i * 4) = h;
        }
    } else if (bid < 1504) {
        int base = (bid - 1216) * 1024;
#pragma unroll
        for (int j = 0; j < 4; j++) {
            int i = base + j * 256 + tid;
            float4 x = ((const float4*)Wq)[i];
            uint2 h;
            h.x = pack2h(x.x, x.y);
            h.y = pack2h(x.z, x.w);
            *(uint2*)(g_wqh + (size_t)i * 4) = h;
        }
    } else if (bid == 1504) {
        for (int k = tid; k < HK; k += 256) {
            float s = 0.f;
#pragma unroll
            for (int h = 0; h < HOUT; h++) {
                float w = h_mat[h * HK + k];
                g_hwh[h * HK + k] = __float2half_rn(w);
                s += w;
            }
            g_hwh[HOUT * HK + k] = __float2half_rn(s);
        }
        if (tid == 0) {
            float s = 0.f;
#pragma unroll
            for (int h = 0; h < HOUT; h++) s += h_bias[h];
            g_hbsum = s;
        }
    } else {
        int i = (bid - 1505) * 256 + tid;     // float4 index, 6144 total
        ((float4*)g_lk)[i] = make_float4(0.f, 0.f, 0.f, 0.f);
    }
}

// ---------------- smem geometry ----------------------------------------------
#define SP   40
#define ABY  (128 * SP * 2)     // 10240 B per array
#define STG2 (2 * ABY)          // 20480 B per stage (A, B)
#define SMB2 (2 * STG2)         // 40960  (proj: 2-stage)
#define SMB3 (3 * STG2)         // 61440  (att: 3-stage)

// ---------------- merged proj GEMM (mode = blockIdx.z), 2-stage --------------
__global__ __launch_bounds__(256, 2) void proj_kernel(
    const float* __restrict__ bv, const float* __restrict__ bq) {
    extern __shared__ char smem[];
    const uint32_t sb = smem_u32(smem);
    const int tid = threadIdx.x;
    const int lane = tid & 31;
    const int wid = tid >> 5;
    const int wm = wid >> 2, wn = wid & 3;
    const int mode = blockIdx.z;
    const int KD = mode ? QD : VD;
    const int CH = KD / 32;
    const int m0 = blockIdx.y * 128;
    const int n0 = blockIdx.x * 128;

    const __half* Agh = mode ? g_qsh : g_vsh;
    const __half* Bgh = mode ? g_wqh : g_wvh;
    const float* bias = mode ? bq : bv;

    const int arow = wm * 64 + (lane & 15);
    const int acol = (lane & 16) ? 8 : 0;
    const uint32_t aoff = (uint32_t)(arow * SP + acol) * 2;
    const int brow = wn * 32 + (lane & 7) + ((lane & 16) ? 8 : 0);
    const int bcol = (lane & 8) ? 8 : 0;
    const uint32_t boff = (uint32_t)(brow * SP + bcol) * 2;

    float acc[4][4][4];
#pragma unroll
    for (int i = 0; i < 4; i++)
#pragma unroll
        for (int j = 0; j < 4; j++)
#pragma unroll
            for (int e = 0; e < 4; e++) acc[i][j][e] = 0.f;

    auto cp_chunk = [&](int c) {
        int k0 = c * 32;
        uint32_t stg = sb + (uint32_t)(c & 1) * STG2;
#pragma unroll
        for (int j = 0; j < 4; j++) {
            int u = tid + j * 256;
            int arr = u >> 9;
            int r = (u >> 2) & 127;
            int seg = u & 3;
            uint32_t dst = stg + (uint32_t)arr * ABY + r * (SP * 2) + seg * 16;
            const __half* src = (arr == 0)
                ? (Agh + (size_t)(m0 + r) * KD + k0 + seg * 8)
                : (Bgh + (size_t)(n0 + r) * KD + k0 + seg * 8);
            CP16(dst, src);
        }
    };

    cp_chunk(0);
    CP_COMMIT();

    for (int c = 0; c < CH; ++c) {
        CP_WAIT0();
        __syncthreads();
        if (c + 1 < CH) { cp_chunk(c + 1); CP_COMMIT(); }

        uint32_t stg = sb + (uint32_t)(c & 1) * STG2;
        uint32_t aAh = stg + aoff;
        uint32_t aBh = stg + ABY + boff;
#pragma unroll
        for (int ks = 0; ks < 2; ks++) {
            uint32_t ah[4][4];
#pragma unroll
            for (int mi = 0; mi < 4; mi++)
                LDMX4(ah[mi], aAh + mi * (16 * SP * 2) + ks * 32);
            uint32_t bh[2][4];
#pragma unroll
            for (int np = 0; np < 2; np++)
                LDMX4(bh[np], aBh + np * (16 * SP * 2) + ks * 32);
#pragma unroll
            for (int mi = 0; mi < 4; mi++)
#pragma unroll
                for (int nj = 0; nj < 4; nj++) {
                    uint32_t b0h = bh[nj >> 1][(nj & 1) * 2];
                    uint32_t b1h = bh[nj >> 1][(nj & 1) * 2 + 1];
                    MMA16816(acc[mi][nj], ah[mi], b0h, b1h);
                }
        }
    }

    const int gid = lane >> 2, tig = lane & 3;
#pragma unroll
    for (int mi = 0; mi < 4; mi++) {
#pragma unroll
        for (int nj = 0; nj < 4; nj++) {
            int row = m0 + wm * 64 + mi * 16 + gid;
            int col = n0 + wn * 32 + nj * 8 + tig * 2;
            float b0 = bias[col], b1 = bias[col + 1];
            float v0 = fmaxf(acc[mi][nj][0] + b0, 0.f);
            float v1 = fmaxf(acc[mi][nj][1] + b1, 0.f);
            float v2 = fmaxf(acc[mi][nj][2] + b0, 0.f);
            float v3 = fmaxf(acc[mi][nj][3] + b1, 0.f);
            size_t o0 = (size_t)row * HK + col;
            size_t o1 = (size_t)(row + 8) * HK + col;
            __half* dst = mode ? g_qh : g_vh;
            *(uint32_t*)(dst + o0) = pack2h(v0, v1);
            *(uint32_t*)(dst + o1) = pack2h(v2, v3);
        }
    }
}

// ---------------- att GEMM: A = v_h (pure cp.async, 3-stage), B = q_h*w ------
__global__ __launch_bounds__(256, 2) void att_kernel(
    const float* __restrict__ h_bias, float* __restrict__ attout) {
    extern __shared__ char smem[];
    const uint32_t sb = smem_u32(smem);
    const int tid = threadIdx.x;
    const int lane = tid & 31;
    const int wid = tid >> 5;
    const int wm = wid >> 2, wn = wid & 3;
    const int CH = HK / 32;

    const int bz = blockIdx.z / 9;
    const int hz = blockIdx.z - bz * 9;
    const int m0 = blockIdx.y * 128;
    const int n0 = blockIdx.x * 128;

    const __half* Ap = g_vh + (size_t)bz * VN * HK;
    const __half* Wrow = g_hwh + hz * HK;
    const __half* Qh = g_qh + (size_t)bz * QN * HK;

    const int arow = wm * 64 + (lane & 15);
    const int acol = (lane & 16) ? 8 : 0;
    const uint32_t aoff = (uint32_t)(arow * SP + acol) * 2;
    const int brow = wn * 32 + (lane & 7) + ((lane & 16) ? 8 : 0);
    const int bcol = (lane & 8) ? 8 : 0;
    const uint32_t boff = (uint32_t)(brow * SP + bcol) * 2;

    float acc[4][4][4];
#pragma unroll
    for (int i = 0; i < 4; i++)
#pragma unroll
        for (int j = 0; j < 4; j++)
#pragma unroll
            for (int e = 0; e < 4; e++) acc[i][j][e] = 0.f;

    uint4 rb[2];

    auto cpA = [&](int c) {
        int k0 = c * 32;
        uint32_t stg = sb + (uint32_t)(c % 3) * STG2;
#pragma unroll
        for (int j = 0; j < 2; j++) {
            int u = tid + j * 256;
            int r = u >> 2, seg = u & 3;
            uint32_t dst = stg + r * (SP * 2) + seg * 16;
            CP16(dst, Ap + (size_t)(m0 + r) * HK + k0 + seg * 8);
        }
    };
    auto ldgB = [&](int c) {
        int k0 = c * 32;
#pragma unroll
        for (int i = 0; i < 2; i++) {
            int idx = tid + i * 256;
            int r = idx >> 2, seg = idx & 3;
            rb[i] = *(const uint4*)(Qh + (size_t)(n0 + r) * HK + k0 + seg * 8);
        }
    };
    auto stsB = [&](int c) {
        int k0 = c * 32;
        char* st = smem + (c % 3) * STG2 + ABY;
#pragma unroll
        for (int i = 0; i < 2; i++) {
            int idx = tid + i * 256;
            int r = idx >> 2, seg = idx & 3;
            uint4 w = *(const uint4*)(Wrow + k0 + seg * 8);
            uint4 a = rb[i];
            __half2 r0 = __hmul2(*(__half2*)&a.x, *(__half2*)&w.x);
            __half2 r1 = __hmul2(*(__half2*)&a.y, *(__half2*)&w.y);
            __half2 r2 = __hmul2(*(__half2*)&a.z, *(__half2*)&w.z);
            __half2 r3 = __hmul2(*(__half2*)&a.w, *(__half2*)&w.w);
            uint4 o;
            o.x = *(uint32_t*)&r0; o.y = *(uint32_t*)&r1;
            o.z = *(uint32_t*)&r2; o.w = *(uint32_t*)&r3;
            *(uint4*)(st + (uint32_t)r * (SP * 2) + seg * 16) = o;
        }
    };

    cpA(0);
    CP_COMMIT();
    cpA(1);
    CP_COMMIT();
    ldgB(0);

    for (int c = 0; c < CH; ++c) {
        CP_WAIT1();
        stsB(c);
        __syncthreads();
        if (c + 1 < CH) ldgB(c + 1);
        if (c + 2 < CH) { cpA(c + 2); CP_COMMIT(); }

        uint32_t stg = sb + (uint32_t)(c % 3) * STG2;
        uint32_t aAh = stg + aoff;
        uint32_t aBh = stg + ABY + boff;
#pragma unroll
        for (int ks = 0; ks < 2; ks++) {
            uint32_t ah[4][4];
#pragma unroll
            for (int mi = 0; mi < 4; mi++)
                LDMX4(ah[mi], aAh + mi * (16 * SP * 2) + ks * 32);
            uint32_t bh[2][4];
#pragma unroll
            for (int np = 0; np < 2; np++)
                LDMX4(bh[np], aBh + np * (16 * SP * 2) + ks * 32);
#pragma unroll
            for (int mi = 0; mi < 4; mi++)
#pragma unroll
                for (int nj = 0; nj < 4; nj++) {
                    uint32_t b0h = bh[nj >> 1][(nj & 1) * 2];
                    uint32_t b1h = bh[nj >> 1][(nj & 1) * 2 + 1];
                    MMA16816(acc[mi][nj], ah[mi], b0h, b1h);
                }
        }
    }

    const int gid = lane >> 2, tig = lane & 3;
    float NI = __int_as_float(0xff800000);
    if (hz < 8) {
        float hb = h_bias[hz];
        float* dst = attout + (((size_t)bz * HOUT + hz) * VN + m0) * QN + n0;
#pragma unroll
        for (int mi = 0; mi < 4; mi++) {
#pragma unroll
            for (int nj = 0; nj < 4; nj++) {
                int rl = wm * 64 + mi * 16 + gid;
                int cl = wn * 32 + nj * 8 + tig * 2;
                bool vm0 = g_vmask[bz * VN + m0 + rl] != 0;
                bool vm1 = g_vmask[bz * VN + m0 + rl + 8] != 0;
                bool qm0 = g_qmask[bz * QN + n0 + cl] != 0;
                bool qm1 = g_qmask[bz * QN + n0 + cl + 1] != 0;
                float v0 = (vm0 || qm0) ? NI : acc[mi][nj][0] + hb;
                float v1 = (vm0 || qm1) ? NI : acc[mi][nj][1] + hb;
                float v2 = (vm1 || qm0) ? NI : acc[mi][nj][2] + hb;
                float v3 = (vm1 || qm1) ? NI : acc[mi][nj][3] + hb;
                *(float2*)(dst + (size_t)rl * QN + cl) = make_float2(v0, v1);
                *(float2*)(dst + (size_t)(rl + 8) * QN + cl) = make_float2(v2, v3);
            }
        }
    } else {
        float hb = g_hbsum;
        __half* dh = g_ssh + ((size_t)bz * VN + m0) * QN + n0;
#pragma unroll
        for (int mi = 0; mi < 4; mi++) {
#pragma unroll
            for (int nj = 0; nj < 4; nj++) {
                int rl = wm * 64 + mi * 16 + gid;
                int cl = wn * 32 + nj * 8 + tig * 2;
                bool vm0 = g_vmask[bz * VN + m0 + rl] != 0;
                bool vm1 = g_vmask[bz * VN + m0 + rl + 8] != 0;
                bool qm0 = g_qmask[bz * QN + n0 + cl] != 0;
                bool qm1 = g_qmask[bz * QN + n0 + cl + 1] != 0;
                float s0 = (vm0 || qm0) ? NI : acc[mi][nj][0] + hb;
                float s1 = (vm0 || qm1) ? NI : acc[mi][nj][1] + hb;
                float s2 = (vm1 || qm0) ? NI : acc[mi][nj][2] + hb;
                float s3 = (vm1 || qm1) ? NI : acc[mi][nj][3] + hb;
                *(uint32_t*)(dh + (size_t)rl * QN + cl) = pack2h(s0, s1);
                *(uint32_t*)(dh + (size_t)(rl + 8) * QN + cl) = pack2h(s2, s3);
            }
        }
    }
}

// ---------------- pool via MMA, z = mt, 3-stage, S fp16 ----------------------
#define PBSP 136
#define PBBY (32 * PBSP * 2)            // 8704
#define PSTG (ABY + PBBY)               // 18944
#define PSMB (3 * PSTG + 1024)          // 57856

__global__ __launch_bounds__(256, 2) void pool_mma_kernel() {
    extern __shared__ char smem[];
    const uint32_t sb = smem_u32(smem);
    float* red = (float*)(smem + 3 * PSTG);
    const int tid = threadIdx.x;
    const int lane = tid & 31;
    const int wid = tid >> 5;
    const int wm = wid >> 2, wn = wid & 3;
    const int gid = lane >> 2, tig = lane & 3;

    const int bz = blockIdx.y;
    const int k0 = blockIdx.x * 128;
    const int mt = blockIdx.z;

    const __half* Sh = g_ssh + (size_t)bz * VN * QN;
    const __half* Qh = g_qh + (size_t)bz * QN * HK;
    const __half* Vp = g_vh + (size_t)bz * VN * HK;

    const int arow = wm * 64 + (lane & 15);
    const int acol = (lane & 16) ? 8 : 0;
    const uint32_t aoff = (uint32_t)(arow * SP + acol) * 2;
    const int bg = lane >> 3, br = lane & 7;
    const uint32_t btoff = (uint32_t)(((bg & 1) * 8 + br) * PBSP +
                                     wn * 32 + (bg >> 1) * 8) * 2;

    float ps[4][2];
#pragma unroll
    for (int j = 0; j < 4; j++) { ps[j][0] = 0.f; ps[j][1] = 0.f; }

    auto cp_chunk = [&](int c) {
        int q0 = c * 32;
        uint32_t stg = sb + (uint32_t)(c % 3) * PSTG;
#pragma unroll
        for (int j = 0; j < 2; j++) {
            int u = tid + j * 256;
            int r = u >> 2;
            int seg = u & 3;
            uint32_t dst = stg + r * (SP * 2) + seg * 16;
            CP16(dst, Sh + (size_t)(mt * 128 + r) * QN + q0 + seg * 8);
        }
#pragma unroll
        for (int j = 0; j < 2; j++) {
            int u = tid + j * 256;
            int r = (u >> 4) & 31;
            int seg = u & 15;
            uint32_t dst = stg + ABY + r * (PBSP * 2) + seg * 16;
            CP16(dst, Qh + (size_t)(q0 + r) * HK + k0 + seg * 8);
        }
    };

    float acc[4][4][4];
#pragma unroll
    for (int i = 0; i < 4; i++)
#pragma unroll
        for (int j = 0; j < 4; j++)
#pragma unroll
            for (int e = 0; e < 4; e++) acc[i][j][e] = 0.f;

    cp_chunk(0);
    CP_COMMIT();
    cp_chunk(1);
    CP_COMMIT();

    for (int c = 0; c < 8; ++c) {
        CP_WAIT1();
        __syncthreads();
        if (c + 2 < 8) { cp_chunk(c + 2); CP_COMMIT(); }

        uint32_t stg = sb + (uint32_t)(c % 3) * PSTG;
        uint32_t aAh = stg + aoff;
        uint32_t aBh = stg + ABY + btoff;
#pragma unroll
        for (int ks = 0; ks < 2; ks++) {
            uint32_t ah[4][4];
#pragma unroll
            for (int mi = 0; mi < 4; mi++)
                LDMX4(ah[mi], aAh + mi * (16 * SP * 2) + ks * 32);
            uint32_t bh[2][4];
#pragma unroll
            for (int np = 0; np < 2; np++) {
                uint32_t bd = aBh + ks * 16 * (PBSP * 2) + np * 32;
                LDMX4T(bh[np], bd);
            }
#pragma unroll
            for (int mi = 0; mi < 4; mi++)
#pragma unroll
                for (int np = 0; np < 2; np++) {
                    MMA16816(acc[mi][np * 2],     ah[mi], bh[np][0], bh[np][1]);
                    MMA16816(acc[mi][np * 2 + 1], ah[mi], bh[np][2], bh[np][3]);
                }
        }
    }

#pragma unroll
    for (int mi = 0; mi < 4; mi++) {
#pragma unroll
        for (int nj = 0; nj < 4; nj++) {
            int row = mt * 128 + wm * 64 + mi * 16 + gid;
            int col = k0 + wn * 32 + nj * 8 + tig * 2;
            float2 v0 = __half22float2(*(const __half2*)(Vp + (size_t)row * HK + col));
            float2 v1 = __half22float2(*(const __half2*)(Vp + (size_t)(row + 8) * HK + col));
            ps[nj][0] = fmaf(acc[mi][nj][0], v0.x, ps[nj][0]);
            ps[nj][1] = fmaf(acc[mi][nj][1], v0.y, ps[nj][1]);
            ps[nj][0] = fmaf(acc[mi][nj][2], v1.x, ps[nj][0]);
            ps[nj][1] = fmaf(acc[mi][nj][3], v1.y, ps[nj][1]);
        }
    }

#pragma unroll
    for (int nj = 0; nj < 4; nj++)
#pragma unroll
        for (int e = 0; e < 2; e++) {
            float s = ps[nj][e];
            s += __shfl_xor_sync(0xffffffffu, s, 4);
            s += __shfl_xor_sync(0xffffffffu, s, 8);
            s += __shfl_xor_sync(0xffffffffu, s, 16);
            ps[nj][e] = s;
        }
    __syncthreads();
    if (gid == 0) {
#pragma unroll
        for (int nj = 0; nj < 4; nj++) {
            red[wid * 32 + nj * 8 + tig * 2 + 0] = ps[nj][0];
            red[wid * 32 + nj * 8 + tig * 2 + 1] = ps[nj][1];
        }
    }
    __syncthreads();
    if (tid < 128) {
        int wn2 = tid >> 5, cc = tid & 31;
        float s = red[wn2 * 32 + cc] + red[(wn2 + 4) * 32 + cc];
        atomicAdd(g_lk + bz * HK + k0 + tid, s);
    }
}

// ---------------- pool-of-3 + BatchNorm --------------------------------------
__global__ void bn_kernel(const float* __restrict__ gamma, const float* __restrict__ beta,
                          float* __restrict__ out) {
    int c = blockIdx.x * blockDim.x + threadIdx.x;
    if (c >= HD) return;
    float x[B];
    float mu = 0.f;
#pragma unroll
    for (int b = 0; b < B; b++) {
        const float* p = g_lk + b * HK + c * KP;
        x[b] = p[0] + p[1] + p[2];
        mu += x[b];
    }
    mu *= (1.f / B);
    float var = 0.f;
#pragma unroll
    for (int b = 0; b < B; b++) {
        float d = x[b] - mu;
        var = fmaf(d, d, var);
    }
    var *= (1.f / B);
    float scale = rsqrtf(var + 1e-5f) * gamma[c];
    float bet = beta[c];
#pragma unroll
    for (int b = 0; b < B; b++) out[b * HD + c] = (x[b] - mu) * scale + bet;
}

// ---------------- launcher ----------------------------------------------------
extern "C" void kernel_launch(void* const* d_in, const int* in_sizes, int n_in,
                              void* d_out, int out_size) {
    const float* v      = (const float*)d_in[0];
    const float* q      = (const float*)d_in[1];
    const float* Wv     = (const float*)d_in[2];
    const float* bv     = (const float*)d_in[3];
    const float* Wq     = (const float*)d_in[4];
    const float* bq     = (const float*)d_in[5];
    const float* h_mat  = (const float*)d_in[6];
    const float* h_bias = (const float*)d_in[7];
    const float* gamma  = (const float*)d_in[8];
    const float* beta   = (const float*)d_in[9];

    float* out    = (float*)d_out;
    float* logits = out;
    float* att    = out + B * HD;

    cudaFuncSetAttribute(proj_kernel,
                         cudaFuncAttributeMaxDynamicSharedMemorySize, SMB2);
    cudaFuncSetAttribute(att_kernel,
                         cudaFuncAttributeMaxDynamicSharedMemorySize, SMB3);
    cudaFuncSetAttribute(pool_mma_kernel,
                         cudaFuncAttributeMaxDynamicSharedMemorySize, PSMB);

    prep_kernel<<<1529, 256>>>(v, q, Wv, Wq, h_mat, h_bias);
    proj_kernel<<<dim3(HK / 128, (B * VN) / 128, 2), 256, SMB2>>>(bv, bq);
    att_kernel<<<dim3(QN / 128, VN / 128, B * 9), 256, SMB3>>>(h_bias, att);
    pool_mma_kernel<<<dim3(HK / 128, B, 2), 256, PSMB>>>();
    bn_kernel<<<(HD + 255) / 256, 256>>>(gamma, beta, logits);
}